// round 1
// baseline (speedup 1.0000x reference)
#include <cuda_runtime.h>
#include <cuda_bf16.h>
#include <math.h>

// Problem constants
#define S_   1024
#define B_   8
#define H_   1024
#define NH_  16
#define DK_  64
#define BH_  128          // NH_*B_  (head-batch)
#define SB_  8192         // S_*B_   (rows of the projection GEMMs)
#define ROWSTRIDE_ 8192   // B_*H_   (floats per seq position in (S,B,H))
#define OUT_ELEMS  (S_*B_*H_)            // 8388608
#define DIST_ELEMS (BH_*S_*S_)           // 134217728

// ---------------- scratch (static device globals; no runtime alloc) ----------
__device__ float g_q[SB_ * H_];
__device__ float g_k[SB_ * H_];
__device__ float g_v[SB_ * H_];
__device__ float g_att[SB_ * H_];          // (B,S,H)
__device__ float g_dist_fallback[DIST_ELEMS];

// ---------------------------------------------------------------------------
// Generic fp32 GEMM: C[M=8192, N=1024] = A[M,1024] @ W[1024,1024]^T
// (i.e. C[m,n] = sum_k A[m,k] * W[n,k])
// Tiles: BM=128, BN=64, BK=16; 256 threads, 8x4 per thread.
// PERM=true remaps the output row m=(b*S+s) -> (s*B+b)  (for the final proj).
// ---------------------------------------------------------------------------
template <bool PERM>
__global__ void __launch_bounds__(256) gemm_xwT_kernel(
    const float* __restrict__ A, const float* __restrict__ W,
    float* __restrict__ C)
{
    const int n0 = blockIdx.x * 64;
    const int m0 = blockIdx.y * 128;
    __shared__ float As[16][132];   // [k][m] (padded)
    __shared__ float Ws[16][68];    // [k][n]

    const int tid = threadIdx.x;
    const int tx  = tid & 15;       // 16 col-groups of 4
    const int ty  = tid >> 4;       // 16 row-groups of 8

    float acc[8][4];
#pragma unroll
    for (int i = 0; i < 8; ++i)
#pragma unroll
        for (int j = 0; j < 4; ++j) acc[i][j] = 0.f;

    for (int kt = 0; kt < 1024; kt += 16) {
#pragma unroll
        for (int l = 0; l < 8; ++l) {
            int e = tid + 256 * l;
            int r = e >> 4, c = e & 15;
            As[c][r] = A[(size_t)(m0 + r) * 1024 + kt + c];
        }
#pragma unroll
        for (int l = 0; l < 4; ++l) {
            int e = tid + 256 * l;
            int r = e >> 4, c = e & 15;
            Ws[c][r] = W[(size_t)(n0 + r) * 1024 + kt + c];
        }
        __syncthreads();
#pragma unroll
        for (int k = 0; k < 16; ++k) {
            float a[8], wv[4];
#pragma unroll
            for (int i = 0; i < 8; ++i) a[i] = As[k][ty * 8 + i];
#pragma unroll
            for (int j = 0; j < 4; ++j) wv[j] = Ws[k][tx * 4 + j];
#pragma unroll
            for (int i = 0; i < 8; ++i)
#pragma unroll
                for (int j = 0; j < 4; ++j) acc[i][j] += a[i] * wv[j];
        }
        __syncthreads();
    }

#pragma unroll
    for (int i = 0; i < 8; ++i) {
        int m = m0 + ty * 8 + i;
        int row = PERM ? ((m & (S_ - 1)) * B_ + (m >> 10)) : m;
#pragma unroll
        for (int j = 0; j < 4; ++j) {
            int n = n0 + tx * 4 + j;
            C[(size_t)row * 1024 + n] = acc[i][j];
        }
    }
}

// ---------------------------------------------------------------------------
// Scores: scores[bb,i,j] = dot(K[i,bb,:], Q[j,bb,:]) / 8
// Layout of Qp/Kp is (S,B,H); head-batch bb = h*B + b selects cols h*64..h*64+63
// of inner-batch b. Writes raw scores into dist[bb,i,j] for lower tiles only
// (tj <= ti); the softmax kernel only reads j <= i and rewrites full rows.
// Grid: (tj=16, ti=16, bb=128); block 256, 64x64 tile, 4x4 per thread.
// ---------------------------------------------------------------------------
__global__ void __launch_bounds__(256) scores_kernel(
    const float* __restrict__ Qp, const float* __restrict__ Kp,
    float* __restrict__ dist)
{
    const int tj = blockIdx.x, ti = blockIdx.y, bb = blockIdx.z;
    if (tj > ti) return;   // fully masked tile

    const int h = bb >> 3;           // bb / B_
    const int b = bb & 7;            // bb % B_
    const int base = b * H_ + h * DK_;

    __shared__ float Ks[64][65];     // [d][i]
    __shared__ float Qs[64][65];     // [d][j]

    const int tid = threadIdx.x;
#pragma unroll
    for (int l = 0; l < 16; ++l) {
        int e = tid + 256 * l;
        int r = e >> 6, d = e & 63;
        Ks[d][r] = Kp[(size_t)(ti * 64 + r) * ROWSTRIDE_ + base + d];
        Qs[d][r] = Qp[(size_t)(tj * 64 + r) * ROWSTRIDE_ + base + d];
    }
    __syncthreads();

    const int tx = tid & 15, ty = tid >> 4;
    float acc[4][4];
#pragma unroll
    for (int i = 0; i < 4; ++i)
#pragma unroll
        for (int j = 0; j < 4; ++j) acc[i][j] = 0.f;

#pragma unroll
    for (int d = 0; d < 64; ++d) {
        float ai[4], qj[4];
#pragma unroll
        for (int i = 0; i < 4; ++i) ai[i] = Ks[d][ty * 4 + i];
#pragma unroll
        for (int j = 0; j < 4; ++j) qj[j] = Qs[d][tx * 4 + j];
#pragma unroll
        for (int i = 0; i < 4; ++i)
#pragma unroll
            for (int j = 0; j < 4; ++j) acc[i][j] += ai[i] * qj[j];
    }

    float* out = dist + ((size_t)bb << 20);
#pragma unroll
    for (int i = 0; i < 4; ++i) {
        int gi = ti * 64 + ty * 4 + i;
#pragma unroll
        for (int j = 0; j < 4; ++j) {
            int gj = tj * 64 + tx * 4 + j;
            out[(size_t)gi * S_ + gj] = acc[i][j] * 0.125f;
        }
    }
}

// ---------------------------------------------------------------------------
// Row softmax over the QUERY axis j (axis=2 of scores), masked to j <= i.
// Writes dist in place: normalized for j<=i, exact 0 for j>i.
// Grid: (i=1024, bb=128); block 256.
// ---------------------------------------------------------------------------
__global__ void __launch_bounds__(256) softmax_kernel(float* __restrict__ dist)
{
    const int i  = blockIdx.x;
    const int bb = blockIdx.y;
    float* row = dist + ((size_t)bb << 20) + (size_t)i * S_;
    const int len = i + 1;

    __shared__ float sh[S_];
    __shared__ float red[8];
    const int tid = threadIdx.x;

    float m = -3.4e38f;
    for (int j = tid; j < len; j += 256) {
        float v = row[j];
        sh[j] = v;
        m = fmaxf(m, v);
    }
#pragma unroll
    for (int o = 16; o; o >>= 1) m = fmaxf(m, __shfl_xor_sync(0xffffffffu, m, o));
    if ((tid & 31) == 0) red[tid >> 5] = m;
    __syncthreads();
    if (tid < 8) {
        m = red[tid];
#pragma unroll
        for (int o = 4; o; o >>= 1) m = fmaxf(m, __shfl_xor_sync(0xffu, m, o));
        if (tid == 0) red[0] = m;
    }
    __syncthreads();
    m = red[0];
    __syncthreads();

    float s = 0.f;
    for (int j = tid; j < len; j += 256) {
        float e = expf(sh[j] - m);
        sh[j] = e;
        s += e;
    }
#pragma unroll
    for (int o = 16; o; o >>= 1) s += __shfl_xor_sync(0xffffffffu, s, o);
    if ((tid & 31) == 0) red[tid >> 5] = s;
    __syncthreads();
    if (tid < 8) {
        s = red[tid];
#pragma unroll
        for (int o = 4; o; o >>= 1) s += __shfl_xor_sync(0xffu, s, o);
        if (tid == 0) red[0] = s;
    }
    __syncthreads();
    const float inv = 1.f / red[0];

    for (int j = tid; j < S_; j += 256)
        row[j] = (j < len) ? sh[j] * inv : 0.f;
}

// ---------------------------------------------------------------------------
// att[j,bb,d] = sum_i dist[bb,i,j] * V[i,bb,d]  (dist is lower-triangular in
// (i,j) so i runs from the diagonal tile). Output layout (B,S,H).
// Grid: (tj=16, bb=128); block 256, tile 64(j) x 64(d), 4x4 per thread.
// ---------------------------------------------------------------------------
__global__ void __launch_bounds__(256) att_kernel(
    const float* __restrict__ dist, const float* __restrict__ Vp,
    float* __restrict__ att)
{
    const int tj = blockIdx.x, bb = blockIdx.y;
    const int h = bb >> 3;
    const int b = bb & 7;
    const int base_v = b * H_ + h * DK_;

    __shared__ float Ds[64][65];   // [i][j]
    __shared__ float Vs[64][65];   // [i][d]

    const int tid = threadIdx.x;
    const int tx = tid & 15, ty = tid >> 4;

    float acc[4][4];
#pragma unroll
    for (int i = 0; i < 4; ++i)
#pragma unroll
        for (int j = 0; j < 4; ++j) acc[i][j] = 0.f;

    const float* drow = dist + ((size_t)bb << 20);

    for (int it = tj; it < 16; ++it) {
#pragma unroll
        for (int l = 0; l < 16; ++l) {
            int e = tid + 256 * l;
            int r = e >> 6, c = e & 63;
            Ds[r][c] = drow[(size_t)(it * 64 + r) * S_ + tj * 64 + c];
            Vs[r][c] = Vp[(size_t)(it * 64 + r) * ROWSTRIDE_ + base_v + c];
        }
        __syncthreads();
#pragma unroll
        for (int i = 0; i < 64; ++i) {
            float dj[4], vd[4];
#pragma unroll
            for (int j = 0; j < 4; ++j) dj[j] = Ds[i][ty * 4 + j];
#pragma unroll
            for (int d = 0; d < 4; ++d) vd[d] = Vs[i][tx * 4 + d];
#pragma unroll
            for (int j = 0; j < 4; ++j)
#pragma unroll
                for (int d = 0; d < 4; ++d) acc[j][d] += dj[j] * vd[d];
        }
        __syncthreads();
    }

#pragma unroll
    for (int j = 0; j < 4; ++j) {
        int gj = tj * 64 + ty * 4 + j;
#pragma unroll
        for (int d = 0; d < 4; ++d) {
            int gd = tx * 4 + d;
            att[((size_t)b * S_ + gj) * H_ + h * DK_ + gd] = acc[j][d];
        }
    }
}

// ---------------------------------------------------------------------------
extern "C" void kernel_launch(void* const* d_in, const int* in_sizes, int n_in,
                              void* d_out, int out_size)
{
    // metadata order: value, key, query, Wq, Wk, Wv, Wo
    const float* value = (const float*)d_in[0];
    const float* key   = (const float*)d_in[1];
    const float* query = (const float*)d_in[2];
    const float* Wq    = (const float*)d_in[3];
    const float* Wk    = (const float*)d_in[4];
    const float* Wv    = (const float*)d_in[5];
    const float* Wo    = (const float*)d_in[6];
    float* out = (float*)d_out;

    float* g_q_p;   cudaGetSymbolAddress((void**)&g_q_p,   g_q);
    float* g_k_p;   cudaGetSymbolAddress((void**)&g_k_p,   g_k);
    float* g_v_p;   cudaGetSymbolAddress((void**)&g_v_p,   g_v);
    float* g_att_p; cudaGetSymbolAddress((void**)&g_att_p, g_att);

    // dist lives directly in the output buffer when it fits (tuple output),
    // otherwise in scratch.
    float* dist_p;
    if (out_size >= (int)(OUT_ELEMS + 0) && (long long)out_size == (long long)OUT_ELEMS + (long long)DIST_ELEMS) {
        dist_p = out + OUT_ELEMS;
    } else {
        cudaGetSymbolAddress((void**)&dist_p, g_dist_fallback);
    }

    dim3 blk(256);
    dim3 grid_proj(16, 64);            // N/64 x M/128
    gemm_xwT_kernel<false><<<grid_proj, blk>>>(query, Wq, g_q_p);
    gemm_xwT_kernel<false><<<grid_proj, blk>>>(key,   Wk, g_k_p);
    gemm_xwT_kernel<false><<<grid_proj, blk>>>(value, Wv, g_v_p);

    dim3 grid_sc(16, 16, 128);
    scores_kernel<<<grid_sc, blk>>>(g_q_p, g_k_p, dist_p);

    dim3 grid_sm(1024, 128);
    softmax_kernel<<<grid_sm, blk>>>(dist_p);

    dim3 grid_att(16, 128);
    att_kernel<<<grid_att, blk>>>(dist_p, g_v_p, g_att_p);

    gemm_xwT_kernel<true><<<grid_proj, blk>>>(g_att_p, Wo, out);
}

// round 3
// speedup vs baseline: 1.5584x; 1.5584x over previous
#include <cuda_runtime.h>
#include <cuda_bf16.h>
#include <math.h>
#include <stdint.h>

// Problem constants
#define S_   1024
#define B_   8
#define H_   1024
#define NH_  16
#define DK_  64
#define BH_  128          // NH_*B_
#define SB_  8192         // S_*B_
#define ROWSTRIDE_ 8192   // B_*H_
#define OUT_ELEMS  (S_*B_*H_)
#define DIST_ELEMS (BH_*S_*S_)

// ---------------- scratch ----------------
__device__ float g_q[SB_ * H_];
__device__ float g_k[SB_ * H_];
__device__ float g_v[SB_ * H_];
__device__ float g_att[SB_ * H_];
__device__ float g_dist_fallback[DIST_ELEMS];
__device__ __nv_bfloat16 g_a_hi[SB_ * H_];
__device__ __nv_bfloat16 g_a_lo[SB_ * H_];
__device__ __nv_bfloat16 g_w_hi[H_ * H_];
__device__ __nv_bfloat16 g_w_lo[H_ * H_];

__device__ __forceinline__ uint32_t smem_u32(const void* p) {
    uint32_t a;
    asm("{ .reg .u64 t; cvta.to.shared.u64 t, %1; cvt.u32.u64 %0, t; }"
        : "=r"(a) : "l"(p));
    return a;
}
__device__ __forceinline__ void cp_async16(uint32_t dst, const void* src) {
    asm volatile("cp.async.ca.shared.global [%0], [%1], 16;" :: "r"(dst), "l"(src));
}
#define CP_COMMIT() asm volatile("cp.async.commit_group;" ::: "memory")
#define CP_WAIT(N)  asm volatile("cp.async.wait_group %0;" :: "n"(N) : "memory")

// ============================================================================
// Split fp32 -> bf16 (hi, lo):  X = hi + lo, lo holds the rounding residual.
// ============================================================================
__global__ void __launch_bounds__(256) conv_split_kernel(
    const float4* __restrict__ X, uint32_t* __restrict__ hi,
    uint32_t* __restrict__ lo, int n4)
{
    int i = blockIdx.x * 256 + threadIdx.x;
    if (i >= n4) return;
    float4 v = X[i];
    __nv_bfloat162 h01 = __floats2bfloat162_rn(v.x, v.y);
    __nv_bfloat162 h23 = __floats2bfloat162_rn(v.z, v.w);
    float r0 = v.x - __bfloat162float(h01.x);
    float r1 = v.y - __bfloat162float(h01.y);
    float r2 = v.z - __bfloat162float(h23.x);
    float r3 = v.w - __bfloat162float(h23.y);
    __nv_bfloat162 l01 = __floats2bfloat162_rn(r0, r1);
    __nv_bfloat162 l23 = __floats2bfloat162_rn(r2, r3);
    hi[2 * i]     = *(uint32_t*)&h01;
    hi[2 * i + 1] = *(uint32_t*)&h23;
    lo[2 * i]     = *(uint32_t*)&l01;
    lo[2 * i + 1] = *(uint32_t*)&l23;
}

// ============================================================================
// HMMA split-bf16 GEMM:  C[8192,1024] = A @ W^T (fp32-accurate via 3 terms)
//   term 0: Ah*Wh, term 1: Ah*Wl, term 2: Al*Wh    (K-loop runs 3*1024)
// CTA tile 128x128, BK=32, 2-stage cp.async pipeline, 8 warps (m32 x n64 each).
// perm!=0 remaps output row m=(b*S+s) -> (s*B+b).
// ============================================================================
#define ROWB 80           // padded smem row stride in bytes (32 bf16 + 8 pad)
#define STAGEB 10240      // 128 * 80

__global__ void __launch_bounds__(256) gemm_split_hmma_kernel(
    const __nv_bfloat16* __restrict__ Ah, const __nv_bfloat16* __restrict__ Al,
    const __nv_bfloat16* __restrict__ Wh, const __nv_bfloat16* __restrict__ Wl,
    float* __restrict__ C, int perm)
{
    __shared__ __nv_bfloat16 As[2][128 * (ROWB / 2)];
    __shared__ __nv_bfloat16 Ws[2][128 * (ROWB / 2)];

    const int tid  = threadIdx.x;
    const int wid  = tid >> 5;
    const int lane = tid & 31;
    const int m0 = blockIdx.y * 128;
    const int n0 = blockIdx.x * 128;
    const int warp_m = (wid & 3) * 32;
    const int warp_n = (wid >> 2) * 64;

    const uint32_t as0 = smem_u32(As);
    const uint32_t ws0 = smem_u32(Ws);

    const __nv_bfloat16* aterm[3] = {Ah, Ah, Al};
    const __nv_bfloat16* wterm[3] = {Wh, Wl, Wh};

    // per-thread load coords: 512 16B-chunks per matrix per stage, 2 per thread
    const int r0g = tid >> 1;            // rows 0..127, chunk (tid&1)*2 and +1
    // simpler: id scheme below

    float acc[2][8][4];
#pragma unroll
    for (int a = 0; a < 2; ++a)
#pragma unroll
        for (int b = 0; b < 8; ++b)
#pragma unroll
            for (int c = 0; c < 4; ++c) acc[a][b][c] = 0.f;

    // ---- loader lambda (as macro) ----
#define LOAD_STAGE(st, kt) do {                                                \
    int term_ = (kt) >> 5;                                                     \
    int kk_ = ((kt) & 31) * 32;                                                \
    const __nv_bfloat16* ga_ = aterm[term_] + (size_t)m0 * 1024 + kk_;         \
    const __nv_bfloat16* gw_ = wterm[term_] + (size_t)n0 * 1024 + kk_;         \
    _Pragma("unroll")                                                          \
    for (int l_ = 0; l_ < 2; ++l_) {                                           \
        int id_ = tid + 256 * l_;                                              \
        int row_ = id_ >> 2, c_ = id_ & 3;                                     \
        cp_async16(as0 + (st) * STAGEB + row_ * ROWB + c_ * 16,                \
                   ga_ + (size_t)row_ * 1024 + c_ * 8);                        \
        cp_async16(ws0 + (st) * STAGEB + row_ * ROWB + c_ * 16,                \
                   gw_ + (size_t)row_ * 1024 + c_ * 8);                        \
    }                                                                          \
    CP_COMMIT();                                                               \
} while (0)

    LOAD_STAGE(0, 0);

    const uint32_t a_lane_row = warp_m + (lane & 15);
    const uint32_t a_lane_col = (lane >> 4) * 16;           // bytes (8 bf16)
    const uint32_t b_lane_row = warp_n + (lane & 7) + ((lane >> 4) << 3);
    const uint32_t b_lane_col = ((lane >> 3) & 1) * 16;     // bytes

    for (int kt = 0; kt < 96; ++kt) {
        const int st = kt & 1;
        if (kt + 1 < 96) { LOAD_STAGE(st ^ 1, kt + 1); CP_WAIT(1); }
        else             { CP_WAIT(0); }
        __syncthreads();

        const uint32_t abase = as0 + st * STAGEB;
        const uint32_t bbase = ws0 + st * STAGEB;

#pragma unroll
        for (int k16 = 0; k16 < 2; ++k16) {
            uint32_t af[2][4];
#pragma unroll
            for (int fm = 0; fm < 2; ++fm) {
                uint32_t addr = abase + (a_lane_row + fm * 16) * ROWB
                              + k16 * 32 + a_lane_col;
                asm volatile("ldmatrix.sync.aligned.m8n8.x4.shared.b16 "
                             "{%0,%1,%2,%3}, [%4];"
                             : "=r"(af[fm][0]), "=r"(af[fm][1]),
                               "=r"(af[fm][2]), "=r"(af[fm][3]) : "r"(addr));
            }
            uint32_t bf[8][2];
#pragma unroll
            for (int fp = 0; fp < 4; ++fp) {
                uint32_t addr = bbase + (b_lane_row + fp * 16) * ROWB
                              + k16 * 32 + b_lane_col;
                uint32_t r0, r1, r2, r3;
                asm volatile("ldmatrix.sync.aligned.m8n8.x4.shared.b16 "
                             "{%0,%1,%2,%3}, [%4];"
                             : "=r"(r0), "=r"(r1), "=r"(r2), "=r"(r3) : "r"(addr));
                bf[fp * 2][0] = r0; bf[fp * 2][1] = r1;
                bf[fp * 2 + 1][0] = r2; bf[fp * 2 + 1][1] = r3;
            }
#pragma unroll
            for (int fm = 0; fm < 2; ++fm)
#pragma unroll
                for (int fn = 0; fn < 8; ++fn) {
                    asm volatile(
                        "mma.sync.aligned.m16n8k16.row.col.f32.bf16.bf16.f32 "
                        "{%0,%1,%2,%3}, {%4,%5,%6,%7}, {%8,%9}, {%0,%1,%2,%3};"
                        : "+f"(acc[fm][fn][0]), "+f"(acc[fm][fn][1]),
                          "+f"(acc[fm][fn][2]), "+f"(acc[fm][fn][3])
                        : "r"(af[fm][0]), "r"(af[fm][1]),
                          "r"(af[fm][2]), "r"(af[fm][3]),
                          "r"(bf[fn][0]), "r"(bf[fn][1]));
                }
        }
        __syncthreads();
    }

    // ---- epilogue ----
#pragma unroll
    for (int fm = 0; fm < 2; ++fm) {
#pragma unroll
        for (int half = 0; half < 2; ++half) {
            int r = m0 + warp_m + fm * 16 + (lane >> 2) + half * 8;
            int orow = perm ? ((r & (S_ - 1)) * B_ + (r >> 10)) : r;
            float* cr = C + (size_t)orow * 1024 + n0 + warp_n + (lane & 3) * 2;
#pragma unroll
            for (int fn = 0; fn < 8; ++fn) {
                float2 v = half ? make_float2(acc[fm][fn][2], acc[fm][fn][3])
                                : make_float2(acc[fm][fn][0], acc[fm][fn][1]);
                *(float2*)(cr + fn * 8) = v;
            }
        }
    }
#undef LOAD_STAGE
}

// ============================================================================
// scores / softmax / att: unchanged from the passing R1 kernel
// ============================================================================
__global__ void __launch_bounds__(256) scores_kernel(
    const float* __restrict__ Qp, const float* __restrict__ Kp,
    float* __restrict__ dist)
{
    const int tj = blockIdx.x, ti = blockIdx.y, bb = blockIdx.z;
    if (tj > ti) return;

    const int h = bb >> 3;
    const int b = bb & 7;
    const int base = b * H_ + h * DK_;

    __shared__ float Ks[64][65];
    __shared__ float Qs[64][65];

    const int tid = threadIdx.x;
#pragma unroll
    for (int l = 0; l < 16; ++l) {
        int e = tid + 256 * l;
        int r = e >> 6, d = e & 63;
        Ks[d][r] = Kp[(size_t)(ti * 64 + r) * ROWSTRIDE_ + base + d];
        Qs[d][r] = Qp[(size_t)(tj * 64 + r) * ROWSTRIDE_ + base + d];
    }
    __syncthreads();

    const int tx = tid & 15, ty = tid >> 4;
    float acc[4][4];
#pragma unroll
    for (int i = 0; i < 4; ++i)
#pragma unroll
        for (int j = 0; j < 4; ++j) acc[i][j] = 0.f;

#pragma unroll
    for (int d = 0; d < 64; ++d) {
        float ai[4], qj[4];
#pragma unroll
        for (int i = 0; i < 4; ++i) ai[i] = Ks[d][ty * 4 + i];
#pragma unroll
        for (int j = 0; j < 4; ++j) qj[j] = Qs[d][tx * 4 + j];
#pragma unroll
        for (int i = 0; i < 4; ++i)
#pragma unroll
            for (int j = 0; j < 4; ++j) acc[i][j] += ai[i] * qj[j];
    }

    float* out = dist + ((size_t)bb << 20);
#pragma unroll
    for (int i = 0; i < 4; ++i) {
        int gi = ti * 64 + ty * 4 + i;
#pragma unroll
        for (int j = 0; j < 4; ++j) {
            int gj = tj * 64 + tx * 4 + j;
            out[(size_t)gi * S_ + gj] = acc[i][j] * 0.125f;
        }
    }
}

__global__ void __launch_bounds__(256) softmax_kernel(float* __restrict__ dist)
{
    const int i  = blockIdx.x;
    const int bb = blockIdx.y;
    float* row = dist + ((size_t)bb << 20) + (size_t)i * S_;
    const int len = i + 1;

    __shared__ float sh[S_];
    __shared__ float red[8];
    const int tid = threadIdx.x;

    float m = -3.4e38f;
    for (int j = tid; j < len; j += 256) {
        float v = row[j];
        sh[j] = v;
        m = fmaxf(m, v);
    }
#pragma unroll
    for (int o = 16; o; o >>= 1) m = fmaxf(m, __shfl_xor_sync(0xffffffffu, m, o));
    if ((tid & 31) == 0) red[tid >> 5] = m;
    __syncthreads();
    if (tid < 8) {
        m = red[tid];
#pragma unroll
        for (int o = 4; o; o >>= 1) m = fmaxf(m, __shfl_xor_sync(0xffu, m, o));
        if (tid == 0) red[0] = m;
    }
    __syncthreads();
    m = red[0];
    __syncthreads();

    float s = 0.f;
    for (int j = tid; j < len; j += 256) {
        float e = expf(sh[j] - m);
        sh[j] = e;
        s += e;
    }
#pragma unroll
    for (int o = 16; o; o >>= 1) s += __shfl_xor_sync(0xffffffffu, s, o);
    if ((tid & 31) == 0) red[tid >> 5] = s;
    __syncthreads();
    if (tid < 8) {
        s = red[tid];
#pragma unroll
        for (int o = 4; o; o >>= 1) s += __shfl_xor_sync(0xffu, s, o);
        if (tid == 0) red[0] = s;
    }
    __syncthreads();
    const float inv = 1.f / red[0];

    for (int j = tid; j < S_; j += 256)
        row[j] = (j < len) ? sh[j] * inv : 0.f;
}

__global__ void __launch_bounds__(256) att_kernel(
    const float* __restrict__ dist, const float* __restrict__ Vp,
    float* __restrict__ att)
{
    const int tj = blockIdx.x, bb = blockIdx.y;
    const int h = bb >> 3;
    const int b = bb & 7;
    const int base_v = b * H_ + h * DK_;

    __shared__ float Ds[64][65];
    __shared__ float Vs[64][65];

    const int tid = threadIdx.x;
    const int tx = tid & 15, ty = tid >> 4;

    float acc[4][4];
#pragma unroll
    for (int i = 0; i < 4; ++i)
#pragma unroll
        for (int j = 0; j < 4; ++j) acc[i][j] = 0.f;

    const float* drow = dist + ((size_t)bb << 20);

    for (int it = tj; it < 16; ++it) {
#pragma unroll
        for (int l = 0; l < 16; ++l) {
            int e = tid + 256 * l;
            int r = e >> 6, c = e & 63;
            Ds[r][c] = drow[(size_t)(it * 64 + r) * S_ + tj * 64 + c];
            Vs[r][c] = Vp[(size_t)(it * 64 + r) * ROWSTRIDE_ + base_v + c];
        }
        __syncthreads();
#pragma unroll
        for (int i = 0; i < 64; ++i) {
            float dj[4], vd[4];
#pragma unroll
            for (int j = 0; j < 4; ++j) dj[j] = Ds[i][ty * 4 + j];
#pragma unroll
            for (int d = 0; d < 4; ++d) vd[d] = Vs[i][tx * 4 + d];
#pragma unroll
            for (int j = 0; j < 4; ++j)
#pragma unroll
                for (int d = 0; d < 4; ++d) acc[j][d] += dj[j] * vd[d];
        }
        __syncthreads();
    }

#pragma unroll
    for (int j = 0; j < 4; ++j) {
        int gj = tj * 64 + ty * 4 + j;
#pragma unroll
        for (int d = 0; d < 4; ++d) {
            int gd = tx * 4 + d;
            att[((size_t)b * S_ + gj) * H_ + h * DK_ + gd] = acc[j][d];
        }
    }
}

// ---------------------------------------------------------------------------
extern "C" void kernel_launch(void* const* d_in, const int* in_sizes, int n_in,
                              void* d_out, int out_size)
{
    const float* value = (const float*)d_in[0];
    const float* key   = (const float*)d_in[1];
    const float* query = (const float*)d_in[2];
    const float* Wq    = (const float*)d_in[3];
    const float* Wk    = (const float*)d_in[4];
    const float* Wv    = (const float*)d_in[5];
    const float* Wo    = (const float*)d_in[6];
    float* out = (float*)d_out;

    float* g_q_p;   cudaGetSymbolAddress((void**)&g_q_p,   g_q);
    float* g_k_p;   cudaGetSymbolAddress((void**)&g_k_p,   g_k);
    float* g_v_p;   cudaGetSymbolAddress((void**)&g_v_p,   g_v);
    float* g_att_p; cudaGetSymbolAddress((void**)&g_att_p, g_att);
    __nv_bfloat16 *ah, *al, *wh, *wl;
    cudaGetSymbolAddress((void**)&ah, g_a_hi);
    cudaGetSymbolAddress((void**)&al, g_a_lo);
    cudaGetSymbolAddress((void**)&wh, g_w_hi);
    cudaGetSymbolAddress((void**)&wl, g_w_lo);

    float* dist_p;
    if ((long long)out_size == (long long)OUT_ELEMS + (long long)DIST_ELEMS) {
        dist_p = out + OUT_ELEMS;
    } else {
        cudaGetSymbolAddress((void**)&dist_p, g_dist_fallback);
    }

    dim3 blk(256);
    dim3 grid_g(8, 64);                    // 128x128 tiles
    const int A4 = SB_ * H_ / 4;           // float4 count for activations
    const int W4 = H_ * H_ / 4;

    // Q projection
    conv_split_kernel<<<(A4 + 255) / 256, blk>>>((const float4*)query, (uint32_t*)ah, (uint32_t*)al, A4);
    conv_split_kernel<<<(W4 + 255) / 256, blk>>>((const float4*)Wq, (uint32_t*)wh, (uint32_t*)wl, W4);
    gemm_split_hmma_kernel<<<grid_g, blk>>>(ah, al, wh, wl, g_q_p, 0);
    // K projection
    conv_split_kernel<<<(A4 + 255) / 256, blk>>>((const float4*)key, (uint32_t*)ah, (uint32_t*)al, A4);
    conv_split_kernel<<<(W4 + 255) / 256, blk>>>((const float4*)Wk, (uint32_t*)wh, (uint32_t*)wl, W4);
    gemm_split_hmma_kernel<<<grid_g, blk>>>(ah, al, wh, wl, g_k_p, 0);
    // V projection
    conv_split_kernel<<<(A4 + 255) / 256, blk>>>((const float4*)value, (uint32_t*)ah, (uint32_t*)al, A4);
    conv_split_kernel<<<(W4 + 255) / 256, blk>>>((const float4*)Wv, (uint32_t*)wh, (uint32_t*)wl, W4);
    gemm_split_hmma_kernel<<<grid_g, blk>>>(ah, al, wh, wl, g_v_p, 0);

    dim3 grid_sc(16, 16, 128);
    scores_kernel<<<grid_sc, blk>>>(g_q_p, g_k_p, dist_p);

    dim3 grid_sm(1024, 128);
    softmax_kernel<<<grid_sm, blk>>>(dist_p);

    dim3 grid_att(16, 128);
    att_kernel<<<grid_att, blk>>>(dist_p, g_v_p, g_att_p);

    // Output projection (with (b,s)->(s,b) permutation fused in the store)
    conv_split_kernel<<<(A4 + 255) / 256, blk>>>((const float4*)g_att_p, (uint32_t*)ah, (uint32_t*)al, A4);
    conv_split_kernel<<<(W4 + 255) / 256, blk>>>((const float4*)Wo, (uint32_t*)wh, (uint32_t*)wl, W4);
    gemm_split_hmma_kernel<<<grid_g, blk>>>(ah, al, wh, wl, out, 1);
}

// round 5
// speedup vs baseline: 1.6099x; 1.0330x over previous
#include <cuda_runtime.h>
#include <cuda_bf16.h>
#include <math.h>
#include <stdint.h>

// Problem constants
#define S_   1024
#define B_   8
#define H_   1024
#define NH_  16
#define DK_  64
#define BH_  128
#define SB_  8192
#define OUT_ELEMS  (S_*B_*H_)
#define DIST_ELEMS (BH_*S_*S_)

// ---------------- scratch ----------------
__device__ float g_v[SB_ * H_];
__device__ float g_att[SB_ * H_];
__device__ float g_dist_fallback[DIST_ELEMS];
__device__ __nv_bfloat16 g_a_hi[SB_ * H_];
__device__ __nv_bfloat16 g_a_lo[SB_ * H_];
__device__ __nv_bfloat16 g_w_hi[H_ * H_];
__device__ __nv_bfloat16 g_w_lo[H_ * H_];
// head-major split projections: [bb][s][64], bb = h*8+b
__device__ __nv_bfloat16 g_qh[SB_ * H_];
__device__ __nv_bfloat16 g_ql[SB_ * H_];
__device__ __nv_bfloat16 g_kh[SB_ * H_];
__device__ __nv_bfloat16 g_kl[SB_ * H_];

__device__ __forceinline__ uint32_t smem_u32(const void* p) {
    uint32_t a;
    asm("{ .reg .u64 t; cvta.to.shared.u64 t, %1; cvt.u32.u64 %0, t; }"
        : "=r"(a) : "l"(p));
    return a;
}
__device__ __forceinline__ void cp_async16(uint32_t dst, const void* src) {
    asm volatile("cp.async.ca.shared.global [%0], [%1], 16;" :: "r"(dst), "l"(src));
}
#define CP_COMMIT() asm volatile("cp.async.commit_group;" ::: "memory")
#define CP_WAIT(N)  asm volatile("cp.async.wait_group %0;" :: "n"(N) : "memory")

#define LDM_X4(r, addr)                                                        \
    asm volatile("ldmatrix.sync.aligned.m8n8.x4.shared.b16 {%0,%1,%2,%3}, [%4];" \
                 : "=r"((r)[0]), "=r"((r)[1]), "=r"((r)[2]), "=r"((r)[3]) : "r"(addr))

#define MMA16816(acc, a, b0, b1)                                               \
    asm volatile("mma.sync.aligned.m16n8k16.row.col.f32.bf16.bf16.f32 "        \
                 "{%0,%1,%2,%3}, {%4,%5,%6,%7}, {%8,%9}, {%0,%1,%2,%3};"       \
                 : "+f"((acc)[0]), "+f"((acc)[1]), "+f"((acc)[2]), "+f"((acc)[3]) \
                 : "r"((a)[0]), "r"((a)[1]), "r"((a)[2]), "r"((a)[3]),         \
                   "r"(b0), "r"(b1))

__device__ __forceinline__ void split2(float x, float y,
                                       uint32_t& hi, uint32_t& lo) {
    __nv_bfloat162 h = __floats2bfloat162_rn(x, y);
    float rx = x - __bfloat162float(h.x);
    float ry = y - __bfloat162float(h.y);
    __nv_bfloat162 l = __floats2bfloat162_rn(rx, ry);
    hi = *(uint32_t*)&h;
    lo = *(uint32_t*)&l;
}

// ============================================================================
// Split fp32 -> bf16 hi/lo (flat)
// ============================================================================
__global__ void __launch_bounds__(256) conv_split_kernel(
    const float4* __restrict__ X, uint32_t* __restrict__ hi,
    uint32_t* __restrict__ lo, int n4)
{
    int i = blockIdx.x * 256 + threadIdx.x;
    if (i >= n4) return;
    float4 v = X[i];
    uint32_t h0, l0, h1, l1;
    split2(v.x, v.y, h0, l0);
    split2(v.z, v.w, h1, l1);
    hi[2 * i] = h0; hi[2 * i + 1] = h1;
    lo[2 * i] = l0; lo[2 * i + 1] = l1;
}

// ============================================================================
// HMMA split-bf16 GEMM: C[8192,1024] = A @ W^T.
// mode 0: fp32 out, rows as-is (V proj)
// mode 1: fp32 out, row m=(b*S+s) -> (s*B+b) (final proj)
// mode 2: split bf16 head-major out (Q/K proj): [h*8+b][s][d]
// ============================================================================
#define ROWB 80
#define STAGEB 10240

__global__ void __launch_bounds__(256) gemm_split_hmma_kernel(
    const __nv_bfloat16* __restrict__ Ah, const __nv_bfloat16* __restrict__ Al,
    const __nv_bfloat16* __restrict__ Wh, const __nv_bfloat16* __restrict__ Wl,
    float* __restrict__ C, __nv_bfloat16* __restrict__ Oh,
    __nv_bfloat16* __restrict__ Ol, int mode)
{
    __shared__ __nv_bfloat16 As[2][128 * (ROWB / 2)];
    __shared__ __nv_bfloat16 Ws[2][128 * (ROWB / 2)];

    const int tid  = threadIdx.x;
    const int wid  = tid >> 5;
    const int lane = tid & 31;
    const int m0 = blockIdx.y * 128;
    const int n0 = blockIdx.x * 128;
    const int warp_m = (wid & 3) * 32;
    const int warp_n = (wid >> 2) * 64;

    const uint32_t as0 = smem_u32(As);
    const uint32_t ws0 = smem_u32(Ws);

    const __nv_bfloat16* aterm[3] = {Ah, Ah, Al};
    const __nv_bfloat16* wterm[3] = {Wh, Wl, Wh};

    float acc[2][8][4];
#pragma unroll
    for (int a = 0; a < 2; ++a)
#pragma unroll
        for (int b = 0; b < 8; ++b)
#pragma unroll
            for (int c = 0; c < 4; ++c) acc[a][b][c] = 0.f;

#define LOAD_STAGE(st, kt) do {                                                \
    int term_ = (kt) >> 5;                                                     \
    int kk_ = ((kt) & 31) * 32;                                                \
    const __nv_bfloat16* ga_ = aterm[term_] + (size_t)m0 * 1024 + kk_;         \
    const __nv_bfloat16* gw_ = wterm[term_] + (size_t)n0 * 1024 + kk_;         \
    _Pragma("unroll")                                                          \
    for (int l_ = 0; l_ < 2; ++l_) {                                           \
        int id_ = tid + 256 * l_;                                              \
        int row_ = id_ >> 2, c_ = id_ & 3;                                     \
        cp_async16(as0 + (st) * STAGEB + row_ * ROWB + c_ * 16,                \
                   ga_ + (size_t)row_ * 1024 + c_ * 8);                        \
        cp_async16(ws0 + (st) * STAGEB + row_ * ROWB + c_ * 16,                \
                   gw_ + (size_t)row_ * 1024 + c_ * 8);                        \
    }                                                                          \
    CP_COMMIT();                                                               \
} while (0)

    LOAD_STAGE(0, 0);

    const uint32_t a_lane_row = warp_m + (lane & 15);
    const uint32_t a_lane_col = (lane >> 4) * 16;
    const uint32_t b_lane_row = warp_n + (lane & 7) + ((lane >> 4) << 3);
    const uint32_t b_lane_col = ((lane >> 3) & 1) * 16;

    for (int kt = 0; kt < 96; ++kt) {
        const int st = kt & 1;
        if (kt + 1 < 96) { LOAD_STAGE(st ^ 1, kt + 1); CP_WAIT(1); }
        else             { CP_WAIT(0); }
        __syncthreads();

        const uint32_t abase = as0 + st * STAGEB;
        const uint32_t bbase = ws0 + st * STAGEB;

#pragma unroll
        for (int k16 = 0; k16 < 2; ++k16) {
            uint32_t af[2][4];
#pragma unroll
            for (int fm = 0; fm < 2; ++fm)
                LDM_X4(af[fm], abase + (a_lane_row + fm * 16) * ROWB
                               + k16 * 32 + a_lane_col);
            uint32_t bf[8][2];
#pragma unroll
            for (int fp = 0; fp < 4; ++fp) {
                uint32_t r[4];
                LDM_X4(r, bbase + (b_lane_row + fp * 16) * ROWB
                          + k16 * 32 + b_lane_col);
                bf[fp * 2][0] = r[0]; bf[fp * 2][1] = r[1];
                bf[fp * 2 + 1][0] = r[2]; bf[fp * 2 + 1][1] = r[3];
            }
#pragma unroll
            for (int fm = 0; fm < 2; ++fm)
#pragma unroll
                for (int fn = 0; fn < 8; ++fn)
                    MMA16816(acc[fm][fn], af[fm], bf[fn][0], bf[fn][1]);
        }
        __syncthreads();
    }

#pragma unroll
    for (int fm = 0; fm < 2; ++fm) {
#pragma unroll
        for (int half = 0; half < 2; ++half) {
            int m = m0 + warp_m + fm * 16 + (lane >> 2) + half * 8;
            if (mode == 2) {
                int s = m >> 3, b = m & 7;
#pragma unroll
                for (int fn = 0; fn < 8; ++fn) {
                    int col = n0 + warp_n + (lane & 3) * 2 + fn * 8;
                    int h = col >> 6, d = col & 63;
                    size_t addr = ((size_t)(h * 8 + b) * 1024 + s) * 64 + d;
                    float x = acc[fm][fn][half * 2];
                    float y = acc[fm][fn][half * 2 + 1];
                    uint32_t hi, lo;
                    split2(x, y, hi, lo);
                    *(uint32_t*)(Oh + addr) = hi;
                    *(uint32_t*)(Ol + addr) = lo;
                }
            } else {
                int orow = mode ? ((m & (S_ - 1)) * B_ + (m >> 10)) : m;
                float* cr = C + (size_t)orow * 1024 + n0 + warp_n + (lane & 3) * 2;
#pragma unroll
                for (int fn = 0; fn < 8; ++fn) {
                    float2 v = half ? make_float2(acc[fm][fn][2], acc[fm][fn][3])
                                    : make_float2(acc[fm][fn][0], acc[fm][fn][1]);
                    *(float2*)(cr + fn * 8) = v;
                }
            }
        }
    }
#undef LOAD_STAGE
}

// ============================================================================
// scores HMMA: dist_raw[bb,i,j] = (K_i . Q_j)/8, lower-tri 128x128 tiles.
// A = Kh/Kl [i][d], B = Qh/Ql [j][d], both head-major split bf16.
// 3 terms: KhQh + KhQl + KlQh.  Dyn smem: 4 x 128 x 144B = 73728 B.
// ============================================================================
#define SROWB 144
#define SBUF  18432

__global__ void __launch_bounds__(256) scores_hmma_kernel(
    const __nv_bfloat16* __restrict__ Qh, const __nv_bfloat16* __restrict__ Ql,
    const __nv_bfloat16* __restrict__ Kh, const __nv_bfloat16* __restrict__ Kl,
    float* __restrict__ dist)
{
    extern __shared__ char sm[];
    const uint32_t s0 = smem_u32(sm);
    const int pid = blockIdx.x;             // 0..35 lower-tri pair
    const int bb  = blockIdx.y;
    int tit = 0;
    while ((tit + 1) * (tit + 2) / 2 <= pid) ++tit;
    const int tjt = pid - tit * (tit + 1) / 2;

    const int tid  = threadIdx.x;
    const int wid  = tid >> 5;
    const int lane = tid & 31;
    const int warp_m = (wid & 3) * 32;      // i
    const int warp_n = (wid >> 2) * 64;     // j

    const size_t hb = (size_t)bb * 65536;
    const __nv_bfloat16* srcs[4] = {Kh + hb, Kl + hb, Qh + hb, Ql + hb};
    const int rbase[4] = {tit * 128, tit * 128, tjt * 128, tjt * 128};

    // load 4 buffers: 128 rows x 64 bf16 each
#pragma unroll
    for (int bfi = 0; bfi < 4; ++bfi) {
#pragma unroll
        for (int l = 0; l < 4; ++l) {
            int id = tid + 256 * l;
            int row = id >> 3, c = id & 7;
            cp_async16(s0 + bfi * SBUF + row * SROWB + c * 16,
                       srcs[bfi] + (size_t)(rbase[bfi] + row) * 64 + c * 8);
        }
    }
    CP_COMMIT();
    CP_WAIT(0);
    __syncthreads();

    const uint32_t a_lane_row = warp_m + (lane & 15);
    const uint32_t a_lane_col = (lane >> 4) * 16;
    const uint32_t b_lane_row = warp_n + (lane & 7) + ((lane >> 4) << 3);
    const uint32_t b_lane_col = ((lane >> 3) & 1) * 16;

    float acc[2][8][4];
#pragma unroll
    for (int a = 0; a < 2; ++a)
#pragma unroll
        for (int b = 0; b < 8; ++b)
#pragma unroll
            for (int c = 0; c < 4; ++c) acc[a][b][c] = 0.f;

    const int at[3] = {0, 0, 1};   // Kh, Kh, Kl
    const int bt[3] = {2, 3, 2};   // Qh, Ql, Qh

#pragma unroll
    for (int t = 0; t < 3; ++t) {
        const uint32_t abase = s0 + at[t] * SBUF;
        const uint32_t bbase = s0 + bt[t] * SBUF;
#pragma unroll
        for (int k16 = 0; k16 < 4; ++k16) {
            uint32_t af[2][4];
#pragma unroll
            for (int fm = 0; fm < 2; ++fm)
                LDM_X4(af[fm], abase + (a_lane_row + fm * 16) * SROWB
                               + k16 * 32 + a_lane_col);
            uint32_t bfr[8][2];
#pragma unroll
            for (int fp = 0; fp < 4; ++fp) {
                uint32_t r[4];
                LDM_X4(r, bbase + (b_lane_row + fp * 16) * SROWB
                          + k16 * 32 + b_lane_col);
                bfr[fp * 2][0] = r[0]; bfr[fp * 2][1] = r[1];
                bfr[fp * 2 + 1][0] = r[2]; bfr[fp * 2 + 1][1] = r[3];
            }
#pragma unroll
            for (int fm = 0; fm < 2; ++fm)
#pragma unroll
                for (int fn = 0; fn < 8; ++fn)
                    MMA16816(acc[fm][fn], af[fm], bfr[fn][0], bfr[fn][1]);
        }
    }

    float* out = dist + ((size_t)bb << 20);
#pragma unroll
    for (int fm = 0; fm < 2; ++fm)
#pragma unroll
        for (int half = 0; half < 2; ++half) {
            int i = tit * 128 + warp_m + fm * 16 + (lane >> 2) + half * 8;
            float* orow = out + (size_t)i * 1024 + tjt * 128 + warp_n + (lane & 3) * 2;
#pragma unroll
            for (int fn = 0; fn < 8; ++fn) {
                float2 v = half
                    ? make_float2(acc[fm][fn][2] * 0.125f, acc[fm][fn][3] * 0.125f)
                    : make_float2(acc[fm][fn][0] * 0.125f, acc[fm][fn][1] * 0.125f);
                *(float2*)(orow + fn * 8) = v;
            }
        }
}

// ============================================================================
// softmax over query axis j (<= i), __expf, in-place on dist.
// ============================================================================
__global__ void __launch_bounds__(256) softmax_kernel(float* __restrict__ dist)
{
    const int i  = blockIdx.x;
    const int bb = blockIdx.y;
    float* row = dist + ((size_t)bb << 20) + (size_t)i * S_;
    const int len = i + 1;

    __shared__ float sh[S_];
    __shared__ float red[8];
    const int tid = threadIdx.x;

    float m = -3.4e38f;
    for (int j = tid; j < len; j += 256) {
        float v = row[j];
        sh[j] = v;
        m = fmaxf(m, v);
    }
#pragma unroll
    for (int o = 16; o; o >>= 1) m = fmaxf(m, __shfl_xor_sync(0xffffffffu, m, o));
    if ((tid & 31) == 0) red[tid >> 5] = m;
    __syncthreads();
    if (tid < 8) {
        m = red[tid];
#pragma unroll
        for (int o = 4; o; o >>= 1) m = fmaxf(m, __shfl_xor_sync(0xffu, m, o));
        if (tid == 0) red[0] = m;
    }
    __syncthreads();
    m = red[0];
    __syncthreads();

    float s = 0.f;
    for (int j = tid; j < len; j += 256) {
        float e = __expf(sh[j] - m);
        sh[j] = e;
        s += e;
    }
#pragma unroll
    for (int o = 16; o; o >>= 1) s += __shfl_xor_sync(0xffffffffu, s, o);
    if ((tid & 31) == 0) red[tid >> 5] = s;
    __syncthreads();
    if (tid < 8) {
        s = red[tid];
#pragma unroll
        for (int o = 4; o; o >>= 1) s += __shfl_xor_sync(0xffu, s, o);
        if (tid == 0) red[0] = s;
    }
    __syncthreads();
    const float inv = 1.f / red[0];

    for (int j = tid; j < S_; j += 256)
        row[j] = (j < len) ? sh[j] * inv : 0.f;
}

// ============================================================================
// att HMMA: att[j][bb->(b,h)] = sum_i dist[bb,i,j] * V[i,(b,h)]
// A = dist^T tile [j][i] (split in-kernel), B = V^T tile [d][i] (split).
// 3 terms; k-step 32 in i; output (B,S,H) fp32.
// smem: DhT/DlT 128x40bf16 (80B rows), VhT/VlT 64x40bf16.
// ============================================================================
#define DT_OFF(buf) ((buf) * 10240u)            // 2 bufs: Dh, Dl
#define VT_OFF(buf) (20480u + (buf) * 5120u)    // 2 bufs: Vh, Vl
#define ATT_SMEM 30720

__global__ void __launch_bounds__(256) att_hmma_kernel(
    const float* __restrict__ dist, const float* __restrict__ Vp,
    float* __restrict__ att)
{
    extern __shared__ char sm[];
    const uint32_t s0 = smem_u32(sm);
    const int jt = blockIdx.x;           // j tile (128)
    const int bb = blockIdx.y;
    const int h = bb >> 3;
    const int b = bb & 7;
    const int j0 = jt * 128;

    const int tid  = threadIdx.x;
    const int wid  = tid >> 5;
    const int lane = tid & 31;
    const int warp_m = (wid & 3) * 32;   // j
    const int warp_n = (wid >> 2) * 32;  // d

    const int li = tid & 31;             // i within 32-chunk
    const int lg = tid >> 5;             // group 0..7

    const float* dbase = dist + ((size_t)bb << 20);
    const float* vbase = Vp + (size_t)b * 1024 + (size_t)h * 64;

    float acc[2][4][4];
#pragma unroll
    for (int a = 0; a < 2; ++a)
#pragma unroll
        for (int c = 0; c < 4; ++c)
#pragma unroll
            for (int e = 0; e < 4; ++e) acc[a][c][e] = 0.f;

    const int nsteps = (1024 - j0) / 32;
    float4 dreg[4];
    float4 vreg[2];

#define PRELOAD(i0_) do {                                                      \
    const float* dr_ = dbase + (size_t)((i0_) + li) * 1024 + j0 + lg * 16;     \
    dreg[0] = *(const float4*)(dr_);                                           \
    dreg[1] = *(const float4*)(dr_ + 4);                                       \
    dreg[2] = *(const float4*)(dr_ + 8);                                       \
    dreg[3] = *(const float4*)(dr_ + 12);                                      \
    const float* vr_ = vbase + (size_t)((i0_) + li) * 8192 + lg * 8;           \
    vreg[0] = *(const float4*)(vr_);                                           \
    vreg[1] = *(const float4*)(vr_ + 4);                                       \
} while (0)

    PRELOAD(j0);

    for (int step = 0; step < nsteps; ++step) {
        __syncthreads();
        // store dist tile transposed + split: DsT[j][i]
#pragma unroll
        for (int q = 0; q < 4; ++q) {
            float vals[4] = {dreg[q].x, dreg[q].y, dreg[q].z, dreg[q].w};
#pragma unroll
            for (int e = 0; e < 4; ++e) {
                int j = lg * 16 + q * 4 + e;
                __nv_bfloat16 hi = __float2bfloat16_rn(vals[e]);
                __nv_bfloat16 lo = __float2bfloat16_rn(vals[e] - __bfloat162float(hi));
                *(__nv_bfloat16*)(sm + DT_OFF(0) + j * 80 + li * 2) = hi;
                *(__nv_bfloat16*)(sm + DT_OFF(1) + j * 80 + li * 2) = lo;
            }
        }
        // store V tile transposed + split: VsT[d][i]
#pragma unroll
        for (int q = 0; q < 2; ++q) {
            float vals[4] = {vreg[q].x, vreg[q].y, vreg[q].z, vreg[q].w};
#pragma unroll
            for (int e = 0; e < 4; ++e) {
                int d = lg * 8 + q * 4 + e;
                __nv_bfloat16 hi = __float2bfloat16_rn(vals[e]);
                __nv_bfloat16 lo = __float2bfloat16_rn(vals[e] - __bfloat162float(hi));
                *(__nv_bfloat16*)(sm + VT_OFF(0) + d * 80 + li * 2) = hi;
                *(__nv_bfloat16*)(sm + VT_OFF(1) + d * 80 + li * 2) = lo;
            }
        }
        __syncthreads();
        if (step + 1 < nsteps) PRELOAD(j0 + (step + 1) * 32);

        const uint32_t a_lane_row = warp_m + (lane & 15);
        const uint32_t a_lane_col = (lane >> 4) * 16;
        const uint32_t b_lane_row = warp_n + (lane & 7) + ((lane >> 4) << 3);
        const uint32_t b_lane_col = ((lane >> 3) & 1) * 16;

#pragma unroll
        for (int k16 = 0; k16 < 2; ++k16) {
            uint32_t aH[2][4], aL[2][4];
#pragma unroll
            for (int fm = 0; fm < 2; ++fm) {
                LDM_X4(aH[fm], s0 + DT_OFF(0) + (a_lane_row + fm * 16) * 80
                               + k16 * 32 + a_lane_col);
                LDM_X4(aL[fm], s0 + DT_OFF(1) + (a_lane_row + fm * 16) * 80
                               + k16 * 32 + a_lane_col);
            }
            uint32_t bH[4][2], bL[4][2];
#pragma unroll
            for (int fp = 0; fp < 2; ++fp) {
                uint32_t r[4];
                LDM_X4(r, s0 + VT_OFF(0) + (b_lane_row + fp * 16) * 80
                          + k16 * 32 + b_lane_col);
                bH[fp * 2][0] = r[0]; bH[fp * 2][1] = r[1];
                bH[fp * 2 + 1][0] = r[2]; bH[fp * 2 + 1][1] = r[3];
                LDM_X4(r, s0 + VT_OFF(1) + (b_lane_row + fp * 16) * 80
                          + k16 * 32 + b_lane_col);
                bL[fp * 2][0] = r[0]; bL[fp * 2][1] = r[1];
                bL[fp * 2 + 1][0] = r[2]; bL[fp * 2 + 1][1] = r[3];
            }
#pragma unroll
            for (int fm = 0; fm < 2; ++fm)
#pragma unroll
                for (int fn = 0; fn < 4; ++fn) {
                    MMA16816(acc[fm][fn], aH[fm], bH[fn][0], bH[fn][1]);
                    MMA16816(acc[fm][fn], aH[fm], bL[fn][0], bL[fn][1]);
                    MMA16816(acc[fm][fn], aL[fm], bH[fn][0], bH[fn][1]);
                }
        }
    }
#undef PRELOAD

#pragma unroll
    for (int fm = 0; fm < 2; ++fm)
#pragma unroll
        for (int half = 0; half < 2; ++half) {
            int j = j0 + warp_m + fm * 16 + (lane >> 2) + half * 8;
            float* cr = att + ((size_t)b * 1024 + j) * 1024 + h * 64
                        + warp_n + (lane & 3) * 2;
#pragma unroll
            for (int fn = 0; fn < 4; ++fn) {
                float2 v = half ? make_float2(acc[fm][fn][2], acc[fm][fn][3])
                                : make_float2(acc[fm][fn][0], acc[fm][fn][1]);
                *(float2*)(cr + fn * 8) = v;
            }
        }
}

// ---------------------------------------------------------------------------
extern "C" void kernel_launch(void* const* d_in, const int* in_sizes, int n_in,
                              void* d_out, int out_size)
{
    const float* value = (const float*)d_in[0];
    const float* key   = (const float*)d_in[1];
    const float* query = (const float*)d_in[2];
    const float* Wq    = (const float*)d_in[3];
    const float* Wk    = (const float*)d_in[4];
    const float* Wv    = (const float*)d_in[5];
    const float* Wo    = (const float*)d_in[6];
    float* out = (float*)d_out;

    float* g_v_p;   cudaGetSymbolAddress((void**)&g_v_p,   g_v);
    float* g_att_p; cudaGetSymbolAddress((void**)&g_att_p, g_att);
    __nv_bfloat16 *ah, *al, *wh, *wl, *qh, *ql, *kh, *kl;
    cudaGetSymbolAddress((void**)&ah, g_a_hi);
    cudaGetSymbolAddress((void**)&al, g_a_lo);
    cudaGetSymbolAddress((void**)&wh, g_w_hi);
    cudaGetSymbolAddress((void**)&wl, g_w_lo);
    cudaGetSymbolAddress((void**)&qh, g_qh);
    cudaGetSymbolAddress((void**)&ql, g_ql);
    cudaGetSymbolAddress((void**)&kh, g_kh);
    cudaGetSymbolAddress((void**)&kl, g_kl);

    float* dist_p;
    if ((long long)out_size == (long long)OUT_ELEMS + (long long)DIST_ELEMS) {
        dist_p = out + OUT_ELEMS;
    } else {
        cudaGetSymbolAddress((void**)&dist_p, g_dist_fallback);
    }

    static int attr_done = 0;
    if (!attr_done) {
        cudaFuncSetAttribute(scores_hmma_kernel,
                             cudaFuncAttributeMaxDynamicSharedMemorySize, 4 * SBUF);
        cudaFuncSetAttribute(att_hmma_kernel,
                             cudaFuncAttributeMaxDynamicSharedMemorySize, ATT_SMEM);
        attr_done = 1;
    }

    dim3 blk(256);
    dim3 grid_g(8, 64);
    const int A4 = SB_ * H_ / 4;
    const int W4 = H_ * H_ / 4;

    // Q projection -> split head-major
    conv_split_kernel<<<(A4 + 255) / 256, blk>>>((const float4*)query, (uint32_t*)ah, (uint32_t*)al, A4);
    conv_split_kernel<<<(W4 + 255) / 256, blk>>>((const float4*)Wq, (uint32_t*)wh, (uint32_t*)wl, W4);
    gemm_split_hmma_kernel<<<grid_g, blk>>>(ah, al, wh, wl, nullptr, qh, ql, 2);
    // K projection -> split head-major
    conv_split_kernel<<<(A4 + 255) / 256, blk>>>((const float4*)key, (uint32_t*)ah, (uint32_t*)al, A4);
    conv_split_kernel<<<(W4 + 255) / 256, blk>>>((const float4*)Wk, (uint32_t*)wh, (uint32_t*)wl, W4);
    gemm_split_hmma_kernel<<<grid_g, blk>>>(ah, al, wh, wl, nullptr, kh, kl, 2);
    // V projection -> fp32
    conv_split_kernel<<<(A4 + 255) / 256, blk>>>((const float4*)value, (uint32_t*)ah, (uint32_t*)al, A4);
    conv_split_kernel<<<(W4 + 255) / 256, blk>>>((const float4*)Wv, (uint32_t*)wh, (uint32_t*)wl, W4);
    gemm_split_hmma_kernel<<<grid_g, blk>>>(ah, al, wh, wl, g_v_p, nullptr, nullptr, 0);

    // scores (lower-tri 128-tiles)
    dim3 grid_sc(36, 128);
    scores_hmma_kernel<<<grid_sc, blk, 4 * SBUF>>>(qh, ql, kh, kl, dist_p);

    // softmax
    dim3 grid_sm(1024, 128);
    softmax_kernel<<<grid_sm, blk>>>(dist_p);

    // att
    dim3 grid_att(8, 128);
    att_hmma_kernel<<<grid_att, blk, ATT_SMEM>>>(dist_p, g_v_p, g_att_p);

    // output projection
    conv_split_kernel<<<(A4 + 255) / 256, blk>>>((const float4*)g_att_p, (uint32_t*)ah, (uint32_t*)al, A4);
    conv_split_kernel<<<(W4 + 255) / 256, blk>>>((const float4*)Wo, (uint32_t*)wh, (uint32_t*)wl, W4);
    gemm_split_hmma_kernel<<<grid_g, blk>>>(ah, al, wh, wl, out, nullptr, nullptr, 1);
}

// round 6
// speedup vs baseline: 1.8817x; 1.1689x over previous
#include <cuda_runtime.h>
#include <cuda_bf16.h>
#include <math.h>
#include <stdint.h>

// Problem constants
#define S_   1024
#define B_   8
#define H_   1024
#define NH_  16
#define DK_  64
#define BH_  128
#define SB_  8192
#define OUT_ELEMS  (S_*B_*H_)
#define DIST_ELEMS (BH_*S_*S_)

// ---------------- scratch ----------------
__device__ float g_v[SB_ * H_];
__device__ float g_att[SB_ * H_];
__device__ float g_dist_fallback[DIST_ELEMS];
__device__ float g_rowm[BH_ * S_];
__device__ float g_rowl[BH_ * S_];
__device__ __nv_bfloat16 g_a_hi[SB_ * H_];
__device__ __nv_bfloat16 g_a_lo[SB_ * H_];
__device__ __nv_bfloat16 g_w_hi[H_ * H_];
__device__ __nv_bfloat16 g_w_lo[H_ * H_];
__device__ __nv_bfloat16 g_qh[SB_ * H_];
__device__ __nv_bfloat16 g_ql[SB_ * H_];
__device__ __nv_bfloat16 g_kh[SB_ * H_];
__device__ __nv_bfloat16 g_kl[SB_ * H_];

__device__ __forceinline__ uint32_t smem_u32(const void* p) {
    uint32_t a;
    asm("{ .reg .u64 t; cvta.to.shared.u64 t, %1; cvt.u32.u64 %0, t; }"
        : "=r"(a) : "l"(p));
    return a;
}
__device__ __forceinline__ void cp_async16(uint32_t dst, const void* src) {
    asm volatile("cp.async.ca.shared.global [%0], [%1], 16;" :: "r"(dst), "l"(src));
}
#define CP_COMMIT() asm volatile("cp.async.commit_group;" ::: "memory")
#define CP_WAIT(N)  asm volatile("cp.async.wait_group %0;" :: "n"(N) : "memory")

#define LDM_X4(r, addr)                                                        \
    asm volatile("ldmatrix.sync.aligned.m8n8.x4.shared.b16 {%0,%1,%2,%3}, [%4];" \
                 : "=r"((r)[0]), "=r"((r)[1]), "=r"((r)[2]), "=r"((r)[3]) : "r"(addr))
#define LDM_X4_T(r, addr)                                                      \
    asm volatile("ldmatrix.sync.aligned.m8n8.x4.trans.shared.b16 {%0,%1,%2,%3}, [%4];" \
                 : "=r"((r)[0]), "=r"((r)[1]), "=r"((r)[2]), "=r"((r)[3]) : "r"(addr))

#define MMA16816(acc, a, b0, b1)                                               \
    asm volatile("mma.sync.aligned.m16n8k16.row.col.f32.bf16.bf16.f32 "        \
                 "{%0,%1,%2,%3}, {%4,%5,%6,%7}, {%8,%9}, {%0,%1,%2,%3};"       \
                 : "+f"((acc)[0]), "+f"((acc)[1]), "+f"((acc)[2]), "+f"((acc)[3]) \
                 : "r"((a)[0]), "r"((a)[1]), "r"((a)[2]), "r"((a)[3]),         \
                   "r"(b0), "r"(b1))

__device__ __forceinline__ void split2(float x, float y,
                                       uint32_t& hi, uint32_t& lo) {
    __nv_bfloat162 h = __floats2bfloat162_rn(x, y);
    float rx = x - __bfloat162float(h.x);
    float ry = y - __bfloat162float(h.y);
    __nv_bfloat162 l = __floats2bfloat162_rn(rx, ry);
    hi = *(uint32_t*)&h;
    lo = *(uint32_t*)&l;
}

// ============================================================================
// Split fp32 -> bf16 hi/lo (flat)
// ============================================================================
__global__ void __launch_bounds__(256) conv_split_kernel(
    const float4* __restrict__ X, uint32_t* __restrict__ hi,
    uint32_t* __restrict__ lo, int n4)
{
    int i = blockIdx.x * 256 + threadIdx.x;
    if (i >= n4) return;
    float4 v = X[i];
    uint32_t h0, l0, h1, l1;
    split2(v.x, v.y, h0, l0);
    split2(v.z, v.w, h1, l1);
    hi[2 * i] = h0; hi[2 * i + 1] = h1;
    lo[2 * i] = l0; lo[2 * i + 1] = l1;
}

// ============================================================================
// HMMA split-bf16 GEMM, 3-stage cp.async ring.  C[8192,1024] = A @ W^T.
// mode 0: fp32 out; mode 1: fp32 out + (b,s)->(s,b) row perm;
// mode 2: split bf16 head-major out [h*8+b][s][d].
// ============================================================================
#define ROWB 80
#define GSTAGE 20480            // A(10240) + W(10240) per stage
#define GEMM_SMEM (3 * GSTAGE)  // 61440

__global__ void __launch_bounds__(256) gemm_split_hmma_kernel(
    const __nv_bfloat16* __restrict__ Ah, const __nv_bfloat16* __restrict__ Al,
    const __nv_bfloat16* __restrict__ Wh, const __nv_bfloat16* __restrict__ Wl,
    float* __restrict__ C, __nv_bfloat16* __restrict__ Oh,
    __nv_bfloat16* __restrict__ Ol, int mode)
{
    extern __shared__ char gsm[];
    const uint32_t s0 = smem_u32(gsm);

    const int tid  = threadIdx.x;
    const int wid  = tid >> 5;
    const int lane = tid & 31;
    const int m0 = blockIdx.y * 128;
    const int n0 = blockIdx.x * 128;
    const int warp_m = (wid & 3) * 32;
    const int warp_n = (wid >> 2) * 64;

    const __nv_bfloat16* aterm[3] = {Ah, Ah, Al};
    const __nv_bfloat16* wterm[3] = {Wh, Wl, Wh};

    float acc[2][8][4];
#pragma unroll
    for (int a = 0; a < 2; ++a)
#pragma unroll
        for (int b = 0; b < 8; ++b)
#pragma unroll
            for (int c = 0; c < 4; ++c) acc[a][b][c] = 0.f;

#define LOAD_STAGE(st, kt) do {                                                \
    int term_ = (kt) >> 5;                                                     \
    int kk_ = ((kt) & 31) * 32;                                                \
    const __nv_bfloat16* ga_ = aterm[term_] + (size_t)m0 * 1024 + kk_;         \
    const __nv_bfloat16* gw_ = wterm[term_] + (size_t)n0 * 1024 + kk_;         \
    uint32_t base_ = s0 + (st) * GSTAGE;                                       \
    _Pragma("unroll")                                                          \
    for (int l_ = 0; l_ < 2; ++l_) {                                           \
        int id_ = tid + 256 * l_;                                              \
        int row_ = id_ >> 2, c_ = id_ & 3;                                     \
        cp_async16(base_ + row_ * ROWB + c_ * 16,                              \
                   ga_ + (size_t)row_ * 1024 + c_ * 8);                        \
        cp_async16(base_ + 10240u + row_ * ROWB + c_ * 16,                     \
                   gw_ + (size_t)row_ * 1024 + c_ * 8);                        \
    }                                                                          \
    CP_COMMIT();                                                               \
} while (0)

    LOAD_STAGE(0, 0);
    LOAD_STAGE(1, 1);

    const uint32_t a_lane_row = warp_m + (lane & 15);
    const uint32_t a_lane_col = (lane >> 4) * 16;
    const uint32_t b_lane_row = warp_n + (lane & 7) + ((lane >> 4) << 3);
    const uint32_t b_lane_col = ((lane >> 3) & 1) * 16;

    for (int kt = 0; kt < 96; ++kt) {
        const int st = kt - (kt / 3) * 3;
        if (kt < 94) CP_WAIT(1); else CP_WAIT(0);
        __syncthreads();
        if (kt + 2 < 96) {
            int st2 = (kt + 2) - ((kt + 2) / 3) * 3;
            LOAD_STAGE(st2, kt + 2);
        }

        const uint32_t abase = s0 + st * GSTAGE;
        const uint32_t bbase = abase + 10240u;

#pragma unroll
        for (int k16 = 0; k16 < 2; ++k16) {
            uint32_t af[2][4];
#pragma unroll
            for (int fm = 0; fm < 2; ++fm)
                LDM_X4(af[fm], abase + (a_lane_row + fm * 16) * ROWB
                               + k16 * 32 + a_lane_col);
            uint32_t bf[8][2];
#pragma unroll
            for (int fp = 0; fp < 4; ++fp) {
                uint32_t r[4];
                LDM_X4(r, bbase + (b_lane_row + fp * 16) * ROWB
                          + k16 * 32 + b_lane_col);
                bf[fp * 2][0] = r[0]; bf[fp * 2][1] = r[1];
                bf[fp * 2 + 1][0] = r[2]; bf[fp * 2 + 1][1] = r[3];
            }
#pragma unroll
            for (int fm = 0; fm < 2; ++fm)
#pragma unroll
                for (int fn = 0; fn < 8; ++fn)
                    MMA16816(acc[fm][fn], af[fm], bf[fn][0], bf[fn][1]);
        }
    }

#pragma unroll
    for (int fm = 0; fm < 2; ++fm) {
#pragma unroll
        for (int half = 0; half < 2; ++half) {
            int m = m0 + warp_m + fm * 16 + (lane >> 2) + half * 8;
            if (mode == 2) {
                int s = m >> 3, b = m & 7;
#pragma unroll
                for (int fn = 0; fn < 8; ++fn) {
                    int col = n0 + warp_n + (lane & 3) * 2 + fn * 8;
                    int h = col >> 6, d = col & 63;
                    size_t addr = ((size_t)(h * 8 + b) * 1024 + s) * 64 + d;
                    uint32_t hi, lo;
                    split2(acc[fm][fn][half * 2], acc[fm][fn][half * 2 + 1], hi, lo);
                    *(uint32_t*)(Oh + addr) = hi;
                    *(uint32_t*)(Ol + addr) = lo;
                }
            } else {
                int orow = mode ? ((m & (S_ - 1)) * B_ + (m >> 10)) : m;
                float* cr = C + (size_t)orow * 1024 + n0 + warp_n + (lane & 3) * 2;
#pragma unroll
                for (int fn = 0; fn < 8; ++fn) {
                    float2 v = half ? make_float2(acc[fm][fn][2], acc[fm][fn][3])
                                    : make_float2(acc[fm][fn][0], acc[fm][fn][1]);
                    *(float2*)(cr + fn * 8) = v;
                }
            }
        }
    }
#undef LOAD_STAGE
}

// ============================================================================
// scores HMMA (unchanged from R5): raw lower-tri 128x128 tiles into dist.
// ============================================================================
#define SROWB 144
#define SBUF  18432

__global__ void __launch_bounds__(256) scores_hmma_kernel(
    const __nv_bfloat16* __restrict__ Qh, const __nv_bfloat16* __restrict__ Ql,
    const __nv_bfloat16* __restrict__ Kh, const __nv_bfloat16* __restrict__ Kl,
    float* __restrict__ dist)
{
    extern __shared__ char sm[];
    const uint32_t s0 = smem_u32(sm);
    const int pid = blockIdx.x;
    const int bb  = blockIdx.y;
    int tit = 0;
    while ((tit + 1) * (tit + 2) / 2 <= pid) ++tit;
    const int tjt = pid - tit * (tit + 1) / 2;

    const int tid  = threadIdx.x;
    const int wid  = tid >> 5;
    const int lane = tid & 31;
    const int warp_m = (wid & 3) * 32;
    const int warp_n = (wid >> 2) * 64;

    const size_t hb = (size_t)bb * 65536;
    const __nv_bfloat16* srcs[4] = {Kh + hb, Kl + hb, Qh + hb, Ql + hb};
    const int rbase[4] = {tit * 128, tit * 128, tjt * 128, tjt * 128};

#pragma unroll
    for (int bfi = 0; bfi < 4; ++bfi) {
#pragma unroll
        for (int l = 0; l < 4; ++l) {
            int id = tid + 256 * l;
            int row = id >> 3, c = id & 7;
            cp_async16(s0 + bfi * SBUF + row * SROWB + c * 16,
                       srcs[bfi] + (size_t)(rbase[bfi] + row) * 64 + c * 8);
        }
    }
    CP_COMMIT();
    CP_WAIT(0);
    __syncthreads();

    const uint32_t a_lane_row = warp_m + (lane & 15);
    const uint32_t a_lane_col = (lane >> 4) * 16;
    const uint32_t b_lane_row = warp_n + (lane & 7) + ((lane >> 4) << 3);
    const uint32_t b_lane_col = ((lane >> 3) & 1) * 16;

    float acc[2][8][4];
#pragma unroll
    for (int a = 0; a < 2; ++a)
#pragma unroll
        for (int b = 0; b < 8; ++b)
#pragma unroll
            for (int c = 0; c < 4; ++c) acc[a][b][c] = 0.f;

    const int at[3] = {0, 0, 1};
    const int bt[3] = {2, 3, 2};

#pragma unroll
    for (int t = 0; t < 3; ++t) {
        const uint32_t abase = s0 + at[t] * SBUF;
        const uint32_t bbase = s0 + bt[t] * SBUF;
#pragma unroll
        for (int k16 = 0; k16 < 4; ++k16) {
            uint32_t af[2][4];
#pragma unroll
            for (int fm = 0; fm < 2; ++fm)
                LDM_X4(af[fm], abase + (a_lane_row + fm * 16) * SROWB
                               + k16 * 32 + a_lane_col);
            uint32_t bfr[8][2];
#pragma unroll
            for (int fp = 0; fp < 4; ++fp) {
                uint32_t r[4];
                LDM_X4(r, bbase + (b_lane_row + fp * 16) * SROWB
                          + k16 * 32 + b_lane_col);
                bfr[fp * 2][0] = r[0]; bfr[fp * 2][1] = r[1];
                bfr[fp * 2 + 1][0] = r[2]; bfr[fp * 2 + 1][1] = r[3];
            }
#pragma unroll
            for (int fm = 0; fm < 2; ++fm)
#pragma unroll
                for (int fn = 0; fn < 8; ++fn)
                    MMA16816(acc[fm][fn], af[fm], bfr[fn][0], bfr[fn][1]);
        }
    }

    float* out = dist + ((size_t)bb << 20);
#pragma unroll
    for (int fm = 0; fm < 2; ++fm)
#pragma unroll
        for (int half = 0; half < 2; ++half) {
            int i = tit * 128 + warp_m + fm * 16 + (lane >> 2) + half * 8;
            float* orow = out + (size_t)i * 1024 + tjt * 128 + warp_n + (lane & 3) * 2;
#pragma unroll
            for (int fn = 0; fn < 8; ++fn) {
                float2 v = half
                    ? make_float2(acc[fm][fn][2] * 0.125f, acc[fm][fn][3] * 0.125f)
                    : make_float2(acc[fm][fn][0] * 0.125f, acc[fm][fn][1] * 0.125f);
                *(float2*)(orow + fn * 8) = v;
            }
        }
}

// ============================================================================
// rowstat: per (bb, i) compute m = max_j<=i s, invl = 1/sum __expf(s - m).
// ============================================================================
__global__ void __launch_bounds__(256) rowstat_kernel(
    const float* __restrict__ dist, float* __restrict__ rowm,
    float* __restrict__ rowl)
{
    const int i  = blockIdx.x;
    const int bb = blockIdx.y;
    const float* row = dist + ((size_t)bb << 20) + (size_t)i * S_;
    const int len = i + 1;

    __shared__ float sh[S_];
    __shared__ float red[8];
    const int tid = threadIdx.x;

    float m = -3.4e38f;
    for (int j = tid; j < len; j += 256) {
        float v = row[j];
        sh[j] = v;
        m = fmaxf(m, v);
    }
#pragma unroll
    for (int o = 16; o; o >>= 1) m = fmaxf(m, __shfl_xor_sync(0xffffffffu, m, o));
    if ((tid & 31) == 0) red[tid >> 5] = m;
    __syncthreads();
    if (tid < 8) {
        m = red[tid];
#pragma unroll
        for (int o = 4; o; o >>= 1) m = fmaxf(m, __shfl_xor_sync(0xffu, m, o));
        if (tid == 0) red[0] = m;
    }
    __syncthreads();
    m = red[0];
    __syncthreads();

    float s = 0.f;
    for (int j = tid; j < len; j += 256)
        s += __expf(sh[j] - m);
#pragma unroll
    for (int o = 16; o; o >>= 1) s += __shfl_xor_sync(0xffffffffu, s, o);
    if ((tid & 31) == 0) red[tid >> 5] = s;
    __syncthreads();
    if (tid < 8) {
        s = red[tid];
#pragma unroll
        for (int o = 4; o; o >>= 1) s += __shfl_xor_sync(0xffu, s, o);
        if (tid == 0) {
            rowm[(bb << 10) + i] = m;
            rowl[(bb << 10) + i] = 1.f / s;
        }
    }
}

// ============================================================================
// att fused: for (bb, j-tile 128): write zero upper dist tiles; then stream
// i-chunks of 32: read raw scores, p = __expf(s-m)*invl (masked), write p to
// dist, split to bf16 hi/lo smem, HMMA accumulate with V (ldmatrix.trans).
// Output att (B,S,H) fp32.
// ============================================================================
__global__ void __launch_bounds__(256) att_fused_kernel(
    float* __restrict__ dist, const float* __restrict__ Vp,
    const float* __restrict__ rowm, const float* __restrict__ rowl,
    float* __restrict__ att)
{
    __shared__ __nv_bfloat16 Ps[2][32][136];   // [hi/lo][i][j] rows 272B
    __shared__ __nv_bfloat16 Vs[2][32][72];    // [hi/lo][i][d] rows 144B

    const int jt = blockIdx.x;
    const int bb = blockIdx.y;
    const int h = bb >> 3;
    const int b = bb & 7;
    const int j0 = jt * 128;

    const int tid  = threadIdx.x;
    const int wid  = tid >> 5;
    const int lane = tid & 31;
    const int warp_m = (wid & 3) * 32;   // j
    const int warp_n = (wid >> 2) * 32;  // d

    float* dbase = dist + ((size_t)bb << 20);
    const float* vbase = Vp + (size_t)b * 1024 + (size_t)h * 64;
    const float* mrow = rowm + (bb << 10);
    const float* lrow = rowl + (bb << 10);

    // zero the upper-triangular tiles of this column band
    const float4 z4 = make_float4(0.f, 0.f, 0.f, 0.f);
    for (int it = 0; it < jt; ++it) {
#pragma unroll
        for (int q = 0; q < 16; ++q) {
            int id = tid + 256 * q;
            int r = id >> 5, c4 = id & 31;
            *(float4*)(dbase + (size_t)(it * 128 + r) * 1024 + j0 + c4 * 4) = z4;
        }
    }

    const uint32_t PhB = smem_u32(&Ps[0][0][0]);
    const uint32_t PlB = smem_u32(&Ps[1][0][0]);
    const uint32_t VhB = smem_u32(&Vs[0][0][0]);
    const uint32_t VlB = smem_u32(&Vs[1][0][0]);

    float acc[2][4][4];
#pragma unroll
    for (int a = 0; a < 2; ++a)
#pragma unroll
        for (int c = 0; c < 4; ++c)
#pragma unroll
            for (int e = 0; e < 4; ++e) acc[a][c][e] = 0.f;

    const int nsteps = (1024 - j0) / 32;

    for (int step = 0; step < nsteps; ++step) {
        const int i0 = j0 + step * 32;

        // ---- score tile -> p -> dist + smem split ----
#pragma unroll
        for (int q = 0; q < 4; ++q) {
            int id = tid + 256 * q;
            int r = id >> 5, c4 = id & 31;
            const int iv = i0 + r;
            float4 s = *(const float4*)(dbase + (size_t)iv * 1024 + j0 + c4 * 4);
            float m  = __ldg(mrow + iv);
            float il = __ldg(lrow + iv);
            int jv = j0 + c4 * 4;
            float p0 = (jv + 0 <= iv) ? __expf(s.x - m) * il : 0.f;
            float p1 = (jv + 1 <= iv) ? __expf(s.y - m) * il : 0.f;
            float p2 = (jv + 2 <= iv) ? __expf(s.z - m) * il : 0.f;
            float p3 = (jv + 3 <= iv) ? __expf(s.w - m) * il : 0.f;
            *(float4*)(dbase + (size_t)iv * 1024 + j0 + c4 * 4)
                = make_float4(p0, p1, p2, p3);
            uint32_t h0, l0, h1, l1;
            split2(p0, p1, h0, l0);
            split2(p2, p3, h1, l1);
            *(uint2*)(&Ps[0][r][c4 * 4]) = make_uint2(h0, h1);
            *(uint2*)(&Ps[1][r][c4 * 4]) = make_uint2(l0, l1);
        }
        // ---- V tile 32 x 64 ----
#pragma unroll
        for (int q = 0; q < 2; ++q) {
            int id = tid + 256 * q;
            int r = id >> 4, c4 = id & 15;
            float4 v = *(const float4*)(vbase + (size_t)(i0 + r) * 8192 + c4 * 4);
            uint32_t h0, l0, h1, l1;
            split2(v.x, v.y, h0, l0);
            split2(v.z, v.w, h1, l1);
            *(uint2*)(&Vs[0][r][c4 * 4]) = make_uint2(h0, h1);
            *(uint2*)(&Vs[1][r][c4 * 4]) = make_uint2(l0, l1);
        }
        __syncthreads();

        // ---- MMA: A = P^T (j x i) via trans, B = V (i x d) via trans ----
#pragma unroll
        for (int k16 = 0; k16 < 2; ++k16) {
            const uint32_t arow = k16 * 16 + ((lane >> 4) << 3) + (lane & 7);
            uint32_t aH[2][4], aL[2][4];
#pragma unroll
            for (int fm = 0; fm < 2; ++fm) {
                const uint32_t acolb =
                    (warp_m + fm * 16 + (((lane >> 3) & 1) << 3)) * 2;
                LDM_X4_T(aH[fm], PhB + arow * 272 + acolb);
                LDM_X4_T(aL[fm], PlB + arow * 272 + acolb);
            }
            const uint32_t brow = k16 * 16 + (((lane >> 3) & 1) << 3) + (lane & 7);
            uint32_t bH[4][2], bL[4][2];
#pragma unroll
            for (int fp = 0; fp < 2; ++fp) {
                const uint32_t bcolb =
                    (warp_n + fp * 16 + ((lane >> 4) << 3)) * 2;
                uint32_t r[4];
                LDM_X4_T(r, VhB + brow * 144 + bcolb);
                bH[fp * 2][0] = r[0]; bH[fp * 2][1] = r[1];
                bH[fp * 2 + 1][0] = r[2]; bH[fp * 2 + 1][1] = r[3];
                LDM_X4_T(r, VlB + brow * 144 + bcolb);
                bL[fp * 2][0] = r[0]; bL[fp * 2][1] = r[1];
                bL[fp * 2 + 1][0] = r[2]; bL[fp * 2 + 1][1] = r[3];
            }
#pragma unroll
            for (int fm = 0; fm < 2; ++fm)
#pragma unroll
                for (int fn = 0; fn < 4; ++fn) {
                    MMA16816(acc[fm][fn], aH[fm], bH[fn][0], bH[fn][1]);
                    MMA16816(acc[fm][fn], aH[fm], bL[fn][0], bL[fn][1]);
                    MMA16816(acc[fm][fn], aL[fm], bH[fn][0], bH[fn][1]);
                }
        }
        __syncthreads();
    }

#pragma unroll
    for (int fm = 0; fm < 2; ++fm)
#pragma unroll
        for (int half = 0; half < 2; ++half) {
            int j = j0 + warp_m + fm * 16 + (lane >> 2) + half * 8;
            float* cr = att + ((size_t)b * 1024 + j) * 1024 + h * 64
                        + warp_n + (lane & 3) * 2;
#pragma unroll
            for (int fn = 0; fn < 4; ++fn) {
                float2 v = half ? make_float2(acc[fm][fn][2], acc[fm][fn][3])
                                : make_float2(acc[fm][fn][0], acc[fm][fn][1]);
                *(float2*)(cr + fn * 8) = v;
            }
        }
}

// ---------------------------------------------------------------------------
extern "C" void kernel_launch(void* const* d_in, const int* in_sizes, int n_in,
                              void* d_out, int out_size)
{
    const float* value = (const float*)d_in[0];
    const float* key   = (const float*)d_in[1];
    const float* query = (const float*)d_in[2];
    const float* Wq    = (const float*)d_in[3];
    const float* Wk    = (const float*)d_in[4];
    const float* Wv    = (const float*)d_in[5];
    const float* Wo    = (const float*)d_in[6];
    float* out = (float*)d_out;

    float* g_v_p;   cudaGetSymbolAddress((void**)&g_v_p,   g_v);
    float* g_att_p; cudaGetSymbolAddress((void**)&g_att_p, g_att);
    float* rm_p;    cudaGetSymbolAddress((void**)&rm_p,    g_rowm);
    float* rl_p;    cudaGetSymbolAddress((void**)&rl_p,    g_rowl);
    __nv_bfloat16 *ah, *al, *wh, *wl, *qh, *ql, *kh, *kl;
    cudaGetSymbolAddress((void**)&ah, g_a_hi);
    cudaGetSymbolAddress((void**)&al, g_a_lo);
    cudaGetSymbolAddress((void**)&wh, g_w_hi);
    cudaGetSymbolAddress((void**)&wl, g_w_lo);
    cudaGetSymbolAddress((void**)&qh, g_qh);
    cudaGetSymbolAddress((void**)&ql, g_ql);
    cudaGetSymbolAddress((void**)&kh, g_kh);
    cudaGetSymbolAddress((void**)&kl, g_kl);

    float* dist_p;
    if ((long long)out_size == (long long)OUT_ELEMS + (long long)DIST_ELEMS) {
        dist_p = out + OUT_ELEMS;
    } else {
        cudaGetSymbolAddress((void**)&dist_p, g_dist_fallback);
    }

    static int attr_done = 0;
    if (!attr_done) {
        cudaFuncSetAttribute(gemm_split_hmma_kernel,
                             cudaFuncAttributeMaxDynamicSharedMemorySize, GEMM_SMEM);
        cudaFuncSetAttribute(scores_hmma_kernel,
                             cudaFuncAttributeMaxDynamicSharedMemorySize, 4 * SBUF);
        attr_done = 1;
    }

    dim3 blk(256);
    dim3 grid_g(8, 64);
    const int A4 = SB_ * H_ / 4;
    const int W4 = H_ * H_ / 4;

    conv_split_kernel<<<(A4 + 255) / 256, blk>>>((const float4*)query, (uint32_t*)ah, (uint32_t*)al, A4);
    conv_split_kernel<<<(W4 + 255) / 256, blk>>>((const float4*)Wq, (uint32_t*)wh, (uint32_t*)wl, W4);
    gemm_split_hmma_kernel<<<grid_g, blk, GEMM_SMEM>>>(ah, al, wh, wl, nullptr, qh, ql, 2);
    conv_split_kernel<<<(A4 + 255) / 256, blk>>>((const float4*)key, (uint32_t*)ah, (uint32_t*)al, A4);
    conv_split_kernel<<<(W4 + 255) / 256, blk>>>((const float4*)Wk, (uint32_t*)wh, (uint32_t*)wl, W4);
    gemm_split_hmma_kernel<<<grid_g, blk, GEMM_SMEM>>>(ah, al, wh, wl, nullptr, kh, kl, 2);
    conv_split_kernel<<<(A4 + 255) / 256, blk>>>((const float4*)value, (uint32_t*)ah, (uint32_t*)al, A4);
    conv_split_kernel<<<(W4 + 255) / 256, blk>>>((const float4*)Wv, (uint32_t*)wh, (uint32_t*)wl, W4);
    gemm_split_hmma_kernel<<<grid_g, blk, GEMM_SMEM>>>(ah, al, wh, wl, g_v_p, nullptr, nullptr, 0);

    dim3 grid_sc(36, 128);
    scores_hmma_kernel<<<grid_sc, blk, 4 * SBUF>>>(qh, ql, kh, kl, dist_p);

    dim3 grid_rs(1024, 128);
    rowstat_kernel<<<grid_rs, blk>>>(dist_p, rm_p, rl_p);

    dim3 grid_att(8, 128);
    att_fused_kernel<<<grid_att, blk>>>(dist_p, g_v_p, rm_p, rl_p, g_att_p);

    conv_split_kernel<<<(A4 + 255) / 256, blk>>>((const float4*)g_att_p, (uint32_t*)ah, (uint32_t*)al, A4);
    conv_split_kernel<<<(W4 + 255) / 256, blk>>>((const float4*)Wo, (uint32_t*)wh, (uint32_t*)wl, W4);
    gemm_split_hmma_kernel<<<grid_g, blk, GEMM_SMEM>>>(ah, al, wh, wl, out, nullptr, nullptr, 1);
}

// round 7
// speedup vs baseline: 2.2623x; 1.2023x over previous
#include <cuda_runtime.h>
#include <cuda_bf16.h>
#include <cuda_fp16.h>
#include <math.h>
#include <stdint.h>

// Problem constants
#define S_   1024
#define B_   8
#define H_   1024
#define NH_  16
#define DK_  64
#define BH_  128
#define SB_  8192
#define OUT_ELEMS  (S_*B_*H_)
#define DIST_ELEMS (BH_*S_*S_)
#define WW_  (H_*H_)

// ---------------- scratch ----------------
__device__ float g_v[SB_ * H_];
__device__ float g_att[SB_ * H_];
__device__ float g_dist_fallback[DIST_ELEMS];
__device__ float g_rowm[BH_ * S_];
__device__ float g_rowl[BH_ * S_];
__device__ __half g_w16h[4 * WW_];
__device__ __half g_w16l[4 * WW_];
__device__ __half g_x16[3 * SB_ * H_];
__device__ __nv_bfloat16 g_qh[SB_ * H_];
__device__ __nv_bfloat16 g_ql[SB_ * H_];
__device__ __nv_bfloat16 g_kh[SB_ * H_];
__device__ __nv_bfloat16 g_kl[SB_ * H_];

__device__ __forceinline__ uint32_t smem_u32(const void* p) {
    uint32_t a;
    asm("{ .reg .u64 t; cvta.to.shared.u64 t, %1; cvt.u32.u64 %0, t; }"
        : "=r"(a) : "l"(p));
    return a;
}
__device__ __forceinline__ void cp_async16(uint32_t dst, const void* src) {
    asm volatile("cp.async.ca.shared.global [%0], [%1], 16;" :: "r"(dst), "l"(src));
}
#define CP_COMMIT() asm volatile("cp.async.commit_group;" ::: "memory")
#define CP_WAIT(N)  asm volatile("cp.async.wait_group %0;" :: "n"(N) : "memory")

#define LDM_X4(r, addr)                                                        \
    asm volatile("ldmatrix.sync.aligned.m8n8.x4.shared.b16 {%0,%1,%2,%3}, [%4];" \
                 : "=r"((r)[0]), "=r"((r)[1]), "=r"((r)[2]), "=r"((r)[3]) : "r"(addr))
#define LDM_X4_T(r, addr)                                                      \
    asm volatile("ldmatrix.sync.aligned.m8n8.x4.trans.shared.b16 {%0,%1,%2,%3}, [%4];" \
                 : "=r"((r)[0]), "=r"((r)[1]), "=r"((r)[2]), "=r"((r)[3]) : "r"(addr))

#define MMA_BF16(acc, a, b0, b1)                                               \
    asm volatile("mma.sync.aligned.m16n8k16.row.col.f32.bf16.bf16.f32 "        \
                 "{%0,%1,%2,%3}, {%4,%5,%6,%7}, {%8,%9}, {%0,%1,%2,%3};"       \
                 : "+f"((acc)[0]), "+f"((acc)[1]), "+f"((acc)[2]), "+f"((acc)[3]) \
                 : "r"((a)[0]), "r"((a)[1]), "r"((a)[2]), "r"((a)[3]),         \
                   "r"(b0), "r"(b1))
#define MMA_F16(acc, a, b0, b1)                                                \
    asm volatile("mma.sync.aligned.m16n8k16.row.col.f32.f16.f16.f32 "          \
                 "{%0,%1,%2,%3}, {%4,%5,%6,%7}, {%8,%9}, {%0,%1,%2,%3};"       \
                 : "+f"((acc)[0]), "+f"((acc)[1]), "+f"((acc)[2]), "+f"((acc)[3]) \
                 : "r"((a)[0]), "r"((a)[1]), "r"((a)[2]), "r"((a)[3]),         \
                   "r"(b0), "r"(b1))

__device__ __forceinline__ void split2(float x, float y,
                                       uint32_t& hi, uint32_t& lo) {
    __nv_bfloat162 h = __floats2bfloat162_rn(x, y);
    float rx = x - __bfloat162float(h.x);
    float ry = y - __bfloat162float(h.y);
    __nv_bfloat162 l = __floats2bfloat162_rn(rx, ry);
    hi = *(uint32_t*)&h;
    lo = *(uint32_t*)&l;
}
__device__ __forceinline__ void split2h(float x, float y,
                                        uint32_t& hi, uint32_t& lo) {
    __half2 h = __floats2half2_rn(x, y);
    float rx = x - __half2float(__low2half(h));
    float ry = y - __half2float(__high2half(h));
    __half2 l = __floats2half2_rn(rx, ry);
    hi = *(uint32_t*)&h;
    lo = *(uint32_t*)&l;
}

// ============================================================================
// conv: 4 weights -> fp16 hi/lo
// ============================================================================
__global__ void __launch_bounds__(256) conv_w4_kernel(
    const float4* __restrict__ W0, const float4* __restrict__ W1,
    const float4* __restrict__ W2, const float4* __restrict__ W3,
    uint32_t* __restrict__ hi, uint32_t* __restrict__ lo)
{
    int i = blockIdx.x * 256 + threadIdx.x;      // 4 * 262144 total
    int mat = i >> 18, off = i & 262143;
    const float4* src = (mat == 0) ? W0 : (mat == 1) ? W1 : (mat == 2) ? W2 : W3;
    float4 v = src[off];
    uint32_t h0, l0, h1, l1;
    split2h(v.x, v.y, h0, l0);
    split2h(v.z, v.w, h1, l1);
    hi[2 * i] = h0; hi[2 * i + 1] = h1;
    lo[2 * i] = l0; lo[2 * i + 1] = l1;
}

// conv: 3 activations (q,k,v) -> fp16 (hi only)
__global__ void __launch_bounds__(256) conv_a3_kernel(
    const float4* __restrict__ X0, const float4* __restrict__ X1,
    const float4* __restrict__ X2, uint32_t* __restrict__ dst)
{
    int i = blockIdx.x * 256 + threadIdx.x;      // 3 * 2097152 total
    int mat = i >> 21, off = i & 2097151;
    const float4* src = (mat == 0) ? X0 : (mat == 1) ? X1 : X2;
    float4 v = src[off];
    __half2 h01 = __floats2half2_rn(v.x, v.y);
    __half2 h23 = __floats2half2_rn(v.z, v.w);
    dst[2 * i] = *(uint32_t*)&h01;
    dst[2 * i + 1] = *(uint32_t*)&h23;
}

__global__ void __launch_bounds__(256) conv_a1_kernel(
    const float4* __restrict__ X, uint32_t* __restrict__ dst)
{
    int i = blockIdx.x * 256 + threadIdx.x;      // 2097152 total
    float4 v = X[i];
    __half2 h01 = __floats2half2_rn(v.x, v.y);
    __half2 h23 = __floats2half2_rn(v.z, v.w);
    dst[2 * i] = *(uint32_t*)&h01;
    dst[2 * i + 1] = *(uint32_t*)&h23;
}

// ============================================================================
// fp16 2-term GEMM: C = A @ W^T,  A fp16, W = Wh + Wl fp16.
// D = A Wh + A Wl (fp32 accum).  Tile 128x128, BK=32, 3-stage cp.async ring.
// mode 0: fp32 out; mode 1: fp32 out + row perm; mode 2: bf16 hi/lo head-major.
// ============================================================================
#define ROWB 80
#define G2STAGE 30720            // A + Wh + Wl, 10240 each
#define G2_SMEM (3 * G2STAGE)    // 92160

__global__ void __launch_bounds__(256) gemm_fp16_kernel(
    const __half* __restrict__ A16, const __half* __restrict__ Wh,
    const __half* __restrict__ Wl, float* __restrict__ C,
    __nv_bfloat16* __restrict__ Oh, __nv_bfloat16* __restrict__ Ol, int mode)
{
    extern __shared__ char gsm[];
    const uint32_t s0 = smem_u32(gsm);

    const int tid  = threadIdx.x;
    const int wid  = tid >> 5;
    const int lane = tid & 31;
    const int m0 = blockIdx.y * 128;
    const int n0 = blockIdx.x * 128;
    const int warp_m = (wid & 3) * 32;
    const int warp_n = (wid >> 2) * 64;

    float acc[2][8][4];
#pragma unroll
    for (int a = 0; a < 2; ++a)
#pragma unroll
        for (int b = 0; b < 8; ++b)
#pragma unroll
            for (int c = 0; c < 4; ++c) acc[a][b][c] = 0.f;

#define LOAD2(st, kt) do {                                                     \
    int kk_ = (kt) * 32;                                                       \
    const __half* ga_ = A16 + (size_t)m0 * 1024 + kk_;                         \
    const __half* gh_ = Wh + (size_t)n0 * 1024 + kk_;                          \
    const __half* gl_ = Wl + (size_t)n0 * 1024 + kk_;                          \
    uint32_t base_ = s0 + (st) * G2STAGE;                                      \
    _Pragma("unroll")                                                          \
    for (int l_ = 0; l_ < 2; ++l_) {                                           \
        int id_ = tid + 256 * l_;                                              \
        int row_ = id_ >> 2, c_ = id_ & 3;                                     \
        cp_async16(base_ + row_ * ROWB + c_ * 16,                              \
                   ga_ + (size_t)row_ * 1024 + c_ * 8);                        \
        cp_async16(base_ + 10240u + row_ * ROWB + c_ * 16,                     \
                   gh_ + (size_t)row_ * 1024 + c_ * 8);                        \
        cp_async16(base_ + 20480u + row_ * ROWB + c_ * 16,                     \
                   gl_ + (size_t)row_ * 1024 + c_ * 8);                        \
    }                                                                          \
    CP_COMMIT();                                                               \
} while (0)

    LOAD2(0, 0);
    LOAD2(1, 1);

    const uint32_t a_lane_row = warp_m + (lane & 15);
    const uint32_t a_lane_col = (lane >> 4) * 16;
    const uint32_t b_lane_row = warp_n + (lane & 7) + ((lane >> 4) << 3);
    const uint32_t b_lane_col = ((lane >> 3) & 1) * 16;

    for (int kt = 0; kt < 32; ++kt) {
        const int st = kt - (kt / 3) * 3;
        if (kt < 30) CP_WAIT(1); else CP_WAIT(0);
        __syncthreads();
        if (kt + 2 < 32) {
            int st2 = (kt + 2) - ((kt + 2) / 3) * 3;
            LOAD2(st2, kt + 2);
        }

        const uint32_t abase = s0 + st * G2STAGE;
        const uint32_t hbase = abase + 10240u;
        const uint32_t lbase = abase + 20480u;

#pragma unroll
        for (int k16 = 0; k16 < 2; ++k16) {
            uint32_t af[2][4];
#pragma unroll
            for (int fm = 0; fm < 2; ++fm)
                LDM_X4(af[fm], abase + (a_lane_row + fm * 16) * ROWB
                               + k16 * 32 + a_lane_col);
            uint32_t bh[8][2], bl[8][2];
#pragma unroll
            for (int fp = 0; fp < 4; ++fp) {
                uint32_t r[4];
                LDM_X4(r, hbase + (b_lane_row + fp * 16) * ROWB
                          + k16 * 32 + b_lane_col);
                bh[fp * 2][0] = r[0]; bh[fp * 2][1] = r[1];
                bh[fp * 2 + 1][0] = r[2]; bh[fp * 2 + 1][1] = r[3];
                LDM_X4(r, lbase + (b_lane_row + fp * 16) * ROWB
                          + k16 * 32 + b_lane_col);
                bl[fp * 2][0] = r[0]; bl[fp * 2][1] = r[1];
                bl[fp * 2 + 1][0] = r[2]; bl[fp * 2 + 1][1] = r[3];
            }
#pragma unroll
            for (int fm = 0; fm < 2; ++fm)
#pragma unroll
                for (int fn = 0; fn < 8; ++fn) {
                    MMA_F16(acc[fm][fn], af[fm], bh[fn][0], bh[fn][1]);
                    MMA_F16(acc[fm][fn], af[fm], bl[fn][0], bl[fn][1]);
                }
        }
    }

#pragma unroll
    for (int fm = 0; fm < 2; ++fm) {
#pragma unroll
        for (int half = 0; half < 2; ++half) {
            int m = m0 + warp_m + fm * 16 + (lane >> 2) + half * 8;
            if (mode == 2) {
                int s = m >> 3, b = m & 7;
#pragma unroll
                for (int fn = 0; fn < 8; ++fn) {
                    int col = n0 + warp_n + (lane & 3) * 2 + fn * 8;
                    int h = col >> 6, d = col & 63;
                    size_t addr = ((size_t)(h * 8 + b) * 1024 + s) * 64 + d;
                    uint32_t hi, lo;
                    split2(acc[fm][fn][half * 2], acc[fm][fn][half * 2 + 1], hi, lo);
                    *(uint32_t*)(Oh + addr) = hi;
                    *(uint32_t*)(Ol + addr) = lo;
                }
            } else {
                int orow = mode ? ((m & (S_ - 1)) * B_ + (m >> 10)) : m;
                float* cr = C + (size_t)orow * 1024 + n0 + warp_n + (lane & 3) * 2;
#pragma unroll
                for (int fn = 0; fn < 8; ++fn) {
                    float2 v = half ? make_float2(acc[fm][fn][2], acc[fm][fn][3])
                                    : make_float2(acc[fm][fn][0], acc[fm][fn][1]);
                    *(float2*)(cr + fn * 8) = v;
                }
            }
        }
    }
#undef LOAD2
}

// ============================================================================
// scores HMMA (3-term bf16, unchanged): raw lower-tri 128x128 tiles into dist.
// ============================================================================
#define SROWB 144
#define SBUF  18432

__global__ void __launch_bounds__(256) scores_hmma_kernel(
    const __nv_bfloat16* __restrict__ Qh, const __nv_bfloat16* __restrict__ Ql,
    const __nv_bfloat16* __restrict__ Kh, const __nv_bfloat16* __restrict__ Kl,
    float* __restrict__ dist)
{
    extern __shared__ char sm[];
    const uint32_t s0 = smem_u32(sm);
    const int pid = blockIdx.x;
    const int bb  = blockIdx.y;
    int tit = 0;
    while ((tit + 1) * (tit + 2) / 2 <= pid) ++tit;
    const int tjt = pid - tit * (tit + 1) / 2;

    const int tid  = threadIdx.x;
    const int wid  = tid >> 5;
    const int lane = tid & 31;
    const int warp_m = (wid & 3) * 32;
    const int warp_n = (wid >> 2) * 64;

    const size_t hb = (size_t)bb * 65536;
    const __nv_bfloat16* srcs[4] = {Kh + hb, Kl + hb, Qh + hb, Ql + hb};
    const int rbase[4] = {tit * 128, tit * 128, tjt * 128, tjt * 128};

#pragma unroll
    for (int bfi = 0; bfi < 4; ++bfi) {
#pragma unroll
        for (int l = 0; l < 4; ++l) {
            int id = tid + 256 * l;
            int row = id >> 3, c = id & 7;
            cp_async16(s0 + bfi * SBUF + row * SROWB + c * 16,
                       srcs[bfi] + (size_t)(rbase[bfi] + row) * 64 + c * 8);
        }
    }
    CP_COMMIT();
    CP_WAIT(0);
    __syncthreads();

    const uint32_t a_lane_row = warp_m + (lane & 15);
    const uint32_t a_lane_col = (lane >> 4) * 16;
    const uint32_t b_lane_row = warp_n + (lane & 7) + ((lane >> 4) << 3);
    const uint32_t b_lane_col = ((lane >> 3) & 1) * 16;

    float acc[2][8][4];
#pragma unroll
    for (int a = 0; a < 2; ++a)
#pragma unroll
        for (int b = 0; b < 8; ++b)
#pragma unroll
            for (int c = 0; c < 4; ++c) acc[a][b][c] = 0.f;

    const int at[3] = {0, 0, 1};
    const int bt[3] = {2, 3, 2};

#pragma unroll
    for (int t = 0; t < 3; ++t) {
        const uint32_t abase = s0 + at[t] * SBUF;
        const uint32_t bbase = s0 + bt[t] * SBUF;
#pragma unroll
        for (int k16 = 0; k16 < 4; ++k16) {
            uint32_t af[2][4];
#pragma unroll
            for (int fm = 0; fm < 2; ++fm)
                LDM_X4(af[fm], abase + (a_lane_row + fm * 16) * SROWB
                               + k16 * 32 + a_lane_col);
            uint32_t bfr[8][2];
#pragma unroll
            for (int fp = 0; fp < 4; ++fp) {
                uint32_t r[4];
                LDM_X4(r, bbase + (b_lane_row + fp * 16) * SROWB
                          + k16 * 32 + b_lane_col);
                bfr[fp * 2][0] = r[0]; bfr[fp * 2][1] = r[1];
                bfr[fp * 2 + 1][0] = r[2]; bfr[fp * 2 + 1][1] = r[3];
            }
#pragma unroll
            for (int fm = 0; fm < 2; ++fm)
#pragma unroll
                for (int fn = 0; fn < 8; ++fn)
                    MMA_BF16(acc[fm][fn], af[fm], bfr[fn][0], bfr[fn][1]);
        }
    }

    float* out = dist + ((size_t)bb << 20);
#pragma unroll
    for (int fm = 0; fm < 2; ++fm)
#pragma unroll
        for (int half = 0; half < 2; ++half) {
            int i = tit * 128 + warp_m + fm * 16 + (lane >> 2) + half * 8;
            float* orow = out + (size_t)i * 1024 + tjt * 128 + warp_n + (lane & 3) * 2;
#pragma unroll
            for (int fn = 0; fn < 8; ++fn) {
                float2 v = half
                    ? make_float2(acc[fm][fn][2] * 0.125f, acc[fm][fn][3] * 0.125f)
                    : make_float2(acc[fm][fn][0] * 0.125f, acc[fm][fn][1] * 0.125f);
                *(float2*)(orow + fn * 8) = v;
            }
        }
}

// ============================================================================
// rowstat: per (bb, i) compute m = max_j<=i s, invl = 1/sum __expf(s - m).
// ============================================================================
__global__ void __launch_bounds__(256) rowstat_kernel(
    const float* __restrict__ dist, float* __restrict__ rowm,
    float* __restrict__ rowl)
{
    const int i  = blockIdx.x;
    const int bb = blockIdx.y;
    const float* row = dist + ((size_t)bb << 20) + (size_t)i * S_;
    const int len = i + 1;

    __shared__ float sh[S_];
    __shared__ float red[8];
    const int tid = threadIdx.x;

    float m = -3.4e38f;
    for (int j = tid; j < len; j += 256) {
        float v = row[j];
        sh[j] = v;
        m = fmaxf(m, v);
    }
#pragma unroll
    for (int o = 16; o; o >>= 1) m = fmaxf(m, __shfl_xor_sync(0xffffffffu, m, o));
    if ((tid & 31) == 0) red[tid >> 5] = m;
    __syncthreads();
    if (tid < 8) {
        m = red[tid];
#pragma unroll
        for (int o = 4; o; o >>= 1) m = fmaxf(m, __shfl_xor_sync(0xffu, m, o));
        if (tid == 0) red[0] = m;
    }
    __syncthreads();
    m = red[0];
    __syncthreads();

    float s = 0.f;
    for (int j = tid; j < len; j += 256)
        s += __expf(sh[j] - m);
#pragma unroll
    for (int o = 16; o; o >>= 1) s += __shfl_xor_sync(0xffffffffu, s, o);
    if ((tid & 31) == 0) red[tid >> 5] = s;
    __syncthreads();
    if (tid < 8) {
        s = red[tid];
#pragma unroll
        for (int o = 4; o; o >>= 1) s += __shfl_xor_sync(0xffu, s, o);
        if (tid == 0) {
            rowm[(bb << 10) + i] = m;
            rowl[(bb << 10) + i] = 1.f / s;
        }
    }
}

// ============================================================================
// att fused (fp16 2-term): p = exp(s-m)*invl written to dist (+zero upper),
// P fp16, V fp16 hi/lo; acc += P^T Vh + P^T Vl.
// ============================================================================
__global__ void __launch_bounds__(256) att_fused_kernel(
    float* __restrict__ dist, const float* __restrict__ Vp,
    const float* __restrict__ rowm, const float* __restrict__ rowl,
    float* __restrict__ att)
{
    __shared__ __half Ps[32][136];        // [i][j], 272B rows
    __shared__ __half Vs[2][32][72];      // [hi/lo][i][d], 144B rows

    const int jt = blockIdx.x;
    const int bb = blockIdx.y;
    const int h = bb >> 3;
    const int b = bb & 7;
    const int j0 = jt * 128;

    const int tid  = threadIdx.x;
    const int wid  = tid >> 5;
    const int lane = tid & 31;
    const int warp_m = (wid & 3) * 32;   // j
    const int warp_n = (wid >> 2) * 32;  // d

    float* dbase = dist + ((size_t)bb << 20);
    const float* vbase = Vp + (size_t)b * 1024 + (size_t)h * 64;
    const float* mrow = rowm + (bb << 10);
    const float* lrow = rowl + (bb << 10);

    const float4 z4 = make_float4(0.f, 0.f, 0.f, 0.f);
    for (int it = 0; it < jt; ++it) {
#pragma unroll
        for (int q = 0; q < 16; ++q) {
            int id = tid + 256 * q;
            int r = id >> 5, c4 = id & 31;
            *(float4*)(dbase + (size_t)(it * 128 + r) * 1024 + j0 + c4 * 4) = z4;
        }
    }

    const uint32_t PB = smem_u32(&Ps[0][0]);
    const uint32_t VhB = smem_u32(&Vs[0][0][0]);
    const uint32_t VlB = smem_u32(&Vs[1][0][0]);

    float acc[2][4][4];
#pragma unroll
    for (int a = 0; a < 2; ++a)
#pragma unroll
        for (int c = 0; c < 4; ++c)
#pragma unroll
            for (int e = 0; e < 4; ++e) acc[a][c][e] = 0.f;

    const int nsteps = (1024 - j0) / 32;

    for (int step = 0; step < nsteps; ++step) {
        const int i0 = j0 + step * 32;

#pragma unroll
        for (int q = 0; q < 4; ++q) {
            int id = tid + 256 * q;
            int r = id >> 5, c4 = id & 31;
            const int iv = i0 + r;
            float4 s = *(const float4*)(dbase + (size_t)iv * 1024 + j0 + c4 * 4);
            float m  = __ldg(mrow + iv);
            float il = __ldg(lrow + iv);
            int jv = j0 + c4 * 4;
            float p0 = (jv + 0 <= iv) ? __expf(s.x - m) * il : 0.f;
            float p1 = (jv + 1 <= iv) ? __expf(s.y - m) * il : 0.f;
            float p2 = (jv + 2 <= iv) ? __expf(s.z - m) * il : 0.f;
            float p3 = (jv + 3 <= iv) ? __expf(s.w - m) * il : 0.f;
            *(float4*)(dbase + (size_t)iv * 1024 + j0 + c4 * 4)
                = make_float4(p0, p1, p2, p3);
            __half2 h01 = __floats2half2_rn(p0, p1);
            __half2 h23 = __floats2half2_rn(p2, p3);
            *(uint2*)(&Ps[r][c4 * 4]) = make_uint2(*(uint32_t*)&h01, *(uint32_t*)&h23);
        }
#pragma unroll
        for (int q = 0; q < 2; ++q) {
            int id = tid + 256 * q;
            int r = id >> 4, c4 = id & 15;
            float4 v = *(const float4*)(vbase + (size_t)(i0 + r) * 8192 + c4 * 4);
            uint32_t h0, l0, h1, l1;
            split2h(v.x, v.y, h0, l0);
            split2h(v.z, v.w, h1, l1);
            *(uint2*)(&Vs[0][r][c4 * 4]) = make_uint2(h0, h1);
            *(uint2*)(&Vs[1][r][c4 * 4]) = make_uint2(l0, l1);
        }
        __syncthreads();

#pragma unroll
        for (int k16 = 0; k16 < 2; ++k16) {
            const uint32_t arow = k16 * 16 + ((lane >> 4) << 3) + (lane & 7);
            uint32_t af[2][4];
#pragma unroll
            for (int fm = 0; fm < 2; ++fm) {
                const uint32_t acolb =
                    (warp_m + fm * 16 + (((lane >> 3) & 1) << 3)) * 2;
                LDM_X4_T(af[fm], PB + arow * 272 + acolb);
            }
            const uint32_t brow = k16 * 16 + (((lane >> 3) & 1) << 3) + (lane & 7);
            uint32_t bH[4][2], bL[4][2];
#pragma unroll
            for (int fp = 0; fp < 2; ++fp) {
                const uint32_t bcolb =
                    (warp_n + fp * 16 + ((lane >> 4) << 3)) * 2;
                uint32_t r[4];
                LDM_X4_T(r, VhB + brow * 144 + bcolb);
                bH[fp * 2][0] = r[0]; bH[fp * 2][1] = r[1];
                bH[fp * 2 + 1][0] = r[2]; bH[fp * 2 + 1][1] = r[3];
                LDM_X4_T(r, VlB + brow * 144 + bcolb);
                bL[fp * 2][0] = r[0]; bL[fp * 2][1] = r[1];
                bL[fp * 2 + 1][0] = r[2]; bL[fp * 2 + 1][1] = r[3];
            }
#pragma unroll
            for (int fm = 0; fm < 2; ++fm)
#pragma unroll
                for (int fn = 0; fn < 4; ++fn) {
                    MMA_F16(acc[fm][fn], af[fm], bH[fn][0], bH[fn][1]);
                    MMA_F16(acc[fm][fn], af[fm], bL[fn][0], bL[fn][1]);
                }
        }
        __syncthreads();
    }

#pragma unroll
    for (int fm = 0; fm < 2; ++fm)
#pragma unroll
        for (int half = 0; half < 2; ++half) {
            int j = j0 + warp_m + fm * 16 + (lane >> 2) + half * 8;
            float* cr = att + ((size_t)b * 1024 + j) * 1024 + h * 64
                        + warp_n + (lane & 3) * 2;
#pragma unroll
            for (int fn = 0; fn < 4; ++fn) {
                float2 v = half ? make_float2(acc[fm][fn][2], acc[fm][fn][3])
                                : make_float2(acc[fm][fn][0], acc[fm][fn][1]);
                *(float2*)(cr + fn * 8) = v;
            }
        }
}

// ---------------------------------------------------------------------------
extern "C" void kernel_launch(void* const* d_in, const int* in_sizes, int n_in,
                              void* d_out, int out_size)
{
    const float* value = (const float*)d_in[0];
    const float* key   = (const float*)d_in[1];
    const float* query = (const float*)d_in[2];
    const float* Wq    = (const float*)d_in[3];
    const float* Wk    = (const float*)d_in[4];
    const float* Wv    = (const float*)d_in[5];
    const float* Wo    = (const float*)d_in[6];
    float* out = (float*)d_out;

    float* g_v_p;   cudaGetSymbolAddress((void**)&g_v_p,   g_v);
    float* g_att_p; cudaGetSymbolAddress((void**)&g_att_p, g_att);
    float* rm_p;    cudaGetSymbolAddress((void**)&rm_p,    g_rowm);
    float* rl_p;    cudaGetSymbolAddress((void**)&rl_p,    g_rowl);
    __half *w16h, *w16l, *x16;
    cudaGetSymbolAddress((void**)&w16h, g_w16h);
    cudaGetSymbolAddress((void**)&w16l, g_w16l);
    cudaGetSymbolAddress((void**)&x16,  g_x16);
    __nv_bfloat16 *qh, *ql, *kh, *kl;
    cudaGetSymbolAddress((void**)&qh, g_qh);
    cudaGetSymbolAddress((void**)&ql, g_ql);
    cudaGetSymbolAddress((void**)&kh, g_kh);
    cudaGetSymbolAddress((void**)&kl, g_kl);

    float* dist_p;
    if ((long long)out_size == (long long)OUT_ELEMS + (long long)DIST_ELEMS) {
        dist_p = out + OUT_ELEMS;
    } else {
        cudaGetSymbolAddress((void**)&dist_p, g_dist_fallback);
    }

    static int attr_done = 0;
    if (!attr_done) {
        cudaFuncSetAttribute(gemm_fp16_kernel,
                             cudaFuncAttributeMaxDynamicSharedMemorySize, G2_SMEM);
        cudaFuncSetAttribute(scores_hmma_kernel,
                             cudaFuncAttributeMaxDynamicSharedMemorySize, 4 * SBUF);
        attr_done = 1;
    }

    dim3 blk(256);
    dim3 grid_g(8, 64);
    const size_t ASEG = (size_t)SB_ * H_;   // halves per activation

    // weight conversions (order: Wq, Wk, Wv, Wo)
    conv_w4_kernel<<<4096, blk>>>((const float4*)Wq, (const float4*)Wk,
                                  (const float4*)Wv, (const float4*)Wo,
                                  (uint32_t*)w16h, (uint32_t*)w16l);
    // activation conversions (order: query, key, value)
    conv_a3_kernel<<<24576, blk>>>((const float4*)query, (const float4*)key,
                                   (const float4*)value, (uint32_t*)x16);

    gemm_fp16_kernel<<<grid_g, blk, G2_SMEM>>>(x16,            w16h,           w16l,           nullptr, qh, ql, 2);
    gemm_fp16_kernel<<<grid_g, blk, G2_SMEM>>>(x16 + ASEG,     w16h + WW_,     w16l + WW_,     nullptr, kh, kl, 2);
    gemm_fp16_kernel<<<grid_g, blk, G2_SMEM>>>(x16 + 2 * ASEG, w16h + 2 * WW_, w16l + 2 * WW_, g_v_p, nullptr, nullptr, 0);

    dim3 grid_sc(36, 128);
    scores_hmma_kernel<<<grid_sc, blk, 4 * SBUF>>>(qh, ql, kh, kl, dist_p);

    dim3 grid_rs(1024, 128);
    rowstat_kernel<<<grid_rs, blk>>>(dist_p, rm_p, rl_p);

    dim3 grid_att(8, 128);
    att_fused_kernel<<<grid_att, blk>>>(dist_p, g_v_p, rm_p, rl_p, g_att_p);

    conv_a1_kernel<<<8192, blk>>>((const float4*)g_att_p, (uint32_t*)x16);
    gemm_fp16_kernel<<<grid_g, blk, G2_SMEM>>>(x16, w16h + 3 * WW_, w16l + 3 * WW_, out, nullptr, nullptr, 1);
}

// round 10
// speedup vs baseline: 2.2743x; 1.0053x over previous
#include <cuda_runtime.h>
#include <cuda_bf16.h>
#include <cuda_fp16.h>
#include <math.h>
#include <stdint.h>

// Problem constants
#define S_   1024
#define B_   8
#define H_   1024
#define NH_  16
#define DK_  64
#define BH_  128
#define SB_  8192
#define OUT_ELEMS  (S_*B_*H_)
#define DIST_ELEMS (BH_*S_*S_)
#define WW_  (H_*H_)

// ---------------- scratch ----------------
__device__ float g_v[SB_ * H_];
__device__ float g_att[SB_ * H_];
__device__ float g_dist_fallback[DIST_ELEMS];
__device__ float g_rowm[BH_ * S_];
__device__ float g_rowl[BH_ * S_];
__device__ __half g_w16h[4 * WW_];
__device__ __half g_w16l[4 * WW_];
__device__ __half g_x16[3 * SB_ * H_];
__device__ __nv_bfloat16 g_qh[SB_ * H_];
__device__ __nv_bfloat16 g_ql[SB_ * H_];
__device__ __nv_bfloat16 g_kh[SB_ * H_];
__device__ __nv_bfloat16 g_kl[SB_ * H_];

__device__ __forceinline__ uint32_t smem_u32(const void* p) {
    uint32_t a;
    asm("{ .reg .u64 t; cvta.to.shared.u64 t, %1; cvt.u32.u64 %0, t; }"
        : "=r"(a) : "l"(p));
    return a;
}
__device__ __forceinline__ void cp_async16(uint32_t dst, const void* src) {
    asm volatile("cp.async.ca.shared.global [%0], [%1], 16;" :: "r"(dst), "l"(src));
}
#define CP_COMMIT() asm volatile("cp.async.commit_group;" ::: "memory")
#define CP_WAIT(N)  asm volatile("cp.async.wait_group %0;" :: "n"(N) : "memory")

#define LDM_X4(r, addr)                                                        \
    asm volatile("ldmatrix.sync.aligned.m8n8.x4.shared.b16 {%0,%1,%2,%3}, [%4];" \
                 : "=r"((r)[0]), "=r"((r)[1]), "=r"((r)[2]), "=r"((r)[3]) : "r"(addr))
#define LDM_X4_T(r, addr)                                                      \
    asm volatile("ldmatrix.sync.aligned.m8n8.x4.trans.shared.b16 {%0,%1,%2,%3}, [%4];" \
                 : "=r"((r)[0]), "=r"((r)[1]), "=r"((r)[2]), "=r"((r)[3]) : "r"(addr))

#define MMA_BF16(acc, a, b0, b1)                                               \
    asm volatile("mma.sync.aligned.m16n8k16.row.col.f32.bf16.bf16.f32 "        \
                 "{%0,%1,%2,%3}, {%4,%5,%6,%7}, {%8,%9}, {%0,%1,%2,%3};"       \
                 : "+f"((acc)[0]), "+f"((acc)[1]), "+f"((acc)[2]), "+f"((acc)[3]) \
                 : "r"((a)[0]), "r"((a)[1]), "r"((a)[2]), "r"((a)[3]),         \
                   "r"(b0), "r"(b1))
#define MMA_F16(acc, a, b0, b1)                                                \
    asm volatile("mma.sync.aligned.m16n8k16.row.col.f32.f16.f16.f32 "          \
                 "{%0,%1,%2,%3}, {%4,%5,%6,%7}, {%8,%9}, {%0,%1,%2,%3};"       \
                 : "+f"((acc)[0]), "+f"((acc)[1]), "+f"((acc)[2]), "+f"((acc)[3]) \
                 : "r"((a)[0]), "r"((a)[1]), "r"((a)[2]), "r"((a)[3]),         \
                   "r"(b0), "r"(b1))

__device__ __forceinline__ void split2(float x, float y,
                                       uint32_t& hi, uint32_t& lo) {
    __nv_bfloat162 h = __floats2bfloat162_rn(x, y);
    float rx = x - __bfloat162float(h.x);
    float ry = y - __bfloat162float(h.y);
    __nv_bfloat162 l = __floats2bfloat162_rn(rx, ry);
    hi = *(uint32_t*)&h;
    lo = *(uint32_t*)&l;
}
__device__ __forceinline__ void split2h(float x, float y,
                                        uint32_t& hi, uint32_t& lo) {
    __half2 h = __floats2half2_rn(x, y);
    float rx = x - __half2float(__low2half(h));
    float ry = y - __half2float(__high2half(h));
    __half2 l = __floats2half2_rn(rx, ry);
    hi = *(uint32_t*)&h;
    lo = *(uint32_t*)&l;
}

// ============================================================================
// conv kernels
// ============================================================================
__global__ void __launch_bounds__(256) conv_w4_kernel(
    const float4* __restrict__ W0, const float4* __restrict__ W1,
    const float4* __restrict__ W2, const float4* __restrict__ W3,
    uint32_t* __restrict__ hi, uint32_t* __restrict__ lo)
{
    int i = blockIdx.x * 256 + threadIdx.x;
    int mat = i >> 18, off = i & 262143;
    const float4* src = (mat == 0) ? W0 : (mat == 1) ? W1 : (mat == 2) ? W2 : W3;
    float4 v = src[off];
    uint32_t h0, l0, h1, l1;
    split2h(v.x, v.y, h0, l0);
    split2h(v.z, v.w, h1, l1);
    hi[2 * i] = h0; hi[2 * i + 1] = h1;
    lo[2 * i] = l0; lo[2 * i + 1] = l1;
}

__global__ void __launch_bounds__(256) conv_a3_kernel(
    const float4* __restrict__ X0, const float4* __restrict__ X1,
    const float4* __restrict__ X2, uint32_t* __restrict__ dst)
{
    int i = blockIdx.x * 256 + threadIdx.x;
    int mat = i >> 21, off = i & 2097151;
    const float4* src = (mat == 0) ? X0 : (mat == 1) ? X1 : X2;
    float4 v = src[off];
    __half2 h01 = __floats2half2_rn(v.x, v.y);
    __half2 h23 = __floats2half2_rn(v.z, v.w);
    dst[2 * i] = *(uint32_t*)&h01;
    dst[2 * i + 1] = *(uint32_t*)&h23;
}

__global__ void __launch_bounds__(256) conv_a1_kernel(
    const float4* __restrict__ X, uint32_t* __restrict__ dst)
{
    int i = blockIdx.x * 256 + threadIdx.x;
    float4 v = X[i];
    __half2 h01 = __floats2half2_rn(v.x, v.y);
    __half2 h23 = __floats2half2_rn(v.z, v.w);
    dst[2 * i] = *(uint32_t*)&h01;
    dst[2 * i + 1] = *(uint32_t*)&h23;
}

// ============================================================================
// fp16 2-term GEMM (occupancy 2): C = A @ W^T,  A fp16, W = Wh + Wl fp16.
// Inner loop streams B-hi then B-lo through the SAME fragment registers
// to keep regs <= 128 so two CTAs co-reside per SM.
// ============================================================================
#define ROWB 80
#define G2STAGE 30720
#define G2_SMEM (3 * G2STAGE)

__global__ void __launch_bounds__(256, 2) gemm_fp16_kernel(
    const __half* __restrict__ A16, const __half* __restrict__ Wh,
    const __half* __restrict__ Wl, float* __restrict__ C,
    __nv_bfloat16* __restrict__ Oh, __nv_bfloat16* __restrict__ Ol, int mode)
{
    extern __shared__ char gsm[];
    const uint32_t s0 = smem_u32(gsm);

    const int tid  = threadIdx.x;
    const int wid  = tid >> 5;
    const int lane = tid & 31;
    const int m0 = blockIdx.y * 128;
    const int n0 = blockIdx.x * 128;
    const int warp_m = (wid & 3) * 32;
    const int warp_n = (wid >> 2) * 64;

    float acc[2][8][4];
#pragma unroll
    for (int a = 0; a < 2; ++a)
#pragma unroll
        for (int b = 0; b < 8; ++b)
#pragma unroll
            for (int c = 0; c < 4; ++c) acc[a][b][c] = 0.f;

#define LOAD2(st, kt) do {                                                     \
    int kk_ = (kt) * 32;                                                       \
    const __half* ga_ = A16 + (size_t)m0 * 1024 + kk_;                         \
    const __half* gh_ = Wh + (size_t)n0 * 1024 + kk_;                          \
    const __half* gl_ = Wl + (size_t)n0 * 1024 + kk_;                          \
    uint32_t base_ = s0 + (st) * G2STAGE;                                      \
    _Pragma("unroll")                                                          \
    for (int l_ = 0; l_ < 2; ++l_) {                                           \
        int id_ = tid + 256 * l_;                                              \
        int row_ = id_ >> 2, c_ = id_ & 3;                                     \
        cp_async16(base_ + row_ * ROWB + c_ * 16,                              \
                   ga_ + (size_t)row_ * 1024 + c_ * 8);                        \
        cp_async16(base_ + 10240u + row_ * ROWB + c_ * 16,                     \
                   gh_ + (size_t)row_ * 1024 + c_ * 8);                        \
        cp_async16(base_ + 20480u + row_ * ROWB + c_ * 16,                     \
                   gl_ + (size_t)row_ * 1024 + c_ * 8);                        \
    }                                                                          \
    CP_COMMIT();                                                               \
} while (0)

    LOAD2(0, 0);
    LOAD2(1, 1);

    const uint32_t a_lane_row = warp_m + (lane & 15);
    const uint32_t a_lane_col = (lane >> 4) * 16;
    const uint32_t b_lane_row = warp_n + (lane & 7) + ((lane >> 4) << 3);
    const uint32_t b_lane_col = ((lane >> 3) & 1) * 16;

    for (int kt = 0; kt < 32; ++kt) {
        const int st = kt - (kt / 3) * 3;
        if (kt < 30) CP_WAIT(1); else CP_WAIT(0);
        __syncthreads();
        if (kt + 2 < 32) {
            int st2 = (kt + 2) - ((kt + 2) / 3) * 3;
            LOAD2(st2, kt + 2);
        }

        const uint32_t abase = s0 + st * G2STAGE;

#pragma unroll
        for (int k16 = 0; k16 < 2; ++k16) {
            uint32_t af[2][4];
#pragma unroll
            for (int fm = 0; fm < 2; ++fm)
                LDM_X4(af[fm], abase + (a_lane_row + fm * 16) * ROWB
                               + k16 * 32 + a_lane_col);
            uint32_t bf[8][2];
            // ---- hi pass ----
#pragma unroll
            for (int fp = 0; fp < 4; ++fp) {
                uint32_t r[4];
                LDM_X4(r, abase + 10240u + (b_lane_row + fp * 16) * ROWB
                          + k16 * 32 + b_lane_col);
                bf[fp * 2][0] = r[0]; bf[fp * 2][1] = r[1];
                bf[fp * 2 + 1][0] = r[2]; bf[fp * 2 + 1][1] = r[3];
            }
#pragma unroll
            for (int fm = 0; fm < 2; ++fm)
#pragma unroll
                for (int fn = 0; fn < 8; ++fn)
                    MMA_F16(acc[fm][fn], af[fm], bf[fn][0], bf[fn][1]);
            // ---- lo pass (reuse bf regs) ----
#pragma unroll
            for (int fp = 0; fp < 4; ++fp) {
                uint32_t r[4];
                LDM_X4(r, abase + 20480u + (b_lane_row + fp * 16) * ROWB
                          + k16 * 32 + b_lane_col);
                bf[fp * 2][0] = r[0]; bf[fp * 2][1] = r[1];
                bf[fp * 2 + 1][0] = r[2]; bf[fp * 2 + 1][1] = r[3];
            }
#pragma unroll
            for (int fm = 0; fm < 2; ++fm)
#pragma unroll
                for (int fn = 0; fn < 8; ++fn)
                    MMA_F16(acc[fm][fn], af[fm], bf[fn][0], bf[fn][1]);
        }
    }

#pragma unroll
    for (int fm = 0; fm < 2; ++fm) {
#pragma unroll
        for (int half = 0; half < 2; ++half) {
            int m = m0 + warp_m + fm * 16 + (lane >> 2) + half * 8;
            if (mode == 2) {
                int s = m >> 3, b = m & 7;
#pragma unroll
                for (int fn = 0; fn < 8; ++fn) {
                    int col = n0 + warp_n + (lane & 3) * 2 + fn * 8;
                    int h = col >> 6, d = col & 63;
                    size_t addr = ((size_t)(h * 8 + b) * 1024 + s) * 64 + d;
                    uint32_t hi, lo;
                    split2(acc[fm][fn][half * 2], acc[fm][fn][half * 2 + 1], hi, lo);
                    *(uint32_t*)(Oh + addr) = hi;
                    *(uint32_t*)(Ol + addr) = lo;
                }
            } else {
                int orow = mode ? ((m & (S_ - 1)) * B_ + (m >> 10)) : m;
                float* cr = C + (size_t)orow * 1024 + n0 + warp_n + (lane & 3) * 2;
#pragma unroll
                for (int fn = 0; fn < 8; ++fn) {
                    float2 v = half ? make_float2(acc[fm][fn][2], acc[fm][fn][3])
                                    : make_float2(acc[fm][fn][0], acc[fm][fn][1]);
                    *(float2*)(cr + fn * 8) = v;
                }
            }
        }
    }
#undef LOAD2
}

// ============================================================================
// scores HMMA (3-term bf16): raw lower-tri 128x128 tiles into dist.
// ============================================================================
#define SROWB 144
#define SBUF  18432

__global__ void __launch_bounds__(256, 2) scores_hmma_kernel(
    const __nv_bfloat16* __restrict__ Qh, const __nv_bfloat16* __restrict__ Ql,
    const __nv_bfloat16* __restrict__ Kh, const __nv_bfloat16* __restrict__ Kl,
    float* __restrict__ dist)
{
    extern __shared__ char sm[];
    const uint32_t s0 = smem_u32(sm);
    const int pid = blockIdx.x;
    const int bb  = blockIdx.y;
    int tit = 0;
    while ((tit + 1) * (tit + 2) / 2 <= pid) ++tit;
    const int tjt = pid - tit * (tit + 1) / 2;

    const int tid  = threadIdx.x;
    const int wid  = tid >> 5;
    const int lane = tid & 31;
    const int warp_m = (wid & 3) * 32;
    const int warp_n = (wid >> 2) * 64;

    const size_t hb = (size_t)bb * 65536;
    const __nv_bfloat16* srcs[4] = {Kh + hb, Kl + hb, Qh + hb, Ql + hb};
    const int rbase[4] = {tit * 128, tit * 128, tjt * 128, tjt * 128};

#pragma unroll
    for (int bfi = 0; bfi < 4; ++bfi) {
#pragma unroll
        for (int l = 0; l < 4; ++l) {
            int id = tid + 256 * l;
            int row = id >> 3, c = id & 7;
            cp_async16(s0 + bfi * SBUF + row * SROWB + c * 16,
                       srcs[bfi] + (size_t)(rbase[bfi] + row) * 64 + c * 8);
        }
    }
    CP_COMMIT();
    CP_WAIT(0);
    __syncthreads();

    const uint32_t a_lane_row = warp_m + (lane & 15);
    const uint32_t a_lane_col = (lane >> 4) * 16;
    const uint32_t b_lane_row = warp_n + (lane & 7) + ((lane >> 4) << 3);
    const uint32_t b_lane_col = ((lane >> 3) & 1) * 16;

    float acc[2][8][4];
#pragma unroll
    for (int a = 0; a < 2; ++a)
#pragma unroll
        for (int b = 0; b < 8; ++b)
#pragma unroll
            for (int c = 0; c < 4; ++c) acc[a][b][c] = 0.f;

    const int at[3] = {0, 0, 1};
    const int bt[3] = {2, 3, 2};

#pragma unroll
    for (int t = 0; t < 3; ++t) {
        const uint32_t abase = s0 + at[t] * SBUF;
        const uint32_t bbase = s0 + bt[t] * SBUF;
#pragma unroll
        for (int k16 = 0; k16 < 4; ++k16) {
            uint32_t af[2][4];
#pragma unroll
            for (int fm = 0; fm < 2; ++fm)
                LDM_X4(af[fm], abase + (a_lane_row + fm * 16) * SROWB
                               + k16 * 32 + a_lane_col);
            uint32_t bfr[8][2];
#pragma unroll
            for (int fp = 0; fp < 4; ++fp) {
                uint32_t r[4];
                LDM_X4(r, bbase + (b_lane_row + fp * 16) * SROWB
                          + k16 * 32 + b_lane_col);
                bfr[fp * 2][0] = r[0]; bfr[fp * 2][1] = r[1];
                bfr[fp * 2 + 1][0] = r[2]; bfr[fp * 2 + 1][1] = r[3];
            }
#pragma unroll
            for (int fm = 0; fm < 2; ++fm)
#pragma unroll
                for (int fn = 0; fn < 8; ++fn)
                    MMA_BF16(acc[fm][fn], af[fm], bfr[fn][0], bfr[fn][1]);
        }
    }

    float* out = dist + ((size_t)bb << 20);
#pragma unroll
    for (int fm = 0; fm < 2; ++fm)
#pragma unroll
        for (int half = 0; half < 2; ++half) {
            int i = tit * 128 + warp_m + fm * 16 + (lane >> 2) + half * 8;
            float* orow = out + (size_t)i * 1024 + tjt * 128 + warp_n + (lane & 3) * 2;
#pragma unroll
            for (int fn = 0; fn < 8; ++fn) {
                float2 v = half
                    ? make_float2(acc[fm][fn][2] * 0.125f, acc[fm][fn][3] * 0.125f)
                    : make_float2(acc[fm][fn][0] * 0.125f, acc[fm][fn][1] * 0.125f);
                *(float2*)(orow + fn * 8) = v;
            }
        }
}

// ============================================================================
// rowstat
// ============================================================================
__global__ void __launch_bounds__(256) rowstat_kernel(
    const float* __restrict__ dist, float* __restrict__ rowm,
    float* __restrict__ rowl)
{
    const int i  = blockIdx.x;
    const int bb = blockIdx.y;
    const float* row = dist + ((size_t)bb << 20) + (size_t)i * S_;
    const int len = i + 1;

    __shared__ float sh[S_];
    __shared__ float red[8];
    const int tid = threadIdx.x;

    float m = -3.4e38f;
    for (int j = tid; j < len; j += 256) {
        float v = row[j];
        sh[j] = v;
        m = fmaxf(m, v);
    }
#pragma unroll
    for (int o = 16; o; o >>= 1) m = fmaxf(m, __shfl_xor_sync(0xffffffffu, m, o));
    if ((tid & 31) == 0) red[tid >> 5] = m;
    __syncthreads();
    if (tid < 8) {
        m = red[tid];
#pragma unroll
        for (int o = 4; o; o >>= 1) m = fmaxf(m, __shfl_xor_sync(0xffu, m, o));
        if (tid == 0) red[0] = m;
    }
    __syncthreads();
    m = red[0];
    __syncthreads();

    float s = 0.f;
    for (int j = tid; j < len; j += 256)
        s += __expf(sh[j] - m);
#pragma unroll
    for (int o = 16; o; o >>= 1) s += __shfl_xor_sync(0xffffffffu, s, o);
    if ((tid & 31) == 0) red[tid >> 5] = s;
    __syncthreads();
    if (tid < 8) {
        s = red[tid];
#pragma unroll
        for (int o = 4; o; o >>= 1) s += __shfl_xor_sync(0xffu, s, o);
        if (tid == 0) {
            rowm[(bb << 10) + i] = m;
            rowl[(bb << 10) + i] = 1.f / s;
        }
    }
}

// ============================================================================
// att fused (fp16 2-term)
// ============================================================================
__global__ void __launch_bounds__(256, 2) att_fused_kernel(
    float* __restrict__ dist, const float* __restrict__ Vp,
    const float* __restrict__ rowm, const float* __restrict__ rowl,
    float* __restrict__ att)
{
    __shared__ __half Ps[32][136];
    __shared__ __half Vs[2][32][72];

    const int jt = blockIdx.x;
    const int bb = blockIdx.y;
    const int h = bb >> 3;
    const int b = bb & 7;
    const int j0 = jt * 128;

    const int tid  = threadIdx.x;
    const int wid  = tid >> 5;
    const int lane = tid & 31;
    const int warp_m = (wid & 3) * 32;
    const int warp_n = (wid >> 2) * 32;

    float* dbase = dist + ((size_t)bb << 20);
    const float* vbase = Vp + (size_t)b * 1024 + (size_t)h * 64;
    const float* mrow = rowm + (bb << 10);
    const float* lrow = rowl + (bb << 10);

    const float4 z4 = make_float4(0.f, 0.f, 0.f, 0.f);
    for (int it = 0; it < jt; ++it) {
#pragma unroll
        for (int q = 0; q < 16; ++q) {
            int id = tid + 256 * q;
            int r = id >> 5, c4 = id & 31;
            *(float4*)(dbase + (size_t)(it * 128 + r) * 1024 + j0 + c4 * 4) = z4;
        }
    }

    const uint32_t PB = smem_u32(&Ps[0][0]);
    const uint32_t VhB = smem_u32(&Vs[0][0][0]);
    const uint32_t VlB = smem_u32(&Vs[1][0][0]);

    float acc[2][4][4];
#pragma unroll
    for (int a = 0; a < 2; ++a)
#pragma unroll
        for (int c = 0; c < 4; ++c)
#pragma unroll
            for (int e = 0; e < 4; ++e) acc[a][c][e] = 0.f;

    const int nsteps = (1024 - j0) / 32;

    for (int step = 0; step < nsteps; ++step) {
        const int i0 = j0 + step * 32;

#pragma unroll
        for (int q = 0; q < 4; ++q) {
            int id = tid + 256 * q;
            int r = id >> 5, c4 = id & 31;
            const int iv = i0 + r;
            float4 s = *(const float4*)(dbase + (size_t)iv * 1024 + j0 + c4 * 4);
            float m  = __ldg(mrow + iv);
            float il = __ldg(lrow + iv);
            int jv = j0 + c4 * 4;
            float p0 = (jv + 0 <= iv) ? __expf(s.x - m) * il : 0.f;
            float p1 = (jv + 1 <= iv) ? __expf(s.y - m) * il : 0.f;
            float p2 = (jv + 2 <= iv) ? __expf(s.z - m) * il : 0.f;
            float p3 = (jv + 3 <= iv) ? __expf(s.w - m) * il : 0.f;
            *(float4*)(dbase + (size_t)iv * 1024 + j0 + c4 * 4)
                = make_float4(p0, p1, p2, p3);
            __half2 h01 = __floats2half2_rn(p0, p1);
            __half2 h23 = __floats2half2_rn(p2, p3);
            *(uint2*)(&Ps[r][c4 * 4]) = make_uint2(*(uint32_t*)&h01, *(uint32_t*)&h23);
        }
#pragma unroll
        for (int q = 0; q < 2; ++q) {
            int id = tid + 256 * q;
            int r = id >> 4, c4 = id & 15;
            float4 v = *(const float4*)(vbase + (size_t)(i0 + r) * 8192 + c4 * 4);
            uint32_t h0, l0, h1, l1;
            split2h(v.x, v.y, h0, l0);
            split2h(v.z, v.w, h1, l1);
            *(uint2*)(&Vs[0][r][c4 * 4]) = make_uint2(h0, h1);
            *(uint2*)(&Vs[1][r][c4 * 4]) = make_uint2(l0, l1);
        }
        __syncthreads();

#pragma unroll
        for (int k16 = 0; k16 < 2; ++k16) {
            const uint32_t arow = k16 * 16 + ((lane >> 4) << 3) + (lane & 7);
            uint32_t af[2][4];
#pragma unroll
            for (int fm = 0; fm < 2; ++fm) {
                const uint32_t acolb =
                    (warp_m + fm * 16 + (((lane >> 3) & 1) << 3)) * 2;
                LDM_X4_T(af[fm], PB + arow * 272 + acolb);
            }
            const uint32_t brow = k16 * 16 + (((lane >> 3) & 1) << 3) + (lane & 7);
            uint32_t bH[4][2], bL[4][2];
#pragma unroll
            for (int fp = 0; fp < 2; ++fp) {
                const uint32_t bcolb =
                    (warp_n + fp * 16 + ((lane >> 4) << 3)) * 2;
                uint32_t r[4];
                LDM_X4_T(r, VhB + brow * 144 + bcolb);
                bH[fp * 2][0] = r[0]; bH[fp * 2][1] = r[1];
                bH[fp * 2 + 1][0] = r[2]; bH[fp * 2 + 1][1] = r[3];
                LDM_X4_T(r, VlB + brow * 144 + bcolb);
                bL[fp * 2][0] = r[0]; bL[fp * 2][1] = r[1];
                bL[fp * 2 + 1][0] = r[2]; bL[fp * 2 + 1][1] = r[3];
            }
#pragma unroll
            for (int fm = 0; fm < 2; ++fm)
#pragma unroll
                for (int fn = 0; fn < 4; ++fn) {
                    MMA_F16(acc[fm][fn], af[fm], bH[fn][0], bH[fn][1]);
                    MMA_F16(acc[fm][fn], af[fm], bL[fn][0], bL[fn][1]);
                }
        }
        __syncthreads();
    }

#pragma unroll
    for (int fm = 0; fm < 2; ++fm)
#pragma unroll
        for (int half = 0; half < 2; ++half) {
            int j = j0 + warp_m + fm * 16 + (lane >> 2) + half * 8;
            float* cr = att + ((size_t)b * 1024 + j) * 1024 + h * 64
                        + warp_n + (lane & 3) * 2;
#pragma unroll
            for (int fn = 0; fn < 4; ++fn) {
                float2 v = half ? make_float2(acc[fm][fn][2], acc[fm][fn][3])
                                : make_float2(acc[fm][fn][0], acc[fm][fn][1]);
                *(float2*)(cr + fn * 8) = v;
            }
        }
}

// ---------------------------------------------------------------------------
extern "C" void kernel_launch(void* const* d_in, const int* in_sizes, int n_in,
                              void* d_out, int out_size)
{
    const float* value = (const float*)d_in[0];
    const float* key   = (const float*)d_in[1];
    const float* query = (const float*)d_in[2];
    const float* Wq    = (const float*)d_in[3];
    const float* Wk    = (const float*)d_in[4];
    const float* Wv    = (const float*)d_in[5];
    const float* Wo    = (const float*)d_in[6];
    float* out = (float*)d_out;

    float* g_v_p;   cudaGetSymbolAddress((void**)&g_v_p,   g_v);
    float* g_att_p; cudaGetSymbolAddress((void**)&g_att_p, g_att);
    float* rm_p;    cudaGetSymbolAddress((void**)&rm_p,    g_rowm);
    float* rl_p;    cudaGetSymbolAddress((void**)&rl_p,    g_rowl);
    __half *w16h, *w16l, *x16;
    cudaGetSymbolAddress((void**)&w16h, g_w16h);
    cudaGetSymbolAddress((void**)&w16l, g_w16l);
    cudaGetSymbolAddress((void**)&x16,  g_x16);
    __nv_bfloat16 *qh, *ql, *kh, *kl;
    cudaGetSymbolAddress((void**)&qh, g_qh);
    cudaGetSymbolAddress((void**)&ql, g_ql);
    cudaGetSymbolAddress((void**)&kh, g_kh);
    cudaGetSymbolAddress((void**)&kl, g_kl);

    float* dist_p;
    if ((long long)out_size == (long long)OUT_ELEMS + (long long)DIST_ELEMS) {
        dist_p = out + OUT_ELEMS;
    } else {
        cudaGetSymbolAddress((void**)&dist_p, g_dist_fallback);
    }

    static int attr_done = 0;
    if (!attr_done) {
        cudaFuncSetAttribute(gemm_fp16_kernel,
                             cudaFuncAttributeMaxDynamicSharedMemorySize, G2_SMEM);
        cudaFuncSetAttribute(scores_hmma_kernel,
                             cudaFuncAttributeMaxDynamicSharedMemorySize, 4 * SBUF);
        attr_done = 1;
    }

    dim3 blk(256);
    dim3 grid_g(8, 64);
    const size_t ASEG = (size_t)SB_ * H_;

    conv_w4_kernel<<<4096, blk>>>((const float4*)Wq, (const float4*)Wk,
                                  (const float4*)Wv, (const float4*)Wo,
                                  (uint32_t*)w16h, (uint32_t*)w16l);
    conv_a3_kernel<<<24576, blk>>>((const float4*)query, (const float4*)key,
                                   (const float4*)value, (uint32_t*)x16);

    gemm_fp16_kernel<<<grid_g, blk, G2_SMEM>>>(x16,            w16h,           w16l,           nullptr, qh, ql, 2);
    gemm_fp16_kernel<<<grid_g, blk, G2_SMEM>>>(x16 + ASEG,     w16h + WW_,     w16l + WW_,     nullptr, kh, kl, 2);
    gemm_fp16_kernel<<<grid_g, blk, G2_SMEM>>>(x16 + 2 * ASEG, w16h + 2 * WW_, w16l + 2 * WW_, g_v_p, nullptr, nullptr, 0);

    dim3 grid_sc(36, 128);
    scores_hmma_kernel<<<grid_sc, blk, 4 * SBUF>>>(qh, ql, kh, kl, dist_p);

    dim3 grid_rs(1024, 128);
    rowstat_kernel<<<grid_rs, blk>>>(dist_p, rm_p, rl_p);

    dim3 grid_att(8, 128);
    att_fused_kernel<<<grid_att, blk>>>(dist_p, g_v_p, rm_p, rl_p, g_att_p);

    conv_a1_kernel<<<8192, blk>>>((const float4*)g_att_p, (uint32_t*)x16);
    gemm_fp16_kernel<<<grid_g, blk, G2_SMEM>>>(x16, w16h + 3 * WW_, w16l + 3 * WW_, out, nullptr, nullptr, 1);
}

// round 11
// speedup vs baseline: 2.3456x; 1.0314x over previous
#include <cuda_runtime.h>
#include <cuda_bf16.h>
#include <cuda_fp16.h>
#include <math.h>
#include <stdint.h>

// Problem constants
#define S_   1024
#define B_   8
#define H_   1024
#define NH_  16
#define DK_  64
#define BH_  128
#define SB_  8192
#define OUT_ELEMS  (S_*B_*H_)
#define DIST_ELEMS (BH_*S_*S_)
#define WW_  (H_*H_)

// ---------------- scratch ----------------
__device__ float g_v[SB_ * H_];
__device__ float g_att[SB_ * H_];
__device__ float g_dist_fallback[DIST_ELEMS];
__device__ float g_rowm[BH_ * S_];
__device__ float g_rowl[BH_ * S_];
__device__ __half g_w16h[4 * WW_];
__device__ __half g_w16l[4 * WW_];
__device__ __half g_x16[3 * SB_ * H_];
__device__ __nv_bfloat16 g_qh[SB_ * H_];
__device__ __nv_bfloat16 g_ql[SB_ * H_];
__device__ __nv_bfloat16 g_kh[SB_ * H_];
__device__ __nv_bfloat16 g_kl[SB_ * H_];

__device__ __forceinline__ uint32_t smem_u32(const void* p) {
    uint32_t a;
    asm("{ .reg .u64 t; cvta.to.shared.u64 t, %1; cvt.u32.u64 %0, t; }"
        : "=r"(a) : "l"(p));
    return a;
}
__device__ __forceinline__ void cp_async16(uint32_t dst, const void* src) {
    asm volatile("cp.async.ca.shared.global [%0], [%1], 16;" :: "r"(dst), "l"(src));
}
#define CP_COMMIT() asm volatile("cp.async.commit_group;" ::: "memory")
#define CP_WAIT(N)  asm volatile("cp.async.wait_group %0;" :: "n"(N) : "memory")

#define LDM_X4(r, addr)                                                        \
    asm volatile("ldmatrix.sync.aligned.m8n8.x4.shared.b16 {%0,%1,%2,%3}, [%4];" \
                 : "=r"((r)[0]), "=r"((r)[1]), "=r"((r)[2]), "=r"((r)[3]) : "r"(addr))
#define LDM_X4_T(r, addr)                                                      \
    asm volatile("ldmatrix.sync.aligned.m8n8.x4.trans.shared.b16 {%0,%1,%2,%3}, [%4];" \
                 : "=r"((r)[0]), "=r"((r)[1]), "=r"((r)[2]), "=r"((r)[3]) : "r"(addr))

#define MMA_BF16(acc, a, b0, b1)                                               \
    asm volatile("mma.sync.aligned.m16n8k16.row.col.f32.bf16.bf16.f32 "        \
                 "{%0,%1,%2,%3}, {%4,%5,%6,%7}, {%8,%9}, {%0,%1,%2,%3};"       \
                 : "+f"((acc)[0]), "+f"((acc)[1]), "+f"((acc)[2]), "+f"((acc)[3]) \
                 : "r"((a)[0]), "r"((a)[1]), "r"((a)[2]), "r"((a)[3]),         \
                   "r"(b0), "r"(b1))
#define MMA_F16(acc, a, b0, b1)                                                \
    asm volatile("mma.sync.aligned.m16n8k16.row.col.f32.f16.f16.f32 "          \
                 "{%0,%1,%2,%3}, {%4,%5,%6,%7}, {%8,%9}, {%0,%1,%2,%3};"       \
                 : "+f"((acc)[0]), "+f"((acc)[1]), "+f"((acc)[2]), "+f"((acc)[3]) \
                 : "r"((a)[0]), "r"((a)[1]), "r"((a)[2]), "r"((a)[3]),         \
                   "r"(b0), "r"(b1))

__device__ __forceinline__ void split2(float x, float y,
                                       uint32_t& hi, uint32_t& lo) {
    __nv_bfloat162 h = __floats2bfloat162_rn(x, y);
    float rx = x - __bfloat162float(h.x);
    float ry = y - __bfloat162float(h.y);
    __nv_bfloat162 l = __floats2bfloat162_rn(rx, ry);
    hi = *(uint32_t*)&h;
    lo = *(uint32_t*)&l;
}
__device__ __forceinline__ void split2h(float x, float y,
                                        uint32_t& hi, uint32_t& lo) {
    __half2 h = __floats2half2_rn(x, y);
    float rx = x - __half2float(__low2half(h));
    float ry = y - __half2float(__high2half(h));
    __half2 l = __floats2half2_rn(rx, ry);
    hi = *(uint32_t*)&h;
    lo = *(uint32_t*)&l;
}

// ============================================================================
// conv kernels
// ============================================================================
__global__ void __launch_bounds__(256) conv_w4_kernel(
    const float4* __restrict__ W0, const float4* __restrict__ W1,
    const float4* __restrict__ W2, const float4* __restrict__ W3,
    uint32_t* __restrict__ hi, uint32_t* __restrict__ lo)
{
    int i = blockIdx.x * 256 + threadIdx.x;
    int mat = i >> 18, off = i & 262143;
    const float4* src = (mat == 0) ? W0 : (mat == 1) ? W1 : (mat == 2) ? W2 : W3;
    float4 v = src[off];
    uint32_t h0, l0, h1, l1;
    split2h(v.x, v.y, h0, l0);
    split2h(v.z, v.w, h1, l1);
    hi[2 * i] = h0; hi[2 * i + 1] = h1;
    lo[2 * i] = l0; lo[2 * i + 1] = l1;
}

__global__ void __launch_bounds__(256) conv_a3_kernel(
    const float4* __restrict__ X0, const float4* __restrict__ X1,
    const float4* __restrict__ X2, uint32_t* __restrict__ dst)
{
    int i = blockIdx.x * 256 + threadIdx.x;
    int mat = i >> 21, off = i & 2097151;
    const float4* src = (mat == 0) ? X0 : (mat == 1) ? X1 : X2;
    float4 v = src[off];
    __half2 h01 = __floats2half2_rn(v.x, v.y);
    __half2 h23 = __floats2half2_rn(v.z, v.w);
    dst[2 * i] = *(uint32_t*)&h01;
    dst[2 * i + 1] = *(uint32_t*)&h23;
}

__global__ void __launch_bounds__(256) conv_a1_kernel(
    const float4* __restrict__ X, uint32_t* __restrict__ dst)
{
    int i = blockIdx.x * 256 + threadIdx.x;
    float4 v = X[i];
    __half2 h01 = __floats2half2_rn(v.x, v.y);
    __half2 h23 = __floats2half2_rn(v.z, v.w);
    dst[2 * i] = *(uint32_t*)&h01;
    dst[2 * i + 1] = *(uint32_t*)&h23;
}

// ============================================================================
// fp16 2-term GEMM, 4 warps x (64x64) tiles: C = A @ W^T.
// 12 LDSM per 64 MMAs (vs 10/32 before) -> smem-BW per MMA cut by 40%.
// ============================================================================
#define ROWB 80
#define G2STAGE 30720
#define G2_SMEM (3 * G2STAGE)

__global__ void __launch_bounds__(128, 2) gemm_fp16_kernel(
    const __half* __restrict__ A16, const __half* __restrict__ Wh,
    const __half* __restrict__ Wl, float* __restrict__ C,
    __nv_bfloat16* __restrict__ Oh, __nv_bfloat16* __restrict__ Ol, int mode)
{
    extern __shared__ char gsm[];
    const uint32_t s0 = smem_u32(gsm);

    const int tid  = threadIdx.x;
    const int wid  = tid >> 5;
    const int lane = tid & 31;
    const int m0 = blockIdx.y * 128;
    const int n0 = blockIdx.x * 128;
    const int warp_m = (wid & 1) * 64;
    const int warp_n = (wid >> 1) * 64;

    float acc[4][8][4];
#pragma unroll
    for (int a = 0; a < 4; ++a)
#pragma unroll
        for (int b = 0; b < 8; ++b)
#pragma unroll
            for (int c = 0; c < 4; ++c) acc[a][b][c] = 0.f;

#define LOAD2(st, kt) do {                                                     \
    int kk_ = (kt) * 32;                                                       \
    const __half* ga_ = A16 + (size_t)m0 * 1024 + kk_;                         \
    const __half* gh_ = Wh + (size_t)n0 * 1024 + kk_;                          \
    const __half* gl_ = Wl + (size_t)n0 * 1024 + kk_;                          \
    uint32_t base_ = s0 + (st) * G2STAGE;                                      \
    _Pragma("unroll")                                                          \
    for (int l_ = 0; l_ < 4; ++l_) {                                           \
        int id_ = tid + 128 * l_;                                              \
        int row_ = id_ >> 2, c_ = id_ & 3;                                     \
        cp_async16(base_ + row_ * ROWB + c_ * 16,                              \
                   ga_ + (size_t)row_ * 1024 + c_ * 8);                        \
        cp_async16(base_ + 10240u + row_ * ROWB + c_ * 16,                     \
                   gh_ + (size_t)row_ * 1024 + c_ * 8);                        \
        cp_async16(base_ + 20480u + row_ * ROWB + c_ * 16,                     \
                   gl_ + (size_t)row_ * 1024 + c_ * 8);                        \
    }                                                                          \
    CP_COMMIT();                                                               \
} while (0)

    LOAD2(0, 0);
    LOAD2(1, 1);

    const uint32_t a_lane_row = warp_m + (lane & 15);
    const uint32_t a_lane_col = (lane >> 4) * 16;
    const uint32_t b_lane_row = warp_n + (lane & 7) + ((lane >> 4) << 3);
    const uint32_t b_lane_col = ((lane >> 3) & 1) * 16;

    for (int kt = 0; kt < 32; ++kt) {
        const int st = kt - (kt / 3) * 3;
        if (kt < 30) CP_WAIT(1); else CP_WAIT(0);
        __syncthreads();
        if (kt + 2 < 32) {
            int st2 = (kt + 2) - ((kt + 2) / 3) * 3;
            LOAD2(st2, kt + 2);
        }

        const uint32_t abase = s0 + st * G2STAGE;

#pragma unroll
        for (int k16 = 0; k16 < 2; ++k16) {
            uint32_t af[4][4];
#pragma unroll
            for (int fm = 0; fm < 4; ++fm)
                LDM_X4(af[fm], abase + (a_lane_row + fm * 16) * ROWB
                               + k16 * 32 + a_lane_col);
            uint32_t bf[8][2];
            // ---- hi pass ----
#pragma unroll
            for (int fp = 0; fp < 4; ++fp) {
                uint32_t r[4];
                LDM_X4(r, abase + 10240u + (b_lane_row + fp * 16) * ROWB
                          + k16 * 32 + b_lane_col);
                bf[fp * 2][0] = r[0]; bf[fp * 2][1] = r[1];
                bf[fp * 2 + 1][0] = r[2]; bf[fp * 2 + 1][1] = r[3];
            }
#pragma unroll
            for (int fm = 0; fm < 4; ++fm)
#pragma unroll
                for (int fn = 0; fn < 8; ++fn)
                    MMA_F16(acc[fm][fn], af[fm], bf[fn][0], bf[fn][1]);
            // ---- lo pass (reuse bf regs) ----
#pragma unroll
            for (int fp = 0; fp < 4; ++fp) {
                uint32_t r[4];
                LDM_X4(r, abase + 20480u + (b_lane_row + fp * 16) * ROWB
                          + k16 * 32 + b_lane_col);
                bf[fp * 2][0] = r[0]; bf[fp * 2][1] = r[1];
                bf[fp * 2 + 1][0] = r[2]; bf[fp * 2 + 1][1] = r[3];
            }
#pragma unroll
            for (int fm = 0; fm < 4; ++fm)
#pragma unroll
                for (int fn = 0; fn < 8; ++fn)
                    MMA_F16(acc[fm][fn], af[fm], bf[fn][0], bf[fn][1]);
        }
    }

#pragma unroll
    for (int fm = 0; fm < 4; ++fm) {
#pragma unroll
        for (int half = 0; half < 2; ++half) {
            int m = m0 + warp_m + fm * 16 + (lane >> 2) + half * 8;
            if (mode == 2) {
                int s = m >> 3, b = m & 7;
#pragma unroll
                for (int fn = 0; fn < 8; ++fn) {
                    int col = n0 + warp_n + (lane & 3) * 2 + fn * 8;
                    int h = col >> 6, d = col & 63;
                    size_t addr = ((size_t)(h * 8 + b) * 1024 + s) * 64 + d;
                    uint32_t hi, lo;
                    split2(acc[fm][fn][half * 2], acc[fm][fn][half * 2 + 1], hi, lo);
                    *(uint32_t*)(Oh + addr) = hi;
                    *(uint32_t*)(Ol + addr) = lo;
                }
            } else {
                int orow = mode ? ((m & (S_ - 1)) * B_ + (m >> 10)) : m;
                float* cr = C + (size_t)orow * 1024 + n0 + warp_n + (lane & 3) * 2;
#pragma unroll
                for (int fn = 0; fn < 8; ++fn) {
                    float2 v = half ? make_float2(acc[fm][fn][2], acc[fm][fn][3])
                                    : make_float2(acc[fm][fn][0], acc[fm][fn][1]);
                    *(float2*)(cr + fn * 8) = v;
                }
            }
        }
    }
#undef LOAD2
}

// ============================================================================
// scores HMMA (3-term bf16): raw lower-tri 128x128 tiles into dist.
// ============================================================================
#define SROWB 144
#define SBUF  18432

__global__ void __launch_bounds__(256, 2) scores_hmma_kernel(
    const __nv_bfloat16* __restrict__ Qh, const __nv_bfloat16* __restrict__ Ql,
    const __nv_bfloat16* __restrict__ Kh, const __nv_bfloat16* __restrict__ Kl,
    float* __restrict__ dist)
{
    extern __shared__ char sm[];
    const uint32_t s0 = smem_u32(sm);
    const int pid = blockIdx.x;
    const int bb  = blockIdx.y;
    int tit = 0;
    while ((tit + 1) * (tit + 2) / 2 <= pid) ++tit;
    const int tjt = pid - tit * (tit + 1) / 2;

    const int tid  = threadIdx.x;
    const int wid  = tid >> 5;
    const int lane = tid & 31;
    const int warp_m = (wid & 3) * 32;
    const int warp_n = (wid >> 2) * 64;

    const size_t hb = (size_t)bb * 65536;
    const __nv_bfloat16* srcs[4] = {Kh + hb, Kl + hb, Qh + hb, Ql + hb};
    const int rbase[4] = {tit * 128, tit * 128, tjt * 128, tjt * 128};

#pragma unroll
    for (int bfi = 0; bfi < 4; ++bfi) {
#pragma unroll
        for (int l = 0; l < 4; ++l) {
            int id = tid + 256 * l;
            int row = id >> 3, c = id & 7;
            cp_async16(s0 + bfi * SBUF + row * SROWB + c * 16,
                       srcs[bfi] + (size_t)(rbase[bfi] + row) * 64 + c * 8);
        }
    }
    CP_COMMIT();
    CP_WAIT(0);
    __syncthreads();

    const uint32_t a_lane_row = warp_m + (lane & 15);
    const uint32_t a_lane_col = (lane >> 4) * 16;
    const uint32_t b_lane_row = warp_n + (lane & 7) + ((lane >> 4) << 3);
    const uint32_t b_lane_col = ((lane >> 3) & 1) * 16;

    float acc[2][8][4];
#pragma unroll
    for (int a = 0; a < 2; ++a)
#pragma unroll
        for (int b = 0; b < 8; ++b)
#pragma unroll
            for (int c = 0; c < 4; ++c) acc[a][b][c] = 0.f;

    const int at[3] = {0, 0, 1};
    const int bt[3] = {2, 3, 2};

#pragma unroll
    for (int t = 0; t < 3; ++t) {
        const uint32_t abase = s0 + at[t] * SBUF;
        const uint32_t bbase = s0 + bt[t] * SBUF;
#pragma unroll
        for (int k16 = 0; k16 < 4; ++k16) {
            uint32_t af[2][4];
#pragma unroll
            for (int fm = 0; fm < 2; ++fm)
                LDM_X4(af[fm], abase + (a_lane_row + fm * 16) * SROWB
                               + k16 * 32 + a_lane_col);
            uint32_t bfr[8][2];
#pragma unroll
            for (int fp = 0; fp < 4; ++fp) {
                uint32_t r[4];
                LDM_X4(r, bbase + (b_lane_row + fp * 16) * SROWB
                          + k16 * 32 + b_lane_col);
                bfr[fp * 2][0] = r[0]; bfr[fp * 2][1] = r[1];
                bfr[fp * 2 + 1][0] = r[2]; bfr[fp * 2 + 1][1] = r[3];
            }
#pragma unroll
            for (int fm = 0; fm < 2; ++fm)
#pragma unroll
                for (int fn = 0; fn < 8; ++fn)
                    MMA_BF16(acc[fm][fn], af[fm], bfr[fn][0], bfr[fn][1]);
        }
    }

    float* out = dist + ((size_t)bb << 20);
#pragma unroll
    for (int fm = 0; fm < 2; ++fm)
#pragma unroll
        for (int half = 0; half < 2; ++half) {
            int i = tit * 128 + warp_m + fm * 16 + (lane >> 2) + half * 8;
            float* orow = out + (size_t)i * 1024 + tjt * 128 + warp_n + (lane & 3) * 2;
#pragma unroll
            for (int fn = 0; fn < 8; ++fn) {
                float2 v = half
                    ? make_float2(acc[fm][fn][2] * 0.125f, acc[fm][fn][3] * 0.125f)
                    : make_float2(acc[fm][fn][0] * 0.125f, acc[fm][fn][1] * 0.125f);
                *(float2*)(orow + fn * 8) = v;
            }
        }
}

// ============================================================================
// rowstat
// ============================================================================
__global__ void __launch_bounds__(256) rowstat_kernel(
    const float* __restrict__ dist, float* __restrict__ rowm,
    float* __restrict__ rowl)
{
    const int i  = blockIdx.x;
    const int bb = blockIdx.y;
    const float* row = dist + ((size_t)bb << 20) + (size_t)i * S_;
    const int len = i + 1;

    __shared__ float sh[S_];
    __shared__ float red[8];
    const int tid = threadIdx.x;

    float m = -3.4e38f;
    for (int j = tid; j < len; j += 256) {
        float v = row[j];
        sh[j] = v;
        m = fmaxf(m, v);
    }
#pragma unroll
    for (int o = 16; o; o >>= 1) m = fmaxf(m, __shfl_xor_sync(0xffffffffu, m, o));
    if ((tid & 31) == 0) red[tid >> 5] = m;
    __syncthreads();
    if (tid < 8) {
        m = red[tid];
#pragma unroll
        for (int o = 4; o; o >>= 1) m = fmaxf(m, __shfl_xor_sync(0xffu, m, o));
        if (tid == 0) red[0] = m;
    }
    __syncthreads();
    m = red[0];
    __syncthreads();

    float s = 0.f;
    for (int j = tid; j < len; j += 256)
        s += __expf(sh[j] - m);
#pragma unroll
    for (int o = 16; o; o >>= 1) s += __shfl_xor_sync(0xffffffffu, s, o);
    if ((tid & 31) == 0) red[tid >> 5] = s;
    __syncthreads();
    if (tid < 8) {
        s = red[tid];
#pragma unroll
        for (int o = 4; o; o >>= 1) s += __shfl_xor_sync(0xffu, s, o);
        if (tid == 0) {
            rowm[(bb << 10) + i] = m;
            rowl[(bb << 10) + i] = 1.f / s;
        }
    }
}

// ============================================================================
// att fused (fp16 2-term)
// ============================================================================
__global__ void __launch_bounds__(256, 2) att_fused_kernel(
    float* __restrict__ dist, const float* __restrict__ Vp,
    const float* __restrict__ rowm, const float* __restrict__ rowl,
    float* __restrict__ att)
{
    __shared__ __half Ps[32][136];
    __shared__ __half Vs[2][32][72];

    const int jt = blockIdx.x;
    const int bb = blockIdx.y;
    const int h = bb >> 3;
    const int b = bb & 7;
    const int j0 = jt * 128;

    const int tid  = threadIdx.x;
    const int wid  = tid >> 5;
    const int lane = tid & 31;
    const int warp_m = (wid & 3) * 32;
    const int warp_n = (wid >> 2) * 32;

    float* dbase = dist + ((size_t)bb << 20);
    const float* vbase = Vp + (size_t)b * 1024 + (size_t)h * 64;
    const float* mrow = rowm + (bb << 10);
    const float* lrow = rowl + (bb << 10);

    const float4 z4 = make_float4(0.f, 0.f, 0.f, 0.f);
    for (int it = 0; it < jt; ++it) {
#pragma unroll
        for (int q = 0; q < 16; ++q) {
            int id = tid + 256 * q;
            int r = id >> 5, c4 = id & 31;
            *(float4*)(dbase + (size_t)(it * 128 + r) * 1024 + j0 + c4 * 4) = z4;
        }
    }

    const uint32_t PB = smem_u32(&Ps[0][0]);
    const uint32_t VhB = smem_u32(&Vs[0][0][0]);
    const uint32_t VlB = smem_u32(&Vs[1][0][0]);

    float acc[2][4][4];
#pragma unroll
    for (int a = 0; a < 2; ++a)
#pragma unroll
        for (int c = 0; c < 4; ++c)
#pragma unroll
            for (int e = 0; e < 4; ++e) acc[a][c][e] = 0.f;

    const int nsteps = (1024 - j0) / 32;

    for (int step = 0; step < nsteps; ++step) {
        const int i0 = j0 + step * 32;

#pragma unroll
        for (int q = 0; q < 4; ++q) {
            int id = tid + 256 * q;
            int r = id >> 5, c4 = id & 31;
            const int iv = i0 + r;
            float4 s = *(const float4*)(dbase + (size_t)iv * 1024 + j0 + c4 * 4);
            float m  = __ldg(mrow + iv);
            float il = __ldg(lrow + iv);
            int jv = j0 + c4 * 4;
            float p0 = (jv + 0 <= iv) ? __expf(s.x - m) * il : 0.f;
            float p1 = (jv + 1 <= iv) ? __expf(s.y - m) * il : 0.f;
            float p2 = (jv + 2 <= iv) ? __expf(s.z - m) * il : 0.f;
            float p3 = (jv + 3 <= iv) ? __expf(s.w - m) * il : 0.f;
            *(float4*)(dbase + (size_t)iv * 1024 + j0 + c4 * 4)
                = make_float4(p0, p1, p2, p3);
            __half2 h01 = __floats2half2_rn(p0, p1);
            __half2 h23 = __floats2half2_rn(p2, p3);
            *(uint2*)(&Ps[r][c4 * 4]) = make_uint2(*(uint32_t*)&h01, *(uint32_t*)&h23);
        }
#pragma unroll
        for (int q = 0; q < 2; ++q) {
            int id = tid + 256 * q;
            int r = id >> 4, c4 = id & 15;
            float4 v = *(const float4*)(vbase + (size_t)(i0 + r) * 8192 + c4 * 4);
            uint32_t h0, l0, h1, l1;
            split2h(v.x, v.y, h0, l0);
            split2h(v.z, v.w, h1, l1);
            *(uint2*)(&Vs[0][r][c4 * 4]) = make_uint2(h0, h1);
            *(uint2*)(&Vs[1][r][c4 * 4]) = make_uint2(l0, l1);
        }
        __syncthreads();

#pragma unroll
        for (int k16 = 0; k16 < 2; ++k16) {
            const uint32_t arow = k16 * 16 + ((lane >> 4) << 3) + (lane & 7);
            uint32_t af[2][4];
#pragma unroll
            for (int fm = 0; fm < 2; ++fm) {
                const uint32_t acolb =
                    (warp_m + fm * 16 + (((lane >> 3) & 1) << 3)) * 2;
                LDM_X4_T(af[fm], PB + arow * 272 + acolb);
            }
            const uint32_t brow = k16 * 16 + (((lane >> 3) & 1) << 3) + (lane & 7);
            uint32_t bH[4][2], bL[4][2];
#pragma unroll
            for (int fp = 0; fp < 2; ++fp) {
                const uint32_t bcolb =
                    (warp_n + fp * 16 + ((lane >> 4) << 3)) * 2;
                uint32_t r[4];
                LDM_X4_T(r, VhB + brow * 144 + bcolb);
                bH[fp * 2][0] = r[0]; bH[fp * 2][1] = r[1];
                bH[fp * 2 + 1][0] = r[2]; bH[fp * 2 + 1][1] = r[3];
                LDM_X4_T(r, VlB + brow * 144 + bcolb);
                bL[fp * 2][0] = r[0]; bL[fp * 2][1] = r[1];
                bL[fp * 2 + 1][0] = r[2]; bL[fp * 2 + 1][1] = r[3];
            }
#pragma unroll
            for (int fm = 0; fm < 2; ++fm)
#pragma unroll
                for (int fn = 0; fn < 4; ++fn) {
                    MMA_F16(acc[fm][fn], af[fm], bH[fn][0], bH[fn][1]);
                    MMA_F16(acc[fm][fn], af[fm], bL[fn][0], bL[fn][1]);
                }
        }
        __syncthreads();
    }

#pragma unroll
    for (int fm = 0; fm < 2; ++fm)
#pragma unroll
        for (int half = 0; half < 2; ++half) {
            int j = j0 + warp_m + fm * 16 + (lane >> 2) + half * 8;
            float* cr = att + ((size_t)b * 1024 + j) * 1024 + h * 64
                        + warp_n + (lane & 3) * 2;
#pragma unroll
            for (int fn = 0; fn < 4; ++fn) {
                float2 v = half ? make_float2(acc[fm][fn][2], acc[fm][fn][3])
                                : make_float2(acc[fm][fn][0], acc[fm][fn][1]);
                *(float2*)(cr + fn * 8) = v;
            }
        }
}

// ---------------------------------------------------------------------------
extern "C" void kernel_launch(void* const* d_in, const int* in_sizes, int n_in,
                              void* d_out, int out_size)
{
    const float* value = (const float*)d_in[0];
    const float* key   = (const float*)d_in[1];
    const float* query = (const float*)d_in[2];
    const float* Wq    = (const float*)d_in[3];
    const float* Wk    = (const float*)d_in[4];
    const float* Wv    = (const float*)d_in[5];
    const float* Wo    = (const float*)d_in[6];
    float* out = (float*)d_out;

    float* g_v_p;   cudaGetSymbolAddress((void**)&g_v_p,   g_v);
    float* g_att_p; cudaGetSymbolAddress((void**)&g_att_p, g_att);
    float* rm_p;    cudaGetSymbolAddress((void**)&rm_p,    g_rowm);
    float* rl_p;    cudaGetSymbolAddress((void**)&rl_p,    g_rowl);
    __half *w16h, *w16l, *x16;
    cudaGetSymbolAddress((void**)&w16h, g_w16h);
    cudaGetSymbolAddress((void**)&w16l, g_w16l);
    cudaGetSymbolAddress((void**)&x16,  g_x16);
    __nv_bfloat16 *qh, *ql, *kh, *kl;
    cudaGetSymbolAddress((void**)&qh, g_qh);
    cudaGetSymbolAddress((void**)&ql, g_ql);
    cudaGetSymbolAddress((void**)&kh, g_kh);
    cudaGetSymbolAddress((void**)&kl, g_kl);

    float* dist_p;
    if ((long long)out_size == (long long)OUT_ELEMS + (long long)DIST_ELEMS) {
        dist_p = out + OUT_ELEMS;
    } else {
        cudaGetSymbolAddress((void**)&dist_p, g_dist_fallback);
    }

    static int attr_done = 0;
    if (!attr_done) {
        cudaFuncSetAttribute(gemm_fp16_kernel,
                             cudaFuncAttributeMaxDynamicSharedMemorySize, G2_SMEM);
        cudaFuncSetAttribute(scores_hmma_kernel,
                             cudaFuncAttributeMaxDynamicSharedMemorySize, 4 * SBUF);
        attr_done = 1;
    }

    dim3 blk(256);
    dim3 blkg(128);
    dim3 grid_g(8, 64);
    const size_t ASEG = (size_t)SB_ * H_;

    conv_w4_kernel<<<4096, blk>>>((const float4*)Wq, (const float4*)Wk,
                                  (const float4*)Wv, (const float4*)Wo,
                                  (uint32_t*)w16h, (uint32_t*)w16l);
    conv_a3_kernel<<<24576, blk>>>((const float4*)query, (const float4*)key,
                                   (const float4*)value, (uint32_t*)x16);

    gemm_fp16_kernel<<<grid_g, blkg, G2_SMEM>>>(x16,            w16h,           w16l,           nullptr, qh, ql, 2);
    gemm_fp16_kernel<<<grid_g, blkg, G2_SMEM>>>(x16 + ASEG,     w16h + WW_,     w16l + WW_,     nullptr, kh, kl, 2);
    gemm_fp16_kernel<<<grid_g, blkg, G2_SMEM>>>(x16 + 2 * ASEG, w16h + 2 * WW_, w16l + 2 * WW_, g_v_p, nullptr, nullptr, 0);

    dim3 grid_sc(36, 128);
    scores_hmma_kernel<<<grid_sc, blk, 4 * SBUF>>>(qh, ql, kh, kl, dist_p);

    dim3 grid_rs(1024, 128);
    rowstat_kernel<<<grid_rs, blk>>>(dist_p, rm_p, rl_p);

    dim3 grid_att(8, 128);
    att_fused_kernel<<<grid_att, blk>>>(dist_p, g_v_p, rm_p, rl_p, g_att_p);

    conv_a1_kernel<<<8192, blk>>>((const float4*)g_att_p, (uint32_t*)x16);
    gemm_fp16_kernel<<<grid_g, blkg, G2_SMEM>>>(x16, w16h + 3 * WW_, w16l + 3 * WW_, out, nullptr, nullptr, 1);
}

// round 12
// speedup vs baseline: 2.7883x; 1.1887x over previous
#include <cuda_runtime.h>
#include <cuda_bf16.h>
#include <cuda_fp16.h>
#include <math.h>
#include <stdint.h>

// Problem constants
#define S_   1024
#define B_   8
#define H_   1024
#define NH_  16
#define DK_  64
#define BH_  128
#define SB_  8192
#define OUT_ELEMS  (S_*B_*H_)
#define DIST_ELEMS (BH_*S_*S_)
#define WW_  (H_*H_)

// ---------------- scratch ----------------
__device__ float g_v[SB_ * H_];
__device__ float g_att[SB_ * H_];
__device__ float g_dist_fallback[DIST_ELEMS];
__device__ float g_rowm[BH_ * S_];
__device__ float g_rowl[BH_ * S_];
__device__ __half g_w16h[4 * WW_];
__device__ __half g_w16l[4 * WW_];
__device__ __half g_x16[3 * SB_ * H_];
__device__ __nv_bfloat16 g_qh[SB_ * H_];
__device__ __nv_bfloat16 g_ql[SB_ * H_];
__device__ __nv_bfloat16 g_kh[SB_ * H_];
__device__ __nv_bfloat16 g_kl[SB_ * H_];

__device__ __forceinline__ uint32_t smem_u32(const void* p) {
    uint32_t a;
    asm("{ .reg .u64 t; cvta.to.shared.u64 t, %1; cvt.u32.u64 %0, t; }"
        : "=r"(a) : "l"(p));
    return a;
}
__device__ __forceinline__ void cp_async16(uint32_t dst, const void* src) {
    asm volatile("cp.async.ca.shared.global [%0], [%1], 16;" :: "r"(dst), "l"(src));
}
#define CP_COMMIT() asm volatile("cp.async.commit_group;" ::: "memory")
#define CP_WAIT(N)  asm volatile("cp.async.wait_group %0;" :: "n"(N) : "memory")

#define LDM_X4(r, addr)                                                        \
    asm volatile("ldmatrix.sync.aligned.m8n8.x4.shared.b16 {%0,%1,%2,%3}, [%4];" \
                 : "=r"((r)[0]), "=r"((r)[1]), "=r"((r)[2]), "=r"((r)[3]) : "r"(addr))
#define LDM_X4_T(r, addr)                                                      \
    asm volatile("ldmatrix.sync.aligned.m8n8.x4.trans.shared.b16 {%0,%1,%2,%3}, [%4];" \
                 : "=r"((r)[0]), "=r"((r)[1]), "=r"((r)[2]), "=r"((r)[3]) : "r"(addr))

#define MMA_BF16(acc, a, b0, b1)                                               \
    asm volatile("mma.sync.aligned.m16n8k16.row.col.f32.bf16.bf16.f32 "        \
                 "{%0,%1,%2,%3}, {%4,%5,%6,%7}, {%8,%9}, {%0,%1,%2,%3};"       \
                 : "+f"((acc)[0]), "+f"((acc)[1]), "+f"((acc)[2]), "+f"((acc)[3]) \
                 : "r"((a)[0]), "r"((a)[1]), "r"((a)[2]), "r"((a)[3]),         \
                   "r"(b0), "r"(b1))
#define MMA_F16(acc, a, b0, b1)                                                \
    asm volatile("mma.sync.aligned.m16n8k16.row.col.f32.f16.f16.f32 "          \
                 "{%0,%1,%2,%3}, {%4,%5,%6,%7}, {%8,%9}, {%0,%1,%2,%3};"       \
                 : "+f"((acc)[0]), "+f"((acc)[1]), "+f"((acc)[2]), "+f"((acc)[3]) \
                 : "r"((a)[0]), "r"((a)[1]), "r"((a)[2]), "r"((a)[3]),         \
                   "r"(b0), "r"(b1))

__device__ __forceinline__ void split2(float x, float y,
                                       uint32_t& hi, uint32_t& lo) {
    __nv_bfloat162 h = __floats2bfloat162_rn(x, y);
    float rx = x - __bfloat162float(h.x);
    float ry = y - __bfloat162float(h.y);
    __nv_bfloat162 l = __floats2bfloat162_rn(rx, ry);
    hi = *(uint32_t*)&h;
    lo = *(uint32_t*)&l;
}
__device__ __forceinline__ void split2h(float x, float y,
                                        uint32_t& hi, uint32_t& lo) {
    __half2 h = __floats2half2_rn(x, y);
    float rx = x - __half2float(__low2half(h));
    float ry = y - __half2float(__high2half(h));
    __half2 l = __floats2half2_rn(rx, ry);
    hi = *(uint32_t*)&h;
    lo = *(uint32_t*)&l;
}

// ============================================================================
// conv kernels
// ============================================================================
__global__ void __launch_bounds__(256) conv_w4_kernel(
    const float4* __restrict__ W0, const float4* __restrict__ W1,
    const float4* __restrict__ W2, const float4* __restrict__ W3,
    uint32_t* __restrict__ hi, uint32_t* __restrict__ lo)
{
    int i = blockIdx.x * 256 + threadIdx.x;
    int mat = i >> 18, off = i & 262143;
    const float4* src = (mat == 0) ? W0 : (mat == 1) ? W1 : (mat == 2) ? W2 : W3;
    float4 v = src[off];
    uint32_t h0, l0, h1, l1;
    split2h(v.x, v.y, h0, l0);
    split2h(v.z, v.w, h1, l1);
    hi[2 * i] = h0; hi[2 * i + 1] = h1;
    lo[2 * i] = l0; lo[2 * i + 1] = l1;
}

__global__ void __launch_bounds__(256) conv_a3_kernel(
    const float4* __restrict__ X0, const float4* __restrict__ X1,
    const float4* __restrict__ X2, uint32_t* __restrict__ dst)
{
    int i = blockIdx.x * 256 + threadIdx.x;
    int mat = i >> 21, off = i & 2097151;
    const float4* src = (mat == 0) ? X0 : (mat == 1) ? X1 : X2;
    float4 v = src[off];
    __half2 h01 = __floats2half2_rn(v.x, v.y);
    __half2 h23 = __floats2half2_rn(v.z, v.w);
    dst[2 * i] = *(uint32_t*)&h01;
    dst[2 * i + 1] = *(uint32_t*)&h23;
}

__global__ void __launch_bounds__(256) conv_a1_kernel(
    const float4* __restrict__ X, uint32_t* __restrict__ dst)
{
    int i = blockIdx.x * 256 + threadIdx.x;
    float4 v = X[i];
    __half2 h01 = __floats2half2_rn(v.x, v.y);
    __half2 h23 = __floats2half2_rn(v.z, v.w);
    dst[2 * i] = *(uint32_t*)&h01;
    dst[2 * i + 1] = *(uint32_t*)&h23;
}

// ============================================================================
// fp16 2-term GEMM, 4 warps x (64x64): C = A @ W^T.
// gridDim.z==3 -> fused QKV (z selects A, W, and output); else single_mode.
// ============================================================================
#define ROWB 80
#define G2STAGE 30720
#define G2_SMEM (3 * G2STAGE)

__global__ void __launch_bounds__(128, 2) gemm_fp16_kernel(
    const __half* __restrict__ A16b, const __half* __restrict__ Whb,
    const __half* __restrict__ Wlb, float* __restrict__ C0,
    __nv_bfloat16* __restrict__ qh_, __nv_bfloat16* __restrict__ ql_,
    __nv_bfloat16* __restrict__ kh_, __nv_bfloat16* __restrict__ kl_,
    int smode)
{
    extern __shared__ char gsm[];
    const uint32_t s0 = smem_u32(gsm);

    const __half* A16 = A16b;
    const __half* Wh = Whb;
    const __half* Wl = Wlb;
    float* C = C0;
    __nv_bfloat16* Oh = nullptr;
    __nv_bfloat16* Ol = nullptr;
    int mode = smode;
    if (gridDim.z == 3) {
        int z = blockIdx.z;
        A16 += (size_t)z * ((size_t)SB_ * H_);
        Wh += (size_t)z * WW_;
        Wl += (size_t)z * WW_;
        if (z == 0)      { mode = 2; Oh = qh_; Ol = ql_; }
        else if (z == 1) { mode = 2; Oh = kh_; Ol = kl_; }
        else             { mode = 0; }
    }

    const int tid  = threadIdx.x;
    const int wid  = tid >> 5;
    const int lane = tid & 31;
    const int m0 = blockIdx.y * 128;
    const int n0 = blockIdx.x * 128;
    const int warp_m = (wid & 1) * 64;
    const int warp_n = (wid >> 1) * 64;

    float acc[4][8][4];
#pragma unroll
    for (int a = 0; a < 4; ++a)
#pragma unroll
        for (int b = 0; b < 8; ++b)
#pragma unroll
            for (int c = 0; c < 4; ++c) acc[a][b][c] = 0.f;

#define LOAD2(st, kt) do {                                                     \
    int kk_ = (kt) * 32;                                                       \
    const __half* ga_ = A16 + (size_t)m0 * 1024 + kk_;                         \
    const __half* gh_ = Wh + (size_t)n0 * 1024 + kk_;                          \
    const __half* gl_ = Wl + (size_t)n0 * 1024 + kk_;                          \
    uint32_t base_ = s0 + (st) * G2STAGE;                                      \
    _Pragma("unroll")                                                          \
    for (int l_ = 0; l_ < 4; ++l_) {                                           \
        int id_ = tid + 128 * l_;                                              \
        int row_ = id_ >> 2, c_ = id_ & 3;                                     \
        cp_async16(base_ + row_ * ROWB + c_ * 16,                              \
                   ga_ + (size_t)row_ * 1024 + c_ * 8);                        \
        cp_async16(base_ + 10240u + row_ * ROWB + c_ * 16,                     \
                   gh_ + (size_t)row_ * 1024 + c_ * 8);                        \
        cp_async16(base_ + 20480u + row_ * ROWB + c_ * 16,                     \
                   gl_ + (size_t)row_ * 1024 + c_ * 8);                        \
    }                                                                          \
    CP_COMMIT();                                                               \
} while (0)

    LOAD2(0, 0);
    LOAD2(1, 1);

    const uint32_t a_lane_row = warp_m + (lane & 15);
    const uint32_t a_lane_col = (lane >> 4) * 16;
    const uint32_t b_lane_row = warp_n + (lane & 7) + ((lane >> 4) << 3);
    const uint32_t b_lane_col = ((lane >> 3) & 1) * 16;

    for (int kt = 0; kt < 32; ++kt) {
        const int st = kt - (kt / 3) * 3;
        if (kt < 30) CP_WAIT(1); else CP_WAIT(0);
        __syncthreads();
        if (kt + 2 < 32) {
            int st2 = (kt + 2) - ((kt + 2) / 3) * 3;
            LOAD2(st2, kt + 2);
        }

        const uint32_t abase = s0 + st * G2STAGE;

#pragma unroll
        for (int k16 = 0; k16 < 2; ++k16) {
            uint32_t af[4][4];
#pragma unroll
            for (int fm = 0; fm < 4; ++fm)
                LDM_X4(af[fm], abase + (a_lane_row + fm * 16) * ROWB
                               + k16 * 32 + a_lane_col);
            uint32_t bf[8][2];
            // hi pass
#pragma unroll
            for (int fp = 0; fp < 4; ++fp) {
                uint32_t r[4];
                LDM_X4(r, abase + 10240u + (b_lane_row + fp * 16) * ROWB
                          + k16 * 32 + b_lane_col);
                bf[fp * 2][0] = r[0]; bf[fp * 2][1] = r[1];
                bf[fp * 2 + 1][0] = r[2]; bf[fp * 2 + 1][1] = r[3];
            }
#pragma unroll
            for (int fm = 0; fm < 4; ++fm)
#pragma unroll
                for (int fn = 0; fn < 8; ++fn)
                    MMA_F16(acc[fm][fn], af[fm], bf[fn][0], bf[fn][1]);
            // lo pass
#pragma unroll
            for (int fp = 0; fp < 4; ++fp) {
                uint32_t r[4];
                LDM_X4(r, abase + 20480u + (b_lane_row + fp * 16) * ROWB
                          + k16 * 32 + b_lane_col);
                bf[fp * 2][0] = r[0]; bf[fp * 2][1] = r[1];
                bf[fp * 2 + 1][0] = r[2]; bf[fp * 2 + 1][1] = r[3];
            }
#pragma unroll
            for (int fm = 0; fm < 4; ++fm)
#pragma unroll
                for (int fn = 0; fn < 8; ++fn)
                    MMA_F16(acc[fm][fn], af[fm], bf[fn][0], bf[fn][1]);
        }
    }

#pragma unroll
    for (int fm = 0; fm < 4; ++fm) {
#pragma unroll
        for (int half = 0; half < 2; ++half) {
            int m = m0 + warp_m + fm * 16 + (lane >> 2) + half * 8;
            if (mode == 2) {
                int s = m >> 3, b = m & 7;
#pragma unroll
                for (int fn = 0; fn < 8; ++fn) {
                    int col = n0 + warp_n + (lane & 3) * 2 + fn * 8;
                    int h = col >> 6, d = col & 63;
                    size_t addr = ((size_t)(h * 8 + b) * 1024 + s) * 64 + d;
                    uint32_t hi, lo;
                    split2(acc[fm][fn][half * 2], acc[fm][fn][half * 2 + 1], hi, lo);
                    *(uint32_t*)(Oh + addr) = hi;
                    *(uint32_t*)(Ol + addr) = lo;
                }
            } else {
                int orow = mode ? ((m & (S_ - 1)) * B_ + (m >> 10)) : m;
                float* cr = C + (size_t)orow * 1024 + n0 + warp_n + (lane & 3) * 2;
#pragma unroll
                for (int fn = 0; fn < 8; ++fn) {
                    float2 v = half ? make_float2(acc[fm][fn][2], acc[fm][fn][3])
                                    : make_float2(acc[fm][fn][0], acc[fm][fn][1]);
                    *(float2*)(cr + fn * 8) = v;
                }
            }
        }
    }
#undef LOAD2
}

// ============================================================================
// scores+rowstat fused: CTA owns row band ti (128 rows i) of one bb.
// K band resident in smem; Q tiles double-buffered over tj=0..ti.
// Writes raw scores to dist AND online (m, l) row stats -> rowm/rowl.
// ============================================================================
#define SROWB 144
#define SBUF  18432
#define QSTG  (2 * SBUF)
#define SCF_SMEM (2 * SBUF + 2 * QSTG)   // 110592

__global__ void __launch_bounds__(256, 2) scores_fused_kernel(
    const __nv_bfloat16* __restrict__ Qh, const __nv_bfloat16* __restrict__ Ql,
    const __nv_bfloat16* __restrict__ Kh, const __nv_bfloat16* __restrict__ Kl,
    float* __restrict__ dist, float* __restrict__ rowm,
    float* __restrict__ rowl)
{
    extern __shared__ char sm[];
    const uint32_t s0 = smem_u32(sm);
    const int ti = 7 - blockIdx.x;        // big bands first
    const int bb = blockIdx.y;

    const int tid  = threadIdx.x;
    const int wid  = tid >> 5;
    const int lane = tid & 31;
    const int warp_m = (wid & 3) * 32;    // i
    const int warp_n = (wid >> 2) * 64;   // j

    const size_t hb = (size_t)bb * 65536;

    // K band load (Kh -> 0, Kl -> SBUF)
#pragma unroll
    for (int l = 0; l < 4; ++l) {
        int id = tid + 256 * l;
        int row = id >> 3, c = id & 7;
        cp_async16(s0 + row * SROWB + c * 16,
                   Kh + hb + (size_t)(ti * 128 + row) * 64 + c * 8);
        cp_async16(s0 + SBUF + row * SROWB + c * 16,
                   Kl + hb + (size_t)(ti * 128 + row) * 64 + c * 8);
    }

#define QLOAD(st, tj) do {                                                     \
    uint32_t qb_ = s0 + 2 * SBUF + (st) * QSTG;                                \
    _Pragma("unroll")                                                          \
    for (int l_ = 0; l_ < 4; ++l_) {                                           \
        int id_ = tid + 256 * l_;                                              \
        int row_ = id_ >> 3, c_ = id_ & 7;                                     \
        cp_async16(qb_ + row_ * SROWB + c_ * 16,                               \
                   Qh + hb + (size_t)((tj) * 128 + row_) * 64 + c_ * 8);       \
        cp_async16(qb_ + SBUF + row_ * SROWB + c_ * 16,                        \
                   Ql + hb + (size_t)((tj) * 128 + row_) * 64 + c_ * 8);       \
    }                                                                          \
    CP_COMMIT();                                                               \
} while (0)

    QLOAD(0, 0);                   // group: K + Q0
    if (ti >= 1) QLOAD(1, 1);      // group: Q1

    // running stats per (fm, half): idx = fm*2 + half
    float s_m[4], s_l[4];
#pragma unroll
    for (int x = 0; x < 4; ++x) { s_m[x] = -1e30f; s_l[x] = 0.f; }

    const uint32_t a_lane_row = warp_m + (lane & 15);
    const uint32_t a_lane_col = (lane >> 4) * 16;
    const uint32_t b_lane_row = warp_n + (lane & 7) + ((lane >> 4) << 3);
    const uint32_t b_lane_col = ((lane >> 3) & 1) * 16;

    float* out = dist + ((size_t)bb << 20);

    for (int tj = 0; tj <= ti; ++tj) {
        const int st = tj & 1;
        if (tj < ti) CP_WAIT(1); else CP_WAIT(0);
        __syncthreads();

        const uint32_t kh_b = s0;
        const uint32_t kl_b = s0 + SBUF;
        const uint32_t qh_b = s0 + 2 * SBUF + st * QSTG;
        const uint32_t ql_b = qh_b + SBUF;

        float acc[2][8][4];
#pragma unroll
        for (int a = 0; a < 2; ++a)
#pragma unroll
            for (int b = 0; b < 8; ++b)
#pragma unroll
                for (int c = 0; c < 4; ++c) acc[a][b][c] = 0.f;

        const uint32_t abases[3] = {kh_b, kh_b, kl_b};
        const uint32_t bbases[3] = {qh_b, ql_b, qh_b};

#pragma unroll
        for (int t = 0; t < 3; ++t) {
#pragma unroll
            for (int k16 = 0; k16 < 4; ++k16) {
                uint32_t af[2][4];
#pragma unroll
                for (int fm = 0; fm < 2; ++fm)
                    LDM_X4(af[fm], abases[t] + (a_lane_row + fm * 16) * SROWB
                                   + k16 * 32 + a_lane_col);
                uint32_t bfr[8][2];
#pragma unroll
                for (int fp = 0; fp < 4; ++fp) {
                    uint32_t r[4];
                    LDM_X4(r, bbases[t] + (b_lane_row + fp * 16) * SROWB
                              + k16 * 32 + b_lane_col);
                    bfr[fp * 2][0] = r[0]; bfr[fp * 2][1] = r[1];
                    bfr[fp * 2 + 1][0] = r[2]; bfr[fp * 2 + 1][1] = r[3];
                }
#pragma unroll
                for (int fm = 0; fm < 2; ++fm)
#pragma unroll
                    for (int fn = 0; fn < 8; ++fn)
                        MMA_BF16(acc[fm][fn], af[fm], bfr[fn][0], bfr[fn][1]);
            }
        }

        // epilogue: write raw + update stats
        const bool diag = (tj == ti);
#pragma unroll
        for (int fm = 0; fm < 2; ++fm)
#pragma unroll
            for (int half = 0; half < 2; ++half) {
                const int idx = fm * 2 + half;
                const int ig = ti * 128 + warp_m + fm * 16 + (lane >> 2) + half * 8;
                float* orow = out + (size_t)ig * 1024 + tj * 128 + warp_n
                              + (lane & 3) * 2;
                const int jbase = tj * 128 + warp_n + (lane & 3) * 2;
                float tmax = -1e30f;
#pragma unroll
                for (int fn = 0; fn < 8; ++fn) {
                    float v0 = acc[fm][fn][half * 2]     * 0.125f;
                    float v1 = acc[fm][fn][half * 2 + 1] * 0.125f;
                    *(float2*)(orow + fn * 8) = make_float2(v0, v1);
                    if (diag) {
                        if (jbase + fn * 8 <= ig)     tmax = fmaxf(tmax, v0);
                        if (jbase + fn * 8 + 1 <= ig) tmax = fmaxf(tmax, v1);
                    } else {
                        tmax = fmaxf(tmax, fmaxf(v0, v1));
                    }
                }
                tmax = fmaxf(tmax, __shfl_xor_sync(0xffffffffu, tmax, 1));
                tmax = fmaxf(tmax, __shfl_xor_sync(0xffffffffu, tmax, 2));
                float m_new = fmaxf(s_m[idx], tmax);
                float sum = 0.f;
#pragma unroll
                for (int fn = 0; fn < 8; ++fn) {
                    float v0 = acc[fm][fn][half * 2]     * 0.125f;
                    float v1 = acc[fm][fn][half * 2 + 1] * 0.125f;
                    if (diag) {
                        if (jbase + fn * 8 <= ig)     sum += __expf(v0 - m_new);
                        if (jbase + fn * 8 + 1 <= ig) sum += __expf(v1 - m_new);
                    } else {
                        sum += __expf(v0 - m_new) + __expf(v1 - m_new);
                    }
                }
                sum += __shfl_xor_sync(0xffffffffu, sum, 1);
                sum += __shfl_xor_sync(0xffffffffu, sum, 2);
                s_l[idx] = s_l[idx] * __expf(s_m[idx] - m_new) + sum;
                s_m[idx] = m_new;
            }

        __syncthreads();
        if (tj + 2 <= ti) QLOAD(st, tj + 2);
    }
#undef QLOAD

    // cross-warp combine (warp_n 0 <-> 1), then write rowm/rowl
    __syncthreads();
    float* comb = (float*)sm;   // [wid][lane>>2][idx][2] : 8*8*4*2 floats
    if ((lane & 3) == 0) {
#pragma unroll
        for (int idx = 0; idx < 4; ++idx) {
            int off = ((wid * 8 + (lane >> 2)) * 4 + idx) * 2;
            comb[off]     = s_m[idx];
            comb[off + 1] = s_l[idx];
        }
    }
    __syncthreads();
    if (wid < 4 && (lane & 3) == 0) {
#pragma unroll
        for (int idx = 0; idx < 4; ++idx) {
            int o0 = ((wid * 8 + (lane >> 2)) * 4 + idx) * 2;
            int o1 = (((wid + 4) * 8 + (lane >> 2)) * 4 + idx) * 2;
            float m0 = comb[o0], l0 = comb[o0 + 1];
            float m1 = comb[o1], l1 = comb[o1 + 1];
            float m = fmaxf(m0, m1);
            float l = l0 * __expf(m0 - m) + l1 * __expf(m1 - m);
            int ig = ti * 128 + warp_m + (idx >> 1) * 16 + (lane >> 2)
                     + (idx & 1) * 8;
            rowm[(bb << 10) + ig] = m;
            rowl[(bb << 10) + ig] = 1.f / l;
        }
    }
}

// ============================================================================
// att fused (fp16 2-term)
// ============================================================================
__global__ void __launch_bounds__(256, 2) att_fused_kernel(
    float* __restrict__ dist, const float* __restrict__ Vp,
    const float* __restrict__ rowm, const float* __restrict__ rowl,
    float* __restrict__ att)
{
    __shared__ __half Ps[32][136];
    __shared__ __half Vs[2][32][72];

    const int jt = blockIdx.x;
    const int bb = blockIdx.y;
    const int h = bb >> 3;
    const int b = bb & 7;
    const int j0 = jt * 128;

    const int tid  = threadIdx.x;
    const int wid  = tid >> 5;
    const int lane = tid & 31;
    const int warp_m = (wid & 3) * 32;
    const int warp_n = (wid >> 2) * 32;

    float* dbase = dist + ((size_t)bb << 20);
    const float* vbase = Vp + (size_t)b * 1024 + (size_t)h * 64;
    const float* mrow = rowm + (bb << 10);
    const float* lrow = rowl + (bb << 10);

    const float4 z4 = make_float4(0.f, 0.f, 0.f, 0.f);
    for (int it = 0; it < jt; ++it) {
#pragma unroll
        for (int q = 0; q < 16; ++q) {
            int id = tid + 256 * q;
            int r = id >> 5, c4 = id & 31;
            *(float4*)(dbase + (size_t)(it * 128 + r) * 1024 + j0 + c4 * 4) = z4;
        }
    }

    const uint32_t PB = smem_u32(&Ps[0][0]);
    const uint32_t VhB = smem_u32(&Vs[0][0][0]);
    const uint32_t VlB = smem_u32(&Vs[1][0][0]);

    float acc[2][4][4];
#pragma unroll
    for (int a = 0; a < 2; ++a)
#pragma unroll
        for (int c = 0; c < 4; ++c)
#pragma unroll
            for (int e = 0; e < 4; ++e) acc[a][c][e] = 0.f;

    const int nsteps = (1024 - j0) / 32;

    for (int step = 0; step < nsteps; ++step) {
        const int i0 = j0 + step * 32;

#pragma unroll
        for (int q = 0; q < 4; ++q) {
            int id = tid + 256 * q;
            int r = id >> 5, c4 = id & 31;
            const int iv = i0 + r;
            float4 s = *(const float4*)(dbase + (size_t)iv * 1024 + j0 + c4 * 4);
            float m  = __ldg(mrow + iv);
            float il = __ldg(lrow + iv);
            int jv = j0 + c4 * 4;
            float p0 = (jv + 0 <= iv) ? __expf(s.x - m) * il : 0.f;
            float p1 = (jv + 1 <= iv) ? __expf(s.y - m) * il : 0.f;
            float p2 = (jv + 2 <= iv) ? __expf(s.z - m) * il : 0.f;
            float p3 = (jv + 3 <= iv) ? __expf(s.w - m) * il : 0.f;
            *(float4*)(dbase + (size_t)iv * 1024 + j0 + c4 * 4)
                = make_float4(p0, p1, p2, p3);
            __half2 h01 = __floats2half2_rn(p0, p1);
            __half2 h23 = __floats2half2_rn(p2, p3);
            *(uint2*)(&Ps[r][c4 * 4]) = make_uint2(*(uint32_t*)&h01, *(uint32_t*)&h23);
        }
#pragma unroll
        for (int q = 0; q < 2; ++q) {
            int id = tid + 256 * q;
            int r = id >> 4, c4 = id & 15;
            float4 v = *(const float4*)(vbase + (size_t)(i0 + r) * 8192 + c4 * 4);
            uint32_t h0, l0, h1, l1;
            split2h(v.x, v.y, h0, l0);
            split2h(v.z, v.w, h1, l1);
            *(uint2*)(&Vs[0][r][c4 * 4]) = make_uint2(h0, h1);
            *(uint2*)(&Vs[1][r][c4 * 4]) = make_uint2(l0, l1);
        }
        __syncthreads();

#pragma unroll
        for (int k16 = 0; k16 < 2; ++k16) {
            const uint32_t arow = k16 * 16 + ((lane >> 4) << 3) + (lane & 7);
            uint32_t af[2][4];
#pragma unroll
            for (int fm = 0; fm < 2; ++fm) {
                const uint32_t acolb =
                    (warp_m + fm * 16 + (((lane >> 3) & 1) << 3)) * 2;
                LDM_X4_T(af[fm], PB + arow * 272 + acolb);
            }
            const uint32_t brow = k16 * 16 + (((lane >> 3) & 1) << 3) + (lane & 7);
            uint32_t bH[4][2], bL[4][2];
#pragma unroll
            for (int fp = 0; fp < 2; ++fp) {
                const uint32_t bcolb =
                    (warp_n + fp * 16 + ((lane >> 4) << 3)) * 2;
                uint32_t r[4];
                LDM_X4_T(r, VhB + brow * 144 + bcolb);
                bH[fp * 2][0] = r[0]; bH[fp * 2][1] = r[1];
                bH[fp * 2 + 1][0] = r[2]; bH[fp * 2 + 1][1] = r[3];
                LDM_X4_T(r, VlB + brow * 144 + bcolb);
                bL[fp * 2][0] = r[0]; bL[fp * 2][1] = r[1];
                bL[fp * 2 + 1][0] = r[2]; bL[fp * 2 + 1][1] = r[3];
            }
#pragma unroll
            for (int fm = 0; fm < 2; ++fm)
#pragma unroll
                for (int fn = 0; fn < 4; ++fn) {
                    MMA_F16(acc[fm][fn], af[fm], bH[fn][0], bH[fn][1]);
                    MMA_F16(acc[fm][fn], af[fm], bL[fn][0], bL[fn][1]);
                }
        }
        __syncthreads();
    }

#pragma unroll
    for (int fm = 0; fm < 2; ++fm)
#pragma unroll
        for (int half = 0; half < 2; ++half) {
            int j = j0 + warp_m + fm * 16 + (lane >> 2) + half * 8;
            float* cr = att + ((size_t)b * 1024 + j) * 1024 + h * 64
                        + warp_n + (lane & 3) * 2;
#pragma unroll
            for (int fn = 0; fn < 4; ++fn) {
                float2 v = half ? make_float2(acc[fm][fn][2], acc[fm][fn][3])
                                : make_float2(acc[fm][fn][0], acc[fm][fn][1]);
                *(float2*)(cr + fn * 8) = v;
            }
        }
}

// ---------------------------------------------------------------------------
extern "C" void kernel_launch(void* const* d_in, const int* in_sizes, int n_in,
                              void* d_out, int out_size)
{
    const float* value = (const float*)d_in[0];
    const float* key   = (const float*)d_in[1];
    const float* query = (const float*)d_in[2];
    const float* Wq    = (const float*)d_in[3];
    const float* Wk    = (const float*)d_in[4];
    const float* Wv    = (const float*)d_in[5];
    const float* Wo    = (const float*)d_in[6];
    float* out = (float*)d_out;

    float* g_v_p;   cudaGetSymbolAddress((void**)&g_v_p,   g_v);
    float* g_att_p; cudaGetSymbolAddress((void**)&g_att_p, g_att);
    float* rm_p;    cudaGetSymbolAddress((void**)&rm_p,    g_rowm);
    float* rl_p;    cudaGetSymbolAddress((void**)&rl_p,    g_rowl);
    __half *w16h, *w16l, *x16;
    cudaGetSymbolAddress((void**)&w16h, g_w16h);
    cudaGetSymbolAddress((void**)&w16l, g_w16l);
    cudaGetSymbolAddress((void**)&x16,  g_x16);
    __nv_bfloat16 *qh, *ql, *kh, *kl;
    cudaGetSymbolAddress((void**)&qh, g_qh);
    cudaGetSymbolAddress((void**)&ql, g_ql);
    cudaGetSymbolAddress((void**)&kh, g_kh);
    cudaGetSymbolAddress((void**)&kl, g_kl);

    float* dist_p;
    if ((long long)out_size == (long long)OUT_ELEMS + (long long)DIST_ELEMS) {
        dist_p = out + OUT_ELEMS;
    } else {
        cudaGetSymbolAddress((void**)&dist_p, g_dist_fallback);
    }

    static int attr_done = 0;
    if (!attr_done) {
        cudaFuncSetAttribute(gemm_fp16_kernel,
                             cudaFuncAttributeMaxDynamicSharedMemorySize, G2_SMEM);
        cudaFuncSetAttribute(scores_fused_kernel,
                             cudaFuncAttributeMaxDynamicSharedMemorySize, SCF_SMEM);
        attr_done = 1;
    }

    dim3 blk(256);
    dim3 blkg(128);
    dim3 grid_g3(8, 64, 3);
    dim3 grid_g(8, 64, 1);

    conv_w4_kernel<<<4096, blk>>>((const float4*)Wq, (const float4*)Wk,
                                  (const float4*)Wv, (const float4*)Wo,
                                  (uint32_t*)w16h, (uint32_t*)w16l);
    conv_a3_kernel<<<24576, blk>>>((const float4*)query, (const float4*)key,
                                   (const float4*)value, (uint32_t*)x16);

    // fused QKV projections (z: 0=Q, 1=K, 2=V)
    gemm_fp16_kernel<<<grid_g3, blkg, G2_SMEM>>>(x16, w16h, w16l, g_v_p,
                                                 qh, ql, kh, kl, 0);

    // fused scores + row stats
    dim3 grid_sc(8, 128);
    scores_fused_kernel<<<grid_sc, blk, SCF_SMEM>>>(qh, ql, kh, kl,
                                                    dist_p, rm_p, rl_p);

    dim3 grid_att(8, 128);
    att_fused_kernel<<<grid_att, blk>>>(dist_p, g_v_p, rm_p, rl_p, g_att_p);

    conv_a1_kernel<<<8192, blk>>>((const float4*)g_att_p, (uint32_t*)x16);
    gemm_fp16_kernel<<<grid_g, blkg, G2_SMEM>>>(x16, w16h + 3 * WW_,
                                                w16l + 3 * WW_, out,
                                                nullptr, nullptr, nullptr,
                                                nullptr, 1);
}

// round 13
// speedup vs baseline: 2.9935x; 1.0736x over previous
#include <cuda_runtime.h>
#include <cuda_bf16.h>
#include <cuda_fp16.h>
#include <math.h>
#include <stdint.h>

// Problem constants
#define S_   1024
#define B_   8
#define H_   1024
#define NH_  16
#define DK_  64
#define BH_  128
#define SB_  8192
#define OUT_ELEMS  (S_*B_*H_)
#define DIST_ELEMS (BH_*S_*S_)
#define WW_  (H_*H_)

// ---------------- scratch ----------------
__device__ float g_v[SB_ * H_];
__device__ float g_att[SB_ * H_];
__device__ float g_dist_fallback[DIST_ELEMS];
__device__ __half g_w16h[4 * WW_];
__device__ __half g_w16l[4 * WW_];
__device__ __half g_x16[3 * SB_ * H_];
__device__ __nv_bfloat16 g_qh[SB_ * H_];
__device__ __nv_bfloat16 g_ql[SB_ * H_];
__device__ __nv_bfloat16 g_kh[SB_ * H_];
__device__ __nv_bfloat16 g_kl[SB_ * H_];

__device__ __forceinline__ uint32_t smem_u32(const void* p) {
    uint32_t a;
    asm("{ .reg .u64 t; cvta.to.shared.u64 t, %1; cvt.u32.u64 %0, t; }"
        : "=r"(a) : "l"(p));
    return a;
}
__device__ __forceinline__ void cp_async16(uint32_t dst, const void* src) {
    asm volatile("cp.async.ca.shared.global [%0], [%1], 16;" :: "r"(dst), "l"(src));
}
#define CP_COMMIT() asm volatile("cp.async.commit_group;" ::: "memory")
#define CP_WAIT(N)  asm volatile("cp.async.wait_group %0;" :: "n"(N) : "memory")

#define LDM_X4(r, addr)                                                        \
    asm volatile("ldmatrix.sync.aligned.m8n8.x4.shared.b16 {%0,%1,%2,%3}, [%4];" \
                 : "=r"((r)[0]), "=r"((r)[1]), "=r"((r)[2]), "=r"((r)[3]) : "r"(addr))
#define LDM_X4_T(r, addr)                                                      \
    asm volatile("ldmatrix.sync.aligned.m8n8.x4.trans.shared.b16 {%0,%1,%2,%3}, [%4];" \
                 : "=r"((r)[0]), "=r"((r)[1]), "=r"((r)[2]), "=r"((r)[3]) : "r"(addr))

#define MMA_BF16(acc, a, b0, b1)                                               \
    asm volatile("mma.sync.aligned.m16n8k16.row.col.f32.bf16.bf16.f32 "        \
                 "{%0,%1,%2,%3}, {%4,%5,%6,%7}, {%8,%9}, {%0,%1,%2,%3};"       \
                 : "+f"((acc)[0]), "+f"((acc)[1]), "+f"((acc)[2]), "+f"((acc)[3]) \
                 : "r"((a)[0]), "r"((a)[1]), "r"((a)[2]), "r"((a)[3]),         \
                   "r"(b0), "r"(b1))
#define MMA_F16(acc, a, b0, b1)                                                \
    asm volatile("mma.sync.aligned.m16n8k16.row.col.f32.f16.f16.f32 "          \
                 "{%0,%1,%2,%3}, {%4,%5,%6,%7}, {%8,%9}, {%0,%1,%2,%3};"       \
                 : "+f"((acc)[0]), "+f"((acc)[1]), "+f"((acc)[2]), "+f"((acc)[3]) \
                 : "r"((a)[0]), "r"((a)[1]), "r"((a)[2]), "r"((a)[3]),         \
                   "r"(b0), "r"(b1))

__device__ __forceinline__ void split2(float x, float y,
                                       uint32_t& hi, uint32_t& lo) {
    __nv_bfloat162 h = __floats2bfloat162_rn(x, y);
    float rx = x - __bfloat162float(h.x);
    float ry = y - __bfloat162float(h.y);
    __nv_bfloat162 l = __floats2bfloat162_rn(rx, ry);
    hi = *(uint32_t*)&h;
    lo = *(uint32_t*)&l;
}
__device__ __forceinline__ void split2h(float x, float y,
                                        uint32_t& hi, uint32_t& lo) {
    __half2 h = __floats2half2_rn(x, y);
    float rx = x - __half2float(__low2half(h));
    float ry = y - __half2float(__high2half(h));
    __half2 l = __floats2half2_rn(rx, ry);
    hi = *(uint32_t*)&h;
    lo = *(uint32_t*)&l;
}

// ============================================================================
// conv kernels
// ============================================================================
__global__ void __launch_bounds__(256) conv_w4_kernel(
    const float4* __restrict__ W0, const float4* __restrict__ W1,
    const float4* __restrict__ W2, const float4* __restrict__ W3,
    uint32_t* __restrict__ hi, uint32_t* __restrict__ lo)
{
    int i = blockIdx.x * 256 + threadIdx.x;
    int mat = i >> 18, off = i & 262143;
    const float4* src = (mat == 0) ? W0 : (mat == 1) ? W1 : (mat == 2) ? W2 : W3;
    float4 v = src[off];
    uint32_t h0, l0, h1, l1;
    split2h(v.x, v.y, h0, l0);
    split2h(v.z, v.w, h1, l1);
    hi[2 * i] = h0; hi[2 * i + 1] = h1;
    lo[2 * i] = l0; lo[2 * i + 1] = l1;
}

__global__ void __launch_bounds__(256) conv_a3_kernel(
    const float4* __restrict__ X0, const float4* __restrict__ X1,
    const float4* __restrict__ X2, uint32_t* __restrict__ dst)
{
    int i = blockIdx.x * 256 + threadIdx.x;
    int mat = i >> 21, off = i & 2097151;
    const float4* src = (mat == 0) ? X0 : (mat == 1) ? X1 : X2;
    float4 v = src[off];
    __half2 h01 = __floats2half2_rn(v.x, v.y);
    __half2 h23 = __floats2half2_rn(v.z, v.w);
    dst[2 * i] = *(uint32_t*)&h01;
    dst[2 * i + 1] = *(uint32_t*)&h23;
}

__global__ void __launch_bounds__(256) conv_a1_kernel(
    const float4* __restrict__ X, uint32_t* __restrict__ dst)
{
    int i = blockIdx.x * 256 + threadIdx.x;
    float4 v = X[i];
    __half2 h01 = __floats2half2_rn(v.x, v.y);
    __half2 h23 = __floats2half2_rn(v.z, v.w);
    dst[2 * i] = *(uint32_t*)&h01;
    dst[2 * i + 1] = *(uint32_t*)&h23;
}

// ============================================================================
// fp16 2-term GEMM, 4 warps x (64x64): C = A @ W^T.
// gridDim.z==2 -> fused QK (z=0: Q -> qh/ql, z=1: K -> kh/kl); else smode.
// ============================================================================
#define ROWB 80
#define G2STAGE 30720
#define G2_SMEM (3 * G2STAGE)

__global__ void __launch_bounds__(128, 2) gemm_fp16_kernel(
    const __half* __restrict__ A16b, const __half* __restrict__ Whb,
    const __half* __restrict__ Wlb, float* __restrict__ C0,
    __nv_bfloat16* __restrict__ qh_, __nv_bfloat16* __restrict__ ql_,
    __nv_bfloat16* __restrict__ kh_, __nv_bfloat16* __restrict__ kl_,
    int smode)
{
    extern __shared__ char gsm[];
    const uint32_t s0 = smem_u32(gsm);

    const __half* A16 = A16b;
    const __half* Wh = Whb;
    const __half* Wl = Wlb;
    float* C = C0;
    __nv_bfloat16* Oh = nullptr;
    __nv_bfloat16* Ol = nullptr;
    int mode = smode;
    if (gridDim.z == 2) {
        int z = blockIdx.z;
        A16 += (size_t)z * ((size_t)SB_ * H_);
        Wh += (size_t)z * WW_;
        Wl += (size_t)z * WW_;
        mode = 2;
        if (z == 0) { Oh = qh_; Ol = ql_; }
        else        { Oh = kh_; Ol = kl_; }
    }

    const int tid  = threadIdx.x;
    const int wid  = tid >> 5;
    const int lane = tid & 31;
    const int m0 = blockIdx.y * 128;
    const int n0 = blockIdx.x * 128;
    const int warp_m = (wid & 1) * 64;
    const int warp_n = (wid >> 1) * 64;

    float acc[4][8][4];
#pragma unroll
    for (int a = 0; a < 4; ++a)
#pragma unroll
        for (int b = 0; b < 8; ++b)
#pragma unroll
            for (int c = 0; c < 4; ++c) acc[a][b][c] = 0.f;

#define LOAD2(st, kt) do {                                                     \
    int kk_ = (kt) * 32;                                                       \
    const __half* ga_ = A16 + (size_t)m0 * 1024 + kk_;                         \
    const __half* gh_ = Wh + (size_t)n0 * 1024 + kk_;                          \
    const __half* gl_ = Wl + (size_t)n0 * 1024 + kk_;                          \
    uint32_t base_ = s0 + (st) * G2STAGE;                                      \
    _Pragma("unroll")                                                          \
    for (int l_ = 0; l_ < 4; ++l_) {                                           \
        int id_ = tid + 128 * l_;                                              \
        int row_ = id_ >> 2, c_ = id_ & 3;                                     \
        cp_async16(base_ + row_ * ROWB + c_ * 16,                              \
                   ga_ + (size_t)row_ * 1024 + c_ * 8);                        \
        cp_async16(base_ + 10240u + row_ * ROWB + c_ * 16,                     \
                   gh_ + (size_t)row_ * 1024 + c_ * 8);                        \
        cp_async16(base_ + 20480u + row_ * ROWB + c_ * 16,                     \
                   gl_ + (size_t)row_ * 1024 + c_ * 8);                        \
    }                                                                          \
    CP_COMMIT();                                                               \
} while (0)

    LOAD2(0, 0);
    LOAD2(1, 1);

    const uint32_t a_lane_row = warp_m + (lane & 15);
    const uint32_t a_lane_col = (lane >> 4) * 16;
    const uint32_t b_lane_row = warp_n + (lane & 7) + ((lane >> 4) << 3);
    const uint32_t b_lane_col = ((lane >> 3) & 1) * 16;

    for (int kt = 0; kt < 32; ++kt) {
        const int st = kt - (kt / 3) * 3;
        if (kt < 30) CP_WAIT(1); else CP_WAIT(0);
        __syncthreads();
        if (kt + 2 < 32) {
            int st2 = (kt + 2) - ((kt + 2) / 3) * 3;
            LOAD2(st2, kt + 2);
        }

        const uint32_t abase = s0 + st * G2STAGE;

#pragma unroll
        for (int k16 = 0; k16 < 2; ++k16) {
            uint32_t af[4][4];
#pragma unroll
            for (int fm = 0; fm < 4; ++fm)
                LDM_X4(af[fm], abase + (a_lane_row + fm * 16) * ROWB
                               + k16 * 32 + a_lane_col);
            uint32_t bf[8][2];
#pragma unroll
            for (int fp = 0; fp < 4; ++fp) {
                uint32_t r[4];
                LDM_X4(r, abase + 10240u + (b_lane_row + fp * 16) * ROWB
                          + k16 * 32 + b_lane_col);
                bf[fp * 2][0] = r[0]; bf[fp * 2][1] = r[1];
                bf[fp * 2 + 1][0] = r[2]; bf[fp * 2 + 1][1] = r[3];
            }
#pragma unroll
            for (int fm = 0; fm < 4; ++fm)
#pragma unroll
                for (int fn = 0; fn < 8; ++fn)
                    MMA_F16(acc[fm][fn], af[fm], bf[fn][0], bf[fn][1]);
#pragma unroll
            for (int fp = 0; fp < 4; ++fp) {
                uint32_t r[4];
                LDM_X4(r, abase + 20480u + (b_lane_row + fp * 16) * ROWB
                          + k16 * 32 + b_lane_col);
                bf[fp * 2][0] = r[0]; bf[fp * 2][1] = r[1];
                bf[fp * 2 + 1][0] = r[2]; bf[fp * 2 + 1][1] = r[3];
            }
#pragma unroll
            for (int fm = 0; fm < 4; ++fm)
#pragma unroll
                for (int fn = 0; fn < 8; ++fn)
                    MMA_F16(acc[fm][fn], af[fm], bf[fn][0], bf[fn][1]);
        }
    }

#pragma unroll
    for (int fm = 0; fm < 4; ++fm) {
#pragma unroll
        for (int half = 0; half < 2; ++half) {
            int m = m0 + warp_m + fm * 16 + (lane >> 2) + half * 8;
            if (mode == 2) {
                int s = m >> 3, b = m & 7;
#pragma unroll
                for (int fn = 0; fn < 8; ++fn) {
                    int col = n0 + warp_n + (lane & 3) * 2 + fn * 8;
                    int h = col >> 6, d = col & 63;
                    size_t addr = ((size_t)(h * 8 + b) * 1024 + s) * 64 + d;
                    uint32_t hi, lo;
                    split2(acc[fm][fn][half * 2], acc[fm][fn][half * 2 + 1], hi, lo);
                    *(uint32_t*)(Oh + addr) = hi;
                    *(uint32_t*)(Ol + addr) = lo;
                }
            } else {
                int orow = mode ? ((m & (S_ - 1)) * B_ + (m >> 10)) : m;
                float* cr = C + (size_t)orow * 1024 + n0 + warp_n + (lane & 3) * 2;
#pragma unroll
                for (int fn = 0; fn < 8; ++fn) {
                    float2 v = half ? make_float2(acc[fm][fn][2], acc[fm][fn][3])
                                    : make_float2(acc[fm][fn][0], acc[fm][fn][1]);
                    *(float2*)(cr + fn * 8) = v;
                }
            }
        }
    }
#undef LOAD2
}

// ============================================================================
// scores two-pass fused: CTA owns row band ti of one bb.
// Pass 1: MMA all tiles, online (m, l) stats in regs (no global writes).
// Combine stats in smem. Pass 2: recompute tiles, write normalized p to dist
// (masked zeros on diag), plus zero-fill the row band's upper tiles.
// ============================================================================
#define SROWB 144
#define SBUF  18432
#define QSTG  (2 * SBUF)
#define SCF_SMEM (2 * SBUF + 2 * QSTG)   // 110592

__global__ void __launch_bounds__(256, 2) scores_fused_kernel(
    const __nv_bfloat16* __restrict__ Qh, const __nv_bfloat16* __restrict__ Ql,
    const __nv_bfloat16* __restrict__ Kh, const __nv_bfloat16* __restrict__ Kl,
    float* __restrict__ dist)
{
    extern __shared__ char sm[];
    __shared__ float rowstats[256];      // [0:128) m, [128:256) invl
    __shared__ float comb[8 * 8 * 4 * 2];
    const uint32_t s0 = smem_u32(sm);
    const int ti = 7 - blockIdx.x;
    const int bb = blockIdx.y;

    const int tid  = threadIdx.x;
    const int wid  = tid >> 5;
    const int lane = tid & 31;
    const int warp_m = (wid & 3) * 32;    // i
    const int warp_n = (wid >> 2) * 64;   // j

    const size_t hb = (size_t)bb * 65536;
    float* out = dist + ((size_t)bb << 20);

    // K band load (resident both passes)
#pragma unroll
    for (int l = 0; l < 4; ++l) {
        int id = tid + 256 * l;
        int row = id >> 3, c = id & 7;
        cp_async16(s0 + row * SROWB + c * 16,
                   Kh + hb + (size_t)(ti * 128 + row) * 64 + c * 8);
        cp_async16(s0 + SBUF + row * SROWB + c * 16,
                   Kl + hb + (size_t)(ti * 128 + row) * 64 + c * 8);
    }

#define QLOAD(st, tj) do {                                                     \
    uint32_t qb_ = s0 + 2 * SBUF + (st) * QSTG;                                \
    _Pragma("unroll")                                                          \
    for (int l_ = 0; l_ < 4; ++l_) {                                           \
        int id_ = tid + 256 * l_;                                              \
        int row_ = id_ >> 3, c_ = id_ & 7;                                     \
        cp_async16(qb_ + row_ * SROWB + c_ * 16,                               \
                   Qh + hb + (size_t)((tj) * 128 + row_) * 64 + c_ * 8);       \
        cp_async16(qb_ + SBUF + row_ * SROWB + c_ * 16,                        \
                   Ql + hb + (size_t)((tj) * 128 + row_) * 64 + c_ * 8);       \
    }                                                                          \
    CP_COMMIT();                                                               \
} while (0)

#define TILE_MMA(acc_)                                                         \
    do {                                                                       \
        const uint32_t kh_b = s0;                                              \
        const uint32_t kl_b = s0 + SBUF;                                       \
        const uint32_t qh_b = s0 + 2 * SBUF + st * QSTG;                       \
        const uint32_t ql_b = qh_b + SBUF;                                     \
        const uint32_t abases[3] = {kh_b, kh_b, kl_b};                         \
        const uint32_t bbases[3] = {qh_b, ql_b, qh_b};                         \
        _Pragma("unroll")                                                      \
        for (int t = 0; t < 3; ++t) {                                          \
            _Pragma("unroll")                                                  \
            for (int k16 = 0; k16 < 4; ++k16) {                                \
                uint32_t af[2][4];                                             \
                _Pragma("unroll")                                              \
                for (int fm = 0; fm < 2; ++fm)                                 \
                    LDM_X4(af[fm], abases[t] + (a_lane_row + fm * 16) * SROWB  \
                                   + k16 * 32 + a_lane_col);                   \
                uint32_t bfr[8][2];                                            \
                _Pragma("unroll")                                              \
                for (int fp = 0; fp < 4; ++fp) {                               \
                    uint32_t r[4];                                             \
                    LDM_X4(r, bbases[t] + (b_lane_row + fp * 16) * SROWB       \
                              + k16 * 32 + b_lane_col);                        \
                    bfr[fp * 2][0] = r[0]; bfr[fp * 2][1] = r[1];              \
                    bfr[fp * 2 + 1][0] = r[2]; bfr[fp * 2 + 1][1] = r[3];      \
                }                                                              \
                _Pragma("unroll")                                              \
                for (int fm = 0; fm < 2; ++fm)                                 \
                    _Pragma("unroll")                                          \
                    for (int fn = 0; fn < 8; ++fn)                             \
                        MMA_BF16(acc_[fm][fn], af[fm], bfr[fn][0], bfr[fn][1]);\
            }                                                                  \
        }                                                                      \
    } while (0)

    const uint32_t a_lane_row = warp_m + (lane & 15);
    const uint32_t a_lane_col = (lane >> 4) * 16;
    const uint32_t b_lane_row = warp_n + (lane & 7) + ((lane >> 4) << 3);
    const uint32_t b_lane_col = ((lane >> 3) & 1) * 16;

    // ---------------- PASS 1: stats only ----------------
    QLOAD(0, 0);
    if (ti >= 1) QLOAD(1, 1);

    float s_m[4], s_l[4];
#pragma unroll
    for (int x = 0; x < 4; ++x) { s_m[x] = -1e30f; s_l[x] = 0.f; }

    for (int tj = 0; tj <= ti; ++tj) {
        const int st = tj & 1;
        if (tj < ti) CP_WAIT(1); else CP_WAIT(0);
        __syncthreads();

        float acc[2][8][4];
#pragma unroll
        for (int a = 0; a < 2; ++a)
#pragma unroll
            for (int b = 0; b < 8; ++b)
#pragma unroll
                for (int c = 0; c < 4; ++c) acc[a][b][c] = 0.f;

        TILE_MMA(acc);

        const bool diag = (tj == ti);
#pragma unroll
        for (int fm = 0; fm < 2; ++fm)
#pragma unroll
            for (int half = 0; half < 2; ++half) {
                const int idx = fm * 2 + half;
                const int ig = ti * 128 + warp_m + fm * 16 + (lane >> 2) + half * 8;
                const int jbase = tj * 128 + warp_n + (lane & 3) * 2;
                float tmax = -1e30f;
                float sum = 0.f;
#pragma unroll
                for (int fn = 0; fn < 8; ++fn) {
                    float v0 = acc[fm][fn][half * 2]     * 0.125f;
                    float v1 = acc[fm][fn][half * 2 + 1] * 0.125f;
                    if (diag) {
                        if (jbase + fn * 8 <= ig)     tmax = fmaxf(tmax, v0);
                        if (jbase + fn * 8 + 1 <= ig) tmax = fmaxf(tmax, v1);
                    } else {
                        tmax = fmaxf(tmax, fmaxf(v0, v1));
                    }
                }
                tmax = fmaxf(tmax, __shfl_xor_sync(0xffffffffu, tmax, 1));
                tmax = fmaxf(tmax, __shfl_xor_sync(0xffffffffu, tmax, 2));
                float m_new = fmaxf(s_m[idx], tmax);
#pragma unroll
                for (int fn = 0; fn < 8; ++fn) {
                    float v0 = acc[fm][fn][half * 2]     * 0.125f;
                    float v1 = acc[fm][fn][half * 2 + 1] * 0.125f;
                    if (diag) {
                        if (jbase + fn * 8 <= ig)     sum += __expf(v0 - m_new);
                        if (jbase + fn * 8 + 1 <= ig) sum += __expf(v1 - m_new);
                    } else {
                        sum += __expf(v0 - m_new) + __expf(v1 - m_new);
                    }
                }
                sum += __shfl_xor_sync(0xffffffffu, sum, 1);
                sum += __shfl_xor_sync(0xffffffffu, sum, 2);
                s_l[idx] = s_l[idx] * __expf(s_m[idx] - m_new) + sum;
                s_m[idx] = m_new;
            }

        __syncthreads();
        if (tj + 2 <= ti) QLOAD(st, tj + 2);
    }

    // ---------------- combine stats -> smem ----------------
    if ((lane & 3) == 0) {
#pragma unroll
        for (int idx = 0; idx < 4; ++idx) {
            int off = ((wid * 8 + (lane >> 2)) * 4 + idx) * 2;
            comb[off]     = s_m[idx];
            comb[off + 1] = s_l[idx];
        }
    }
    __syncthreads();
    if (wid < 4 && (lane & 3) == 0) {
#pragma unroll
        for (int idx = 0; idx < 4; ++idx) {
            int o0 = ((wid * 8 + (lane >> 2)) * 4 + idx) * 2;
            int o1 = (((wid + 4) * 8 + (lane >> 2)) * 4 + idx) * 2;
            float m0 = comb[o0], l0 = comb[o0 + 1];
            float m1 = comb[o1], l1 = comb[o1 + 1];
            float m = fmaxf(m0, m1);
            float l = l0 * __expf(m0 - m) + l1 * __expf(m1 - m);
            int il = warp_m + (idx >> 1) * 16 + (lane >> 2) + (idx & 1) * 8;
            rowstats[il] = m;
            rowstats[128 + il] = 1.f / l;
        }
    }
    __syncthreads();

    // per-thread stats for pass 2
    float r_m[4], r_il[4];
#pragma unroll
    for (int idx = 0; idx < 4; ++idx) {
        int il = warp_m + (idx >> 1) * 16 + (lane >> 2) + (idx & 1) * 8;
        r_m[idx]  = rowstats[il];
        r_il[idx] = rowstats[128 + il];
    }

    // ---------------- zero-fill upper tiles of this row band --------------
    for (int jt = ti + 1; jt < 8; ++jt) {
        const float4 z4 = make_float4(0.f, 0.f, 0.f, 0.f);
#pragma unroll
        for (int q = 0; q < 16; ++q) {
            int id = tid + 256 * q;
            int r = id >> 5, c4 = id & 31;
            *(float4*)(out + (size_t)(ti * 128 + r) * 1024 + jt * 128 + c4 * 4) = z4;
        }
    }

    // ---------------- PASS 2: recompute + write normalized p --------------
    QLOAD(0, 0);
    if (ti >= 1) QLOAD(1, 1);

    for (int tj = 0; tj <= ti; ++tj) {
        const int st = tj & 1;
        if (tj < ti) CP_WAIT(1); else CP_WAIT(0);
        __syncthreads();

        float acc[2][8][4];
#pragma unroll
        for (int a = 0; a < 2; ++a)
#pragma unroll
            for (int b = 0; b < 8; ++b)
#pragma unroll
                for (int c = 0; c < 4; ++c) acc[a][b][c] = 0.f;

        TILE_MMA(acc);

        const bool diag = (tj == ti);
#pragma unroll
        for (int fm = 0; fm < 2; ++fm)
#pragma unroll
            for (int half = 0; half < 2; ++half) {
                const int idx = fm * 2 + half;
                const int ig = ti * 128 + warp_m + fm * 16 + (lane >> 2) + half * 8;
                float* orow = out + (size_t)ig * 1024 + tj * 128 + warp_n
                              + (lane & 3) * 2;
                const int jbase = tj * 128 + warp_n + (lane & 3) * 2;
                const float m = r_m[idx], il = r_il[idx];
#pragma unroll
                for (int fn = 0; fn < 8; ++fn) {
                    float v0 = acc[fm][fn][half * 2]     * 0.125f;
                    float v1 = acc[fm][fn][half * 2 + 1] * 0.125f;
                    float p0, p1;
                    if (diag) {
                        p0 = (jbase + fn * 8 <= ig)     ? __expf(v0 - m) * il : 0.f;
                        p1 = (jbase + fn * 8 + 1 <= ig) ? __expf(v1 - m) * il : 0.f;
                    } else {
                        p0 = __expf(v0 - m) * il;
                        p1 = __expf(v1 - m) * il;
                    }
                    *(float2*)(orow + fn * 8) = make_float2(p0, p1);
                }
            }

        __syncthreads();
        if (tj + 2 <= ti) QLOAD(st, tj + 2);
    }
#undef QLOAD
#undef TILE_MMA
}

// ============================================================================
// att: read normalized p fp32 from dist, pack fp16, P^T (trans) x V (2-term).
// No dist writes, no exp.
// ============================================================================
__global__ void __launch_bounds__(256, 2) att_kernel(
    const float* __restrict__ dist, const float* __restrict__ Vp,
    float* __restrict__ att)
{
    __shared__ __half Ps[32][136];
    __shared__ __half Vs[2][32][72];

    const int jt = blockIdx.x;
    const int bb = blockIdx.y;
    const int h = bb >> 3;
    const int b = bb & 7;
    const int j0 = jt * 128;

    const int tid  = threadIdx.x;
    const int wid  = tid >> 5;
    const int lane = tid & 31;
    const int warp_m = (wid & 3) * 32;
    const int warp_n = (wid >> 2) * 32;

    const float* dbase = dist + ((size_t)bb << 20);
    const float* vbase = Vp + (size_t)b * 1024 + (size_t)h * 64;

    const uint32_t PB = smem_u32(&Ps[0][0]);
    const uint32_t VhB = smem_u32(&Vs[0][0][0]);
    const uint32_t VlB = smem_u32(&Vs[1][0][0]);

    float acc[2][4][4];
#pragma unroll
    for (int a = 0; a < 2; ++a)
#pragma unroll
        for (int c = 0; c < 4; ++c)
#pragma unroll
            for (int e = 0; e < 4; ++e) acc[a][c][e] = 0.f;

    const int nsteps = (1024 - j0) / 32;

    for (int step = 0; step < nsteps; ++step) {
        const int i0 = j0 + step * 32;

#pragma unroll
        for (int q = 0; q < 4; ++q) {
            int id = tid + 256 * q;
            int r = id >> 5, c4 = id & 31;
            float4 p = *(const float4*)(dbase + (size_t)(i0 + r) * 1024 + j0 + c4 * 4);
            __half2 h01 = __floats2half2_rn(p.x, p.y);
            __half2 h23 = __floats2half2_rn(p.z, p.w);
            *(uint2*)(&Ps[r][c4 * 4]) = make_uint2(*(uint32_t*)&h01, *(uint32_t*)&h23);
        }
#pragma unroll
        for (int q = 0; q < 2; ++q) {
            int id = tid + 256 * q;
            int r = id >> 4, c4 = id & 15;
            float4 v = *(const float4*)(vbase + (size_t)(i0 + r) * 8192 + c4 * 4);
            uint32_t h0, l0, h1, l1;
            split2h(v.x, v.y, h0, l0);
            split2h(v.z, v.w, h1, l1);
            *(uint2*)(&Vs[0][r][c4 * 4]) = make_uint2(h0, h1);
            *(uint2*)(&Vs[1][r][c4 * 4]) = make_uint2(l0, l1);
        }
        __syncthreads();

#pragma unroll
        for (int k16 = 0; k16 < 2; ++k16) {
            const uint32_t arow = k16 * 16 + ((lane >> 4) << 3) + (lane & 7);
            uint32_t af[2][4];
#pragma unroll
            for (int fm = 0; fm < 2; ++fm) {
                const uint32_t acolb =
                    (warp_m + fm * 16 + (((lane >> 3) & 1) << 3)) * 2;
                LDM_X4_T(af[fm], PB + arow * 272 + acolb);
            }
            const uint32_t brow = k16 * 16 + (((lane >> 3) & 1) << 3) + (lane & 7);
            uint32_t bH[4][2], bL[4][2];
#pragma unroll
            for (int fp = 0; fp < 2; ++fp) {
                const uint32_t bcolb =
                    (warp_n + fp * 16 + ((lane >> 4) << 3)) * 2;
                uint32_t r[4];
                LDM_X4_T(r, VhB + brow * 144 + bcolb);
                bH[fp * 2][0] = r[0]; bH[fp * 2][1] = r[1];
                bH[fp * 2 + 1][0] = r[2]; bH[fp * 2 + 1][1] = r[3];
                LDM_X4_T(r, VlB + brow * 144 + bcolb);
                bL[fp * 2][0] = r[0]; bL[fp * 2][1] = r[1];
                bL[fp * 2 + 1][0] = r[2]; bL[fp * 2 + 1][1] = r[3];
            }
#pragma unroll
            for (int fm = 0; fm < 2; ++fm)
#pragma unroll
                for (int fn = 0; fn < 4; ++fn) {
                    MMA_F16(acc[fm][fn], af[fm], bH[fn][0], bH[fn][1]);
                    MMA_F16(acc[fm][fn], af[fm], bL[fn][0], bL[fn][1]);
                }
        }
        __syncthreads();
    }

#pragma unroll
    for (int fm = 0; fm < 2; ++fm)
#pragma unroll
        for (int half = 0; half < 2; ++half) {
            int j = j0 + warp_m + fm * 16 + (lane >> 2) + half * 8;
            float* cr = att + ((size_t)b * 1024 + j) * 1024 + h * 64
                        + warp_n + (lane & 3) * 2;
#pragma unroll
            for (int fn = 0; fn < 4; ++fn) {
                float2 v = half ? make_float2(acc[fm][fn][2], acc[fm][fn][3])
                                : make_float2(acc[fm][fn][0], acc[fm][fn][1]);
                *(float2*)(cr + fn * 8) = v;
            }
        }
}

// ---------------------------------------------------------------------------
extern "C" void kernel_launch(void* const* d_in, const int* in_sizes, int n_in,
                              void* d_out, int out_size)
{
    const float* value = (const float*)d_in[0];
    const float* key   = (const float*)d_in[1];
    const float* query = (const float*)d_in[2];
    const float* Wq    = (const float*)d_in[3];
    const float* Wk    = (const float*)d_in[4];
    const float* Wv    = (const float*)d_in[5];
    const float* Wo    = (const float*)d_in[6];
    float* out = (float*)d_out;

    float* g_v_p;   cudaGetSymbolAddress((void**)&g_v_p,   g_v);
    float* g_att_p; cudaGetSymbolAddress((void**)&g_att_p, g_att);
    __half *w16h, *w16l, *x16;
    cudaGetSymbolAddress((void**)&w16h, g_w16h);
    cudaGetSymbolAddress((void**)&w16l, g_w16l);
    cudaGetSymbolAddress((void**)&x16,  g_x16);
    __nv_bfloat16 *qh, *ql, *kh, *kl;
    cudaGetSymbolAddress((void**)&qh, g_qh);
    cudaGetSymbolAddress((void**)&ql, g_ql);
    cudaGetSymbolAddress((void**)&kh, g_kh);
    cudaGetSymbolAddress((void**)&kl, g_kl);

    float* dist_p;
    if ((long long)out_size == (long long)OUT_ELEMS + (long long)DIST_ELEMS) {
        dist_p = out + OUT_ELEMS;
    } else {
        cudaGetSymbolAddress((void**)&dist_p, g_dist_fallback);
    }

    static int init_done = 0;
    static cudaStream_t s2 = 0;
    static cudaEvent_t e1 = 0, e2 = 0;
    if (!init_done) {
        cudaFuncSetAttribute(gemm_fp16_kernel,
                             cudaFuncAttributeMaxDynamicSharedMemorySize, G2_SMEM);
        cudaFuncSetAttribute(scores_fused_kernel,
                             cudaFuncAttributeMaxDynamicSharedMemorySize, SCF_SMEM);
        cudaStreamCreateWithFlags(&s2, cudaStreamNonBlocking);
        cudaEventCreateWithFlags(&e1, cudaEventDisableTiming);
        cudaEventCreateWithFlags(&e2, cudaEventDisableTiming);
        init_done = 1;
    }

    dim3 blk(256);
    dim3 blkg(128);
    dim3 grid_qk(8, 64, 2);
    dim3 grid_v(8, 64, 1);

    conv_w4_kernel<<<4096, blk>>>((const float4*)Wq, (const float4*)Wk,
                                  (const float4*)Wv, (const float4*)Wo,
                                  (uint32_t*)w16h, (uint32_t*)w16l);
    conv_a3_kernel<<<24576, blk>>>((const float4*)query, (const float4*)key,
                                   (const float4*)value, (uint32_t*)x16);

    // fork: V projection runs on s2 concurrent with QK GEMM + scores
    cudaEventRecord(e1, 0);
    cudaStreamWaitEvent(s2, e1, 0);
    gemm_fp16_kernel<<<grid_v, blkg, G2_SMEM, s2>>>(
        x16 + 2 * (size_t)SB_ * H_, w16h + 2 * WW_, w16l + 2 * WW_,
        g_v_p, nullptr, nullptr, nullptr, nullptr, 0);
    cudaEventRecord(e2, s2);

    // QK projections (z=0 Q, z=1 K)
    gemm_fp16_kernel<<<grid_qk, blkg, G2_SMEM>>>(x16, w16h, w16l, nullptr,
                                                 qh, ql, kh, kl, 0);

    // two-pass scores: stats then normalized p (+ zero upper) into dist
    dim3 grid_sc(8, 128);
    scores_fused_kernel<<<grid_sc, blk, SCF_SMEM>>>(qh, ql, kh, kl, dist_p);

    // join: att needs V
    cudaStreamWaitEvent(0, e2, 0);
    dim3 grid_att(8, 128);
    att_kernel<<<grid_att, blk>>>(dist_p, g_v_p, g_att_p);

    conv_a1_kernel<<<8192, blk>>>((const float4*)g_att_p, (uint32_t*)x16);
    gemm_fp16_kernel<<<grid_v, blkg, G2_SMEM>>>(x16, w16h + 3 * WW_,
                                                w16l + 3 * WW_, out,
                                                nullptr, nullptr, nullptr,
                                                nullptr, 1);
}

// round 14
// speedup vs baseline: 3.5911x; 1.1996x over previous
#include <cuda_runtime.h>
#include <cuda_bf16.h>
#include <cuda_fp16.h>
#include <math.h>
#include <stdint.h>

// Problem constants
#define S_   1024
#define B_   8
#define H_   1024
#define NH_  16
#define DK_  64
#define BH_  128
#define SB_  8192
#define OUT_ELEMS  (S_*B_*H_)
#define DIST_ELEMS (BH_*S_*S_)
#define WW_  (H_*H_)

// ---------------- scratch ----------------
__device__ float g_dist_fallback[DIST_ELEMS];
__device__ __half g_w16h[4 * WW_];
__device__ __half g_w16l[4 * WW_];
__device__ __half g_x16[3 * SB_ * H_];   // QKV fp16 in; slot 0 reused for att out
__device__ __half g_qh[SB_ * H_];
__device__ __half g_ql[SB_ * H_];
__device__ __half g_kh[SB_ * H_];
__device__ __half g_kl[SB_ * H_];
__device__ __half g_vh[SB_ * H_];
__device__ __half g_vl[SB_ * H_];

__device__ __forceinline__ uint32_t smem_u32(const void* p) {
    uint32_t a;
    asm("{ .reg .u64 t; cvta.to.shared.u64 t, %1; cvt.u32.u64 %0, t; }"
        : "=r"(a) : "l"(p));
    return a;
}
__device__ __forceinline__ void cp_async16(uint32_t dst, const void* src) {
    asm volatile("cp.async.ca.shared.global [%0], [%1], 16;" :: "r"(dst), "l"(src));
}
#define CP_COMMIT() asm volatile("cp.async.commit_group;" ::: "memory")
#define CP_WAIT(N)  asm volatile("cp.async.wait_group %0;" :: "n"(N) : "memory")

#define LDM_X4(r, addr)                                                        \
    asm volatile("ldmatrix.sync.aligned.m8n8.x4.shared.b16 {%0,%1,%2,%3}, [%4];" \
                 : "=r"((r)[0]), "=r"((r)[1]), "=r"((r)[2]), "=r"((r)[3]) : "r"(addr))
#define LDM_X4_T(r, addr)                                                      \
    asm volatile("ldmatrix.sync.aligned.m8n8.x4.trans.shared.b16 {%0,%1,%2,%3}, [%4];" \
                 : "=r"((r)[0]), "=r"((r)[1]), "=r"((r)[2]), "=r"((r)[3]) : "r"(addr))

#define MMA_F16(acc, a, b0, b1)                                                \
    asm volatile("mma.sync.aligned.m16n8k16.row.col.f32.f16.f16.f32 "          \
                 "{%0,%1,%2,%3}, {%4,%5,%6,%7}, {%8,%9}, {%0,%1,%2,%3};"       \
                 : "+f"((acc)[0]), "+f"((acc)[1]), "+f"((acc)[2]), "+f"((acc)[3]) \
                 : "r"((a)[0]), "r"((a)[1]), "r"((a)[2]), "r"((a)[3]),         \
                   "r"(b0), "r"(b1))

__device__ __forceinline__ void split2h(float x, float y,
                                        uint32_t& hi, uint32_t& lo) {
    __half2 h = __floats2half2_rn(x, y);
    float rx = x - __half2float(__low2half(h));
    float ry = y - __half2float(__high2half(h));
    __half2 l = __floats2half2_rn(rx, ry);
    hi = *(uint32_t*)&h;
    lo = *(uint32_t*)&l;
}

// ============================================================================
// conv kernels
// ============================================================================
__global__ void __launch_bounds__(256) conv_w4_kernel(
    const float4* __restrict__ W0, const float4* __restrict__ W1,
    const float4* __restrict__ W2, const float4* __restrict__ W3,
    uint32_t* __restrict__ hi, uint32_t* __restrict__ lo)
{
    int i = blockIdx.x * 256 + threadIdx.x;
    int mat = i >> 18, off = i & 262143;
    const float4* src = (mat == 0) ? W0 : (mat == 1) ? W1 : (mat == 2) ? W2 : W3;
    float4 v = src[off];
    uint32_t h0, l0, h1, l1;
    split2h(v.x, v.y, h0, l0);
    split2h(v.z, v.w, h1, l1);
    hi[2 * i] = h0; hi[2 * i + 1] = h1;
    lo[2 * i] = l0; lo[2 * i + 1] = l1;
}

__global__ void __launch_bounds__(256) conv_a3_kernel(
    const float4* __restrict__ X0, const float4* __restrict__ X1,
    const float4* __restrict__ X2, uint32_t* __restrict__ dst)
{
    int i = blockIdx.x * 256 + threadIdx.x;
    int mat = i >> 21, off = i & 2097151;
    const float4* src = (mat == 0) ? X0 : (mat == 1) ? X1 : X2;
    float4 v = src[off];
    __half2 h01 = __floats2half2_rn(v.x, v.y);
    __half2 h23 = __floats2half2_rn(v.z, v.w);
    dst[2 * i] = *(uint32_t*)&h01;
    dst[2 * i + 1] = *(uint32_t*)&h23;
}

// ============================================================================
// fp16 2-term GEMM, 4 warps x (64x64): C = A @ W^T.
// gridDim.z==2 -> fused QK (z=0: Q -> qh/ql, z=1: K -> kh/kl).
// mode 1: fp32 out + (b,s)->(s,b) perm.  mode 2: fp16 hi/lo head-major Oh/Ol.
// ============================================================================
#define ROWB 80
#define G2STAGE 30720
#define G2_SMEM (3 * G2STAGE)

__global__ void __launch_bounds__(128, 2) gemm_fp16_kernel(
    const __half* __restrict__ A16b, const __half* __restrict__ Whb,
    const __half* __restrict__ Wlb, float* __restrict__ C0,
    __half* __restrict__ qh_, __half* __restrict__ ql_,
    __half* __restrict__ kh_, __half* __restrict__ kl_,
    int smode)
{
    extern __shared__ char gsm[];
    const uint32_t s0 = smem_u32(gsm);

    const __half* A16 = A16b;
    const __half* Wh = Whb;
    const __half* Wl = Wlb;
    float* C = C0;
    __half* Oh = qh_;
    __half* Ol = ql_;
    int mode = smode;
    if (gridDim.z == 2) {
        int z = blockIdx.z;
        A16 += (size_t)z * ((size_t)SB_ * H_);
        Wh += (size_t)z * WW_;
        Wl += (size_t)z * WW_;
        mode = 2;
        if (z == 1) { Oh = kh_; Ol = kl_; }
    }

    const int tid  = threadIdx.x;
    const int wid  = tid >> 5;
    const int lane = tid & 31;
    const int m0 = blockIdx.y * 128;
    const int n0 = blockIdx.x * 128;
    const int warp_m = (wid & 1) * 64;
    const int warp_n = (wid >> 1) * 64;

    float acc[4][8][4];
#pragma unroll
    for (int a = 0; a < 4; ++a)
#pragma unroll
        for (int b = 0; b < 8; ++b)
#pragma unroll
            for (int c = 0; c < 4; ++c) acc[a][b][c] = 0.f;

#define LOAD2(st, kt) do {                                                     \
    int kk_ = (kt) * 32;                                                       \
    const __half* ga_ = A16 + (size_t)m0 * 1024 + kk_;                         \
    const __half* gh_ = Wh + (size_t)n0 * 1024 + kk_;                          \
    const __half* gl_ = Wl + (size_t)n0 * 1024 + kk_;                          \
    uint32_t base_ = s0 + (st) * G2STAGE;                                      \
    _Pragma("unroll")                                                          \
    for (int l_ = 0; l_ < 4; ++l_) {                                           \
        int id_ = tid + 128 * l_;                                              \
        int row_ = id_ >> 2, c_ = id_ & 3;                                     \
        cp_async16(base_ + row_ * ROWB + c_ * 16,                              \
                   ga_ + (size_t)row_ * 1024 + c_ * 8);                        \
        cp_async16(base_ + 10240u + row_ * ROWB + c_ * 16,                     \
                   gh_ + (size_t)row_ * 1024 + c_ * 8);                        \
        cp_async16(base_ + 20480u + row_ * ROWB + c_ * 16,                     \
                   gl_ + (size_t)row_ * 1024 + c_ * 8);                        \
    }                                                                          \
    CP_COMMIT();                                                               \
} while (0)

    LOAD2(0, 0);
    LOAD2(1, 1);

    const uint32_t a_lane_row = warp_m + (lane & 15);
    const uint32_t a_lane_col = (lane >> 4) * 16;
    const uint32_t b_lane_row = warp_n + (lane & 7) + ((lane >> 4) << 3);
    const uint32_t b_lane_col = ((lane >> 3) & 1) * 16;

    for (int kt = 0; kt < 32; ++kt) {
        const int st = kt - (kt / 3) * 3;
        if (kt < 30) CP_WAIT(1); else CP_WAIT(0);
        __syncthreads();
        if (kt + 2 < 32) {
            int st2 = (kt + 2) - ((kt + 2) / 3) * 3;
            LOAD2(st2, kt + 2);
        }

        const uint32_t abase = s0 + st * G2STAGE;

#pragma unroll
        for (int k16 = 0; k16 < 2; ++k16) {
            uint32_t af[4][4];
#pragma unroll
            for (int fm = 0; fm < 4; ++fm)
                LDM_X4(af[fm], abase + (a_lane_row + fm * 16) * ROWB
                               + k16 * 32 + a_lane_col);
            uint32_t bf[8][2];
#pragma unroll
            for (int fp = 0; fp < 4; ++fp) {
                uint32_t r[4];
                LDM_X4(r, abase + 10240u + (b_lane_row + fp * 16) * ROWB
                          + k16 * 32 + b_lane_col);
                bf[fp * 2][0] = r[0]; bf[fp * 2][1] = r[1];
                bf[fp * 2 + 1][0] = r[2]; bf[fp * 2 + 1][1] = r[3];
            }
#pragma unroll
            for (int fm = 0; fm < 4; ++fm)
#pragma unroll
                for (int fn = 0; fn < 8; ++fn)
                    MMA_F16(acc[fm][fn], af[fm], bf[fn][0], bf[fn][1]);
#pragma unroll
            for (int fp = 0; fp < 4; ++fp) {
                uint32_t r[4];
                LDM_X4(r, abase + 20480u + (b_lane_row + fp * 16) * ROWB
                          + k16 * 32 + b_lane_col);
                bf[fp * 2][0] = r[0]; bf[fp * 2][1] = r[1];
                bf[fp * 2 + 1][0] = r[2]; bf[fp * 2 + 1][1] = r[3];
            }
#pragma unroll
            for (int fm = 0; fm < 4; ++fm)
#pragma unroll
                for (int fn = 0; fn < 8; ++fn)
                    MMA_F16(acc[fm][fn], af[fm], bf[fn][0], bf[fn][1]);
        }
    }

#pragma unroll
    for (int fm = 0; fm < 4; ++fm) {
#pragma unroll
        for (int half = 0; half < 2; ++half) {
            int m = m0 + warp_m + fm * 16 + (lane >> 2) + half * 8;
            if (mode == 2) {
                int s = m >> 3, b = m & 7;
#pragma unroll
                for (int fn = 0; fn < 8; ++fn) {
                    int col = n0 + warp_n + (lane & 3) * 2 + fn * 8;
                    int h = col >> 6, d = col & 63;
                    size_t addr = ((size_t)(h * 8 + b) * 1024 + s) * 64 + d;
                    uint32_t hi, lo;
                    split2h(acc[fm][fn][half * 2], acc[fm][fn][half * 2 + 1], hi, lo);
                    *(uint32_t*)(Oh + addr) = hi;
                    *(uint32_t*)(Ol + addr) = lo;
                }
            } else {
                int orow = (m & (S_ - 1)) * B_ + (m >> 10);
                float* cr = C + (size_t)orow * 1024 + n0 + warp_n + (lane & 3) * 2;
#pragma unroll
                for (int fn = 0; fn < 8; ++fn) {
                    float2 v = half ? make_float2(acc[fm][fn][2], acc[fm][fn][3])
                                    : make_float2(acc[fm][fn][0], acc[fm][fn][1]);
                    *(float2*)(cr + fn * 8) = v;
                }
            }
        }
    }
#undef LOAD2
}

// ============================================================================
// scores two-pass fused (fp16 2-term): s = K (fp16) . (Qh + Ql).
// CTA owns row band ti of one bb. Pass 1: online (m,l) stats. Pass 2:
// recompute, write normalized p (+ zero upper tiles).
// ============================================================================
#define SROWB 144
#define SBUF  18432
#define QSTG  (2 * SBUF)
#define SCF_SMEM (SBUF + 2 * QSTG)   // K + 2 Q stages = 92160

__global__ void __launch_bounds__(256, 2) scores_fused_kernel(
    const __half* __restrict__ Qh, const __half* __restrict__ Ql,
    const __half* __restrict__ Kh,
    float* __restrict__ dist)
{
    extern __shared__ char sm[];
    __shared__ float rowstats[256];
    __shared__ float comb[8 * 8 * 4 * 2];
    const uint32_t s0 = smem_u32(sm);
    const int ti = 7 - blockIdx.x;
    const int bb = blockIdx.y;

    const int tid  = threadIdx.x;
    const int wid  = tid >> 5;
    const int lane = tid & 31;
    const int warp_m = (wid & 3) * 32;    // i
    const int warp_n = (wid >> 2) * 64;   // j

    const size_t hb = (size_t)bb * 65536;
    float* out = dist + ((size_t)bb << 20);

    // K band load (single fp16 buffer, resident both passes)
#pragma unroll
    for (int l = 0; l < 4; ++l) {
        int id = tid + 256 * l;
        int row = id >> 3, c = id & 7;
        cp_async16(s0 + row * SROWB + c * 16,
                   Kh + hb + (size_t)(ti * 128 + row) * 64 + c * 8);
    }

#define QLOAD(st, tj) do {                                                     \
    uint32_t qb_ = s0 + SBUF + (st) * QSTG;                                    \
    _Pragma("unroll")                                                          \
    for (int l_ = 0; l_ < 4; ++l_) {                                           \
        int id_ = tid + 256 * l_;                                              \
        int row_ = id_ >> 3, c_ = id_ & 7;                                     \
        cp_async16(qb_ + row_ * SROWB + c_ * 16,                               \
                   Qh + hb + (size_t)((tj) * 128 + row_) * 64 + c_ * 8);       \
        cp_async16(qb_ + SBUF + row_ * SROWB + c_ * 16,                        \
                   Ql + hb + (size_t)((tj) * 128 + row_) * 64 + c_ * 8);       \
    }                                                                          \
    CP_COMMIT();                                                               \
} while (0)

#define TILE_MMA(acc_)                                                         \
    do {                                                                       \
        const uint32_t qh_b = s0 + SBUF + st * QSTG;                           \
        const uint32_t ql_b = qh_b + SBUF;                                     \
        _Pragma("unroll")                                                      \
        for (int k16 = 0; k16 < 4; ++k16) {                                    \
            uint32_t af[2][4];                                                 \
            _Pragma("unroll")                                                  \
            for (int fm = 0; fm < 2; ++fm)                                     \
                LDM_X4(af[fm], s0 + (a_lane_row + fm * 16) * SROWB             \
                               + k16 * 32 + a_lane_col);                       \
            uint32_t bfr[8][2];                                                \
            _Pragma("unroll")                                                  \
            for (int fp = 0; fp < 4; ++fp) {                                   \
                uint32_t r[4];                                                 \
                LDM_X4(r, qh_b + (b_lane_row + fp * 16) * SROWB                \
                          + k16 * 32 + b_lane_col);                            \
                bfr[fp * 2][0] = r[0]; bfr[fp * 2][1] = r[1];                  \
                bfr[fp * 2 + 1][0] = r[2]; bfr[fp * 2 + 1][1] = r[3];          \
            }                                                                  \
            _Pragma("unroll")                                                  \
            for (int fm = 0; fm < 2; ++fm)                                     \
                _Pragma("unroll")                                              \
                for (int fn = 0; fn < 8; ++fn)                                 \
                    MMA_F16(acc_[fm][fn], af[fm], bfr[fn][0], bfr[fn][1]);     \
            _Pragma("unroll")                                                  \
            for (int fp = 0; fp < 4; ++fp) {                                   \
                uint32_t r[4];                                                 \
                LDM_X4(r, ql_b + (b_lane_row + fp * 16) * SROWB                \
                          + k16 * 32 + b_lane_col);                            \
                bfr[fp * 2][0] = r[0]; bfr[fp * 2][1] = r[1];                  \
                bfr[fp * 2 + 1][0] = r[2]; bfr[fp * 2 + 1][1] = r[3];          \
            }                                                                  \
            _Pragma("unroll")                                                  \
            for (int fm = 0; fm < 2; ++fm)                                     \
                _Pragma("unroll")                                              \
                for (int fn = 0; fn < 8; ++fn)                                 \
                    MMA_F16(acc_[fm][fn], af[fm], bfr[fn][0], bfr[fn][1]);     \
        }                                                                      \
    } while (0)

    const uint32_t a_lane_row = warp_m + (lane & 15);
    const uint32_t a_lane_col = (lane >> 4) * 16;
    const uint32_t b_lane_row = warp_n + (lane & 7) + ((lane >> 4) << 3);
    const uint32_t b_lane_col = ((lane >> 3) & 1) * 16;

    // ---------------- PASS 1: stats only ----------------
    QLOAD(0, 0);
    if (ti >= 1) QLOAD(1, 1);

    float s_m[4], s_l[4];
#pragma unroll
    for (int x = 0; x < 4; ++x) { s_m[x] = -1e30f; s_l[x] = 0.f; }

    for (int tj = 0; tj <= ti; ++tj) {
        const int st = tj & 1;
        if (tj < ti) CP_WAIT(1); else CP_WAIT(0);
        __syncthreads();

        float acc[2][8][4];
#pragma unroll
        for (int a = 0; a < 2; ++a)
#pragma unroll
            for (int b = 0; b < 8; ++b)
#pragma unroll
                for (int c = 0; c < 4; ++c) acc[a][b][c] = 0.f;

        TILE_MMA(acc);

        const bool diag = (tj == ti);
#pragma unroll
        for (int fm = 0; fm < 2; ++fm)
#pragma unroll
            for (int half = 0; half < 2; ++half) {
                const int idx = fm * 2 + half;
                const int ig = ti * 128 + warp_m + fm * 16 + (lane >> 2) + half * 8;
                const int jbase = tj * 128 + warp_n + (lane & 3) * 2;
                float tmax = -1e30f;
                float sum = 0.f;
#pragma unroll
                for (int fn = 0; fn < 8; ++fn) {
                    float v0 = acc[fm][fn][half * 2]     * 0.125f;
                    float v1 = acc[fm][fn][half * 2 + 1] * 0.125f;
                    if (diag) {
                        if (jbase + fn * 8 <= ig)     tmax = fmaxf(tmax, v0);
                        if (jbase + fn * 8 + 1 <= ig) tmax = fmaxf(tmax, v1);
                    } else {
                        tmax = fmaxf(tmax, fmaxf(v0, v1));
                    }
                }
                tmax = fmaxf(tmax, __shfl_xor_sync(0xffffffffu, tmax, 1));
                tmax = fmaxf(tmax, __shfl_xor_sync(0xffffffffu, tmax, 2));
                float m_new = fmaxf(s_m[idx], tmax);
#pragma unroll
                for (int fn = 0; fn < 8; ++fn) {
                    float v0 = acc[fm][fn][half * 2]     * 0.125f;
                    float v1 = acc[fm][fn][half * 2 + 1] * 0.125f;
                    if (diag) {
                        if (jbase + fn * 8 <= ig)     sum += __expf(v0 - m_new);
                        if (jbase + fn * 8 + 1 <= ig) sum += __expf(v1 - m_new);
                    } else {
                        sum += __expf(v0 - m_new) + __expf(v1 - m_new);
                    }
                }
                sum += __shfl_xor_sync(0xffffffffu, sum, 1);
                sum += __shfl_xor_sync(0xffffffffu, sum, 2);
                s_l[idx] = s_l[idx] * __expf(s_m[idx] - m_new) + sum;
                s_m[idx] = m_new;
            }

        __syncthreads();
        if (tj + 2 <= ti) QLOAD(st, tj + 2);
    }

    // ---------------- combine stats ----------------
    if ((lane & 3) == 0) {
#pragma unroll
        for (int idx = 0; idx < 4; ++idx) {
            int off = ((wid * 8 + (lane >> 2)) * 4 + idx) * 2;
            comb[off]     = s_m[idx];
            comb[off + 1] = s_l[idx];
        }
    }
    __syncthreads();
    if (wid < 4 && (lane & 3) == 0) {
#pragma unroll
        for (int idx = 0; idx < 4; ++idx) {
            int o0 = ((wid * 8 + (lane >> 2)) * 4 + idx) * 2;
            int o1 = (((wid + 4) * 8 + (lane >> 2)) * 4 + idx) * 2;
            float m0 = comb[o0], l0 = comb[o0 + 1];
            float m1 = comb[o1], l1 = comb[o1 + 1];
            float m = fmaxf(m0, m1);
            float l = l0 * __expf(m0 - m) + l1 * __expf(m1 - m);
            int il = warp_m + (idx >> 1) * 16 + (lane >> 2) + (idx & 1) * 8;
            rowstats[il] = m;
            rowstats[128 + il] = 1.f / l;
        }
    }
    __syncthreads();

    float r_m[4], r_il[4];
#pragma unroll
    for (int idx = 0; idx < 4; ++idx) {
        int il = warp_m + (idx >> 1) * 16 + (lane >> 2) + (idx & 1) * 8;
        r_m[idx]  = rowstats[il];
        r_il[idx] = rowstats[128 + il];
    }

    // ---------------- zero-fill upper tiles ----------------
    for (int jt = ti + 1; jt < 8; ++jt) {
        const float4 z4 = make_float4(0.f, 0.f, 0.f, 0.f);
#pragma unroll
        for (int q = 0; q < 16; ++q) {
            int id = tid + 256 * q;
            int r = id >> 5, c4 = id & 31;
            *(float4*)(out + (size_t)(ti * 128 + r) * 1024 + jt * 128 + c4 * 4) = z4;
        }
    }

    // ---------------- PASS 2: recompute + write normalized p --------------
    QLOAD(0, 0);
    if (ti >= 1) QLOAD(1, 1);

    for (int tj = 0; tj <= ti; ++tj) {
        const int st = tj & 1;
        if (tj < ti) CP_WAIT(1); else CP_WAIT(0);
        __syncthreads();

        float acc[2][8][4];
#pragma unroll
        for (int a = 0; a < 2; ++a)
#pragma unroll
            for (int b = 0; b < 8; ++b)
#pragma unroll
                for (int c = 0; c < 4; ++c) acc[a][b][c] = 0.f;

        TILE_MMA(acc);

        const bool diag = (tj == ti);
#pragma unroll
        for (int fm = 0; fm < 2; ++fm)
#pragma unroll
            for (int half = 0; half < 2; ++half) {
                const int idx = fm * 2 + half;
                const int ig = ti * 128 + warp_m + fm * 16 + (lane >> 2) + half * 8;
                float* orow = out + (size_t)ig * 1024 + tj * 128 + warp_n
                              + (lane & 3) * 2;
                const int jbase = tj * 128 + warp_n + (lane & 3) * 2;
                const float m = r_m[idx], il = r_il[idx];
#pragma unroll
                for (int fn = 0; fn < 8; ++fn) {
                    float v0 = acc[fm][fn][half * 2]     * 0.125f;
                    float v1 = acc[fm][fn][half * 2 + 1] * 0.125f;
                    float p0, p1;
                    if (diag) {
                        p0 = (jbase + fn * 8 <= ig)     ? __expf(v0 - m) * il : 0.f;
                        p1 = (jbase + fn * 8 + 1 <= ig) ? __expf(v1 - m) * il : 0.f;
                    } else {
                        p0 = __expf(v0 - m) * il;
                        p1 = __expf(v1 - m) * il;
                    }
                    *(float2*)(orow + fn * 8) = make_float2(p0, p1);
                }
            }

        __syncthreads();
        if (tj + 2 <= ti) QLOAD(st, tj + 2);
    }
#undef QLOAD
#undef TILE_MMA
}

// ============================================================================
// att: read normalized p fp32 -> fp16, V pre-split fp16 hi/lo head-major
// via cp.async. acc += P^T Vh + P^T Vl. Epilogue writes fp16 into x16
// (layout [b*1024+j][1024]) -- feeds the final GEMM directly.
// ============================================================================
__global__ void __launch_bounds__(256, 2) att_kernel(
    const float* __restrict__ dist, const __half* __restrict__ Vh,
    const __half* __restrict__ Vl, __half* __restrict__ xout)
{
    __shared__ __half Ps[32][136];
    __shared__ __half Vs[2][32][72];

    const int jt = blockIdx.x;
    const int bb = blockIdx.y;
    const int h = bb >> 3;
    const int b = bb & 7;
    const int j0 = jt * 128;

    const int tid  = threadIdx.x;
    const int wid  = tid >> 5;
    const int lane = tid & 31;
    const int warp_m = (wid & 3) * 32;
    const int warp_n = (wid >> 2) * 32;

    const float* dbase = dist + ((size_t)bb << 20);
    const size_t hb = (size_t)bb * 65536;

    const uint32_t PB = smem_u32(&Ps[0][0]);
    const uint32_t VhB = smem_u32(&Vs[0][0][0]);
    const uint32_t VlB = smem_u32(&Vs[1][0][0]);

    float acc[2][4][4];
#pragma unroll
    for (int a = 0; a < 2; ++a)
#pragma unroll
        for (int c = 0; c < 4; ++c)
#pragma unroll
            for (int e = 0; e < 4; ++e) acc[a][c][e] = 0.f;

    const int nsteps = (1024 - j0) / 32;

    for (int step = 0; step < nsteps; ++step) {
        const int i0 = j0 + step * 32;

        // V tiles via cp.async (32 rows x 128B, hi + lo)
        {
            int r = tid >> 3, c = tid & 7;
            cp_async16(VhB + r * 144 + c * 16, Vh + hb + (size_t)(i0 + r) * 64 + c * 8);
            cp_async16(VlB + r * 144 + c * 16, Vl + hb + (size_t)(i0 + r) * 64 + c * 8);
            CP_COMMIT();
        }

        // P tile: fp32 -> fp16
#pragma unroll
        for (int q = 0; q < 4; ++q) {
            int id = tid + 256 * q;
            int r = id >> 5, c4 = id & 31;
            float4 p = *(const float4*)(dbase + (size_t)(i0 + r) * 1024 + j0 + c4 * 4);
            __half2 h01 = __floats2half2_rn(p.x, p.y);
            __half2 h23 = __floats2half2_rn(p.z, p.w);
            *(uint2*)(&Ps[r][c4 * 4]) = make_uint2(*(uint32_t*)&h01, *(uint32_t*)&h23);
        }
        CP_WAIT(0);
        __syncthreads();

#pragma unroll
        for (int k16 = 0; k16 < 2; ++k16) {
            const uint32_t arow = k16 * 16 + ((lane >> 4) << 3) + (lane & 7);
            uint32_t af[2][4];
#pragma unroll
            for (int fm = 0; fm < 2; ++fm) {
                const uint32_t acolb =
                    (warp_m + fm * 16 + (((lane >> 3) & 1) << 3)) * 2;
                LDM_X4_T(af[fm], PB + arow * 272 + acolb);
            }
            const uint32_t brow = k16 * 16 + (((lane >> 3) & 1) << 3) + (lane & 7);
            uint32_t bH[4][2], bL[4][2];
#pragma unroll
            for (int fp = 0; fp < 2; ++fp) {
                const uint32_t bcolb =
                    (warp_n + fp * 16 + ((lane >> 4) << 3)) * 2;
                uint32_t r[4];
                LDM_X4_T(r, VhB + brow * 144 + bcolb);
                bH[fp * 2][0] = r[0]; bH[fp * 2][1] = r[1];
                bH[fp * 2 + 1][0] = r[2]; bH[fp * 2 + 1][1] = r[3];
                LDM_X4_T(r, VlB + brow * 144 + bcolb);
                bL[fp * 2][0] = r[0]; bL[fp * 2][1] = r[1];
                bL[fp * 2 + 1][0] = r[2]; bL[fp * 2 + 1][1] = r[3];
            }
#pragma unroll
            for (int fm = 0; fm < 2; ++fm)
#pragma unroll
                for (int fn = 0; fn < 4; ++fn) {
                    MMA_F16(acc[fm][fn], af[fm], bH[fn][0], bH[fn][1]);
                    MMA_F16(acc[fm][fn], af[fm], bL[fn][0], bL[fn][1]);
                }
        }
        __syncthreads();
    }

#pragma unroll
    for (int fm = 0; fm < 2; ++fm)
#pragma unroll
        for (int half = 0; half < 2; ++half) {
            int j = j0 + warp_m + fm * 16 + (lane >> 2) + half * 8;
            __half* cr = xout + ((size_t)b * 1024 + j) * 1024 + h * 64
                         + warp_n + (lane & 3) * 2;
#pragma unroll
            for (int fn = 0; fn < 4; ++fn) {
                float2 v = half ? make_float2(acc[fm][fn][2], acc[fm][fn][3])
                                : make_float2(acc[fm][fn][0], acc[fm][fn][1]);
                __half2 hv = __floats2half2_rn(v.x, v.y);
                *(__half2*)(cr + fn * 8) = hv;
            }
        }
}

// ---------------------------------------------------------------------------
extern "C" void kernel_launch(void* const* d_in, const int* in_sizes, int n_in,
                              void* d_out, int out_size)
{
    const float* value = (const float*)d_in[0];
    const float* key   = (const float*)d_in[1];
    const float* query = (const float*)d_in[2];
    const float* Wq    = (const float*)d_in[3];
    const float* Wk    = (const float*)d_in[4];
    const float* Wv    = (const float*)d_in[5];
    const float* Wo    = (const float*)d_in[6];
    float* out = (float*)d_out;

    __half *w16h, *w16l, *x16;
    cudaGetSymbolAddress((void**)&w16h, g_w16h);
    cudaGetSymbolAddress((void**)&w16l, g_w16l);
    cudaGetSymbolAddress((void**)&x16,  g_x16);
    __half *qh, *ql, *kh, *kl, *vh, *vl;
    cudaGetSymbolAddress((void**)&qh, g_qh);
    cudaGetSymbolAddress((void**)&ql, g_ql);
    cudaGetSymbolAddress((void**)&kh, g_kh);
    cudaGetSymbolAddress((void**)&kl, g_kl);
    cudaGetSymbolAddress((void**)&vh, g_vh);
    cudaGetSymbolAddress((void**)&vl, g_vl);

    float* dist_p;
    if ((long long)out_size == (long long)OUT_ELEMS + (long long)DIST_ELEMS) {
        dist_p = out + OUT_ELEMS;
    } else {
        cudaGetSymbolAddress((void**)&dist_p, g_dist_fallback);
    }

    static int init_done = 0;
    static cudaStream_t s2 = 0;
    static cudaEvent_t e1 = 0, e2 = 0;
    if (!init_done) {
        cudaFuncSetAttribute(gemm_fp16_kernel,
                             cudaFuncAttributeMaxDynamicSharedMemorySize, G2_SMEM);
        cudaFuncSetAttribute(scores_fused_kernel,
                             cudaFuncAttributeMaxDynamicSharedMemorySize, SCF_SMEM);
        cudaStreamCreateWithFlags(&s2, cudaStreamNonBlocking);
        cudaEventCreateWithFlags(&e1, cudaEventDisableTiming);
        cudaEventCreateWithFlags(&e2, cudaEventDisableTiming);
        init_done = 1;
    }

    dim3 blk(256);
    dim3 blkg(128);
    dim3 grid_qk(8, 64, 2);
    dim3 grid_1(8, 64, 1);

    conv_w4_kernel<<<4096, blk>>>((const float4*)Wq, (const float4*)Wk,
                                  (const float4*)Wv, (const float4*)Wo,
                                  (uint32_t*)w16h, (uint32_t*)w16l);
    conv_a3_kernel<<<24576, blk>>>((const float4*)query, (const float4*)key,
                                   (const float4*)value, (uint32_t*)x16);

    // fork: V projection (-> fp16 hi/lo head-major) on s2
    cudaEventRecord(e1, 0);
    cudaStreamWaitEvent(s2, e1, 0);
    gemm_fp16_kernel<<<grid_1, blkg, G2_SMEM, s2>>>(
        x16 + 2 * (size_t)SB_ * H_, w16h + 2 * WW_, w16l + 2 * WW_,
        nullptr, vh, vl, nullptr, nullptr, 2);
    cudaEventRecord(e2, s2);

    // QK projections (z=0 Q, z=1 K) -> fp16 hi/lo head-major
    gemm_fp16_kernel<<<grid_qk, blkg, G2_SMEM>>>(x16, w16h, w16l, nullptr,
                                                 qh, ql, kh, kl, 2);

    // two-pass scores: K fp16 single-term operand, Q hi/lo
    dim3 grid_sc(8, 128);
    scores_fused_kernel<<<grid_sc, blk, SCF_SMEM>>>(qh, ql, kh, dist_p);

    // join: att needs V
    cudaStreamWaitEvent(0, e2, 0);
    dim3 grid_att(8, 128);
    att_kernel<<<grid_att, blk>>>(dist_p, vh, vl, x16);

    // output projection (A = att fp16 in x16, with (b,s)->(s,b) perm)
    gemm_fp16_kernel<<<grid_1, blkg, G2_SMEM>>>(x16, w16h + 3 * WW_,
                                                w16l + 3 * WW_, out,
                                                nullptr, nullptr, nullptr,
                                                nullptr, 1);
}